// round 9
// baseline (speedup 1.0000x reference)
#include <cuda_runtime.h>
#include <cuda_fp16.h>
#include <math.h>
#include <stdint.h>

#define N_NODES 20000
#define N_EDGES 640000
#define HDIM    128
#define GDIM    50
#define GPAD    64
#define NLAYERS 6
#define NGRAPH  64
#define CUTOFF  10.0f
#define LOG2F_  0.69314718055994531f
#define PI_     3.14159265358979323846f

#define EPT     128
#define NTILES  (N_EDGES / EPT)
#define BUF_STR 136        // halves/row, shared ea/hid buffer
#define MSTR    132        // msg floats/row
#define NODE_TILES ((N_NODES + 127) / 128)

// ---------------- device scratch ----------------
static __device__ __align__(16) float  g_h[N_NODES * HDIM];
static __device__ __align__(16) float  g_xf[N_NODES * HDIM];
static __device__ __align__(16) float  g_agg[N_NODES * HDIM];
static __device__ __align__(16) float  g_d[N_EDGES];
static __device__ __align__(16) float  g_C[N_EDGES];
static __device__ __align__(16) __half g_ea[(size_t)N_EDGES * GPAD]; // PERMUTED order
static __device__ __align__(16) float  g_sums[NGRAPH * HDIM];
static __device__ float g_cnt[NGRAPH];
static __device__ int   g_hist[N_NODES];
static __device__ int   g_perm[N_EDGES];
static __device__ int   g_srcp[N_EDGES];
static __device__ int   g_dstp[N_EDGES];
static __device__ float g_Cp[N_EDGES];
// prebuilt fp16 B-fragments (m16n8k16 layout), all layers
static __device__ __align__(16) uint2 g_w1f[NLAYERS][2048];
static __device__ __align__(16) uint2 g_w2f[NLAYERS][4096];
static __device__ __align__(16) uint2 g_wAf[NLAYERS][4096];
static __device__ __align__(16) uint2 g_wBf[NLAYERS][4096];
static __device__ __align__(16) uint2 g_wCf[NLAYERS][4096];

// ---------------- helpers ----------------
__device__ __forceinline__ float tf32r(float x) {
    uint32_t r;
    asm("cvt.rna.tf32.f32 %0, %1;" : "=r"(r) : "f"(x));
    return __uint_as_float(r);
}
__device__ __forceinline__ float4 tf32r4(float4 v) {
    v.x = tf32r(v.x); v.y = tf32r(v.y); v.z = tf32r(v.z); v.w = tf32r(v.w);
    return v;
}
__device__ __forceinline__ float sspf(float x) {
    return fmaxf(x, 0.f) + log1pf(expf(-fabsf(x))) - LOG2F_;
}
__device__ __forceinline__ float sspf_fast(float x) {
    return fmaxf(x, 0.f) + __logf(1.f + __expf(-fabsf(x))) - LOG2F_;
}
__device__ __forceinline__ uint32_t smem_u32(const void* p) {
    uint32_t a;
    asm("{ .reg .u64 t; cvta.to.shared.u64 t, %1; cvt.u32.u64 %0, t; }" : "=r"(a) : "l"(p));
    return a;
}
__device__ __forceinline__ uint32_t f2h2(float lo, float hi) {
    __half2 h = __floats2half2_rn(lo, hi);
    return *reinterpret_cast<uint32_t*>(&h);
}
__device__ __forceinline__ void mma16816(float4& d, const uint32_t a[4], uint2 b) {
    asm volatile(
        "mma.sync.aligned.m16n8k16.row.col.f32.f16.f16.f32 "
        "{%0,%1,%2,%3}, {%4,%5,%6,%7}, {%8,%9}, {%0,%1,%2,%3};\n"
        : "+f"(d.x), "+f"(d.y), "+f"(d.z), "+f"(d.w)
        : "r"(a[0]), "r"(a[1]), "r"(a[2]), "r"(a[3]), "r"(b.x), "r"(b.y));
}
__device__ __forceinline__ void ldsm4(uint32_t r[4], const void* p) {
    uint32_t a = smem_u32(p);
    asm volatile("ldmatrix.sync.aligned.m8n8.x4.shared.b16 {%0,%1,%2,%3}, [%4];"
        : "=r"(r[0]), "=r"(r[1]), "=r"(r[2]), "=r"(r[3]) : "r"(a));
}

// ---------------- precompute ----------------
__global__ void init_h_kernel(const int* __restrict__ z, const float* __restrict__ emb) {
    int i = blockIdx.x * blockDim.x + threadIdx.x;
    if (i >= N_NODES * HDIM) return;
    int n = i >> 7, j = i & 127;
    g_h[i] = emb[z[n] * HDIM + j];
}

__global__ void dist_kernel(const int* __restrict__ src, const int* __restrict__ dst,
                            const float* __restrict__ pos) {
    int e = blockIdx.x * blockDim.x + threadIdx.x;
    if (e >= N_EDGES) return;
    int s = src[e], t = dst[e];
    float dx = pos[s * 3 + 0] - pos[t * 3 + 0];
    float dy = pos[s * 3 + 1] - pos[t * 3 + 1];
    float dz = pos[s * 3 + 2] - pos[t * 3 + 2];
    float d = sqrtf(dx * dx + dy * dy + dz * dz);
    g_d[e] = d;
    g_C[e] = 0.5f * (cosf(d * (PI_ / CUTOFF)) + 1.0f);
}

__global__ void zero_hist_kernel() {
    int i = blockIdx.x * blockDim.x + threadIdx.x;
    if (i < N_NODES) g_hist[i] = 0;
}
__global__ void hist_kernel(const int* __restrict__ dst) {
    int e = blockIdx.x * blockDim.x + threadIdx.x;
    if (e < N_EDGES) atomicAdd(&g_hist[dst[e]], 1);
}
__global__ void scan_kernel() {
    __shared__ int s[1024];
    int t = threadIdx.x;
    const int CH = (N_NODES + 1023) / 1024;
    int base = t * CH;
    int sum = 0;
    for (int i = 0; i < CH; i++) {
        int idx = base + i;
        if (idx < N_NODES) sum += g_hist[idx];
    }
    s[t] = sum;
    __syncthreads();
    for (int off = 1; off < 1024; off <<= 1) {
        int v = (t >= off) ? s[t - off] : 0;
        __syncthreads();
        s[t] += v;
        __syncthreads();
    }
    int run = (t > 0) ? s[t - 1] : 0;
    for (int i = 0; i < CH; i++) {
        int idx = base + i;
        if (idx < N_NODES) { int c = g_hist[idx]; g_hist[idx] = run; run += c; }
    }
}
__global__ void scatter_kernel(const int* __restrict__ src, const int* __restrict__ dst) {
    int e = blockIdx.x * blockDim.x + threadIdx.x;
    if (e >= N_EDGES) return;
    int d = dst[e];
    int p = atomicAdd(&g_hist[d], 1);
    g_perm[p] = e;
    g_srcp[p] = src[e];
    g_dstp[p] = d;
    g_Cp[p]   = g_C[e];
}

// gaussian table: only the ±6-center window around d is nonzero in fp16.
// (exp(-12*diff^2) < half of fp16 min-subnormal for |diff| > 5.9 steps, so the
// result is bit-identical to evaluating all 50 centers.)
__global__ __launch_bounds__(256) void gauss_kernel() {
    __shared__ __half buf[256][GPAD];      // 32 KB
    int tid = threadIdx.x;
    int e = blockIdx.x * 256 + tid;
    const float step  = CUTOFF / (GDIM - 1);
    const float coeff = -0.5f / (step * step);
    #pragma unroll
    for (int j = 0; j < 8; j++)
        ((uint4*)buf[tid])[j] = make_uint4(0, 0, 0, 0);

    float d  = g_d[g_perm[e]];
    int c0 = (int)rintf(d / step);
    #pragma unroll
    for (int k = -6; k <= 6; k++) {
        int c = c0 + k;
        if (c >= 0 && c < GDIM) {
            float diff = d - c * step;
            buf[tid][c] = __float2half_rn(__expf(coeff * diff * diff));
        }
    }
    __syncthreads();
    size_t e0 = (size_t)blockIdx.x * 256;
    for (int i = tid; i < 256 * 8; i += 256) {
        int r = i >> 3, j = i & 7;
        ((uint4*)&g_ea[(e0 + r) * GPAD])[j] = ((uint4*)buf[r])[j];
    }
}

// build all fp16 B-fragments once (m16n8k16 layout)
__device__ __forceinline__ uint2 frag_of(const float* w, int k0, int n) {
    return make_uint2(f2h2(w[k0 * 128 + n], w[(k0 + 1) * 128 + n]),
                      f2h2(w[(k0 + 8) * 128 + n], w[(k0 + 9) * 128 + n]));
}
__global__ void build_frags_kernel(const float* __restrict__ mlp_w1,
                                   const float* __restrict__ mlp_w2,
                                   const float* __restrict__ conv_w2,
                                   const float* __restrict__ lin_w,
                                   const float* __restrict__ conv_w1) {
    int i = blockIdx.x * blockDim.x + threadIdx.x;
    if (i >= NLAYERS * 4096) return;
    int l = i / 4096, j = i % 4096;
    int lane = j & 31;
    int g_ = lane >> 2, t_ = lane & 3;
    {   // K=128 fragments
        int kt = (j >> 5) & 7, nt = j >> 8;
        int k0 = kt * 16 + 2 * t_, n = nt * 8 + g_;
        g_w2f[l][j] = frag_of(mlp_w2 + (size_t)l * 16384, k0, n);
        g_wAf[l][j] = frag_of(conv_w2 + (size_t)l * 16384, k0, n);
        g_wBf[l][j] = frag_of(lin_w + (size_t)l * 16384, k0, n);
        g_wCf[l][j] = frag_of(conv_w1 + (size_t)l * 16384, k0, n);
    }
    if (j < 2048) {   // K=64 fragments for w1
        int kt = (j >> 5) & 3, nt = j >> 7;
        int k0 = kt * 16 + 2 * t_, n = nt * 8 + g_;
        const float* w1 = mlp_w1 + (size_t)l * GDIM * 128;
        float v0 = (k0     < GDIM) ? w1[k0 * 128 + n]       : 0.f;
        float v1 = (k0 + 1 < GDIM) ? w1[(k0 + 1) * 128 + n] : 0.f;
        float v2 = (k0 + 8 < GDIM) ? w1[(k0 + 8) * 128 + n] : 0.f;
        float v3 = (k0 + 9 < GDIM) ? w1[(k0 + 9) * 128 + n] : 0.f;
        g_w1f[l][j] = make_uint2(f2h2(v0, v1), f2h2(v2, v3));
    }
}

// ---------------- initial xf = h @ conv_w1[0] ----------------
__global__ __launch_bounds__(128) void matvec_kernel(const float* __restrict__ w) {
    constexpr int NT = 16;
    extern __shared__ float w_s[];
    __shared__ float in_s[NT * 128];
    int tid = threadIdx.x;
    for (int i = tid; i < 16384 / 4; i += 128)
        ((float4*)w_s)[i] = tf32r4(((const float4*)w)[i]);
    int n0 = blockIdx.x * NT;
    for (int i = tid; i < NT * 128 / 4; i += 128)
        ((float4*)in_s)[i] = tf32r4(((const float4*)&g_h[(size_t)n0 * 128])[i]);
    __syncthreads();
    float acc[NT];
    #pragma unroll
    for (int e = 0; e < NT; e++) acc[e] = 0.f;
    #pragma unroll 4
    for (int k = 0; k < 128; k++) {
        float wv = w_s[k * 128 + tid];
        #pragma unroll
        for (int e = 0; e < NT; e++)
            acc[e] = fmaf(in_s[e * 128 + k], wv, acc[e]);
    }
    #pragma unroll
    for (int e = 0; e < NT; e++)
        g_xf[(size_t)(n0 + e) * 128 + tid] = acc[e];
}

__global__ void zero_agg_kernel() {
    int i = blockIdx.x * blockDim.x + threadIdx.x;
    if (i < N_NODES * HDIM) g_agg[i] = 0.f;
}
__global__ void zero_sums_kernel() {
    int i = blockIdx.x * blockDim.x + threadIdx.x;
    if (i < NGRAPH * HDIM) g_sums[i] = 0.f;
    if (i < NGRAPH) g_cnt[i] = 0.f;
}

// ---------------- fp16 MMA edge kernel (3 blocks/SM) ----------------
// smem: buf 34816 (ea cols 0..63, then hid cols 0..127; msg aliases it)
//       w2f 32768 ; tail 2560  => 70144 B total
__global__ __launch_bounds__(256, 3) void edge_mma_kernel(
        int layer, const float* __restrict__ b1, const float* __restrict__ b2) {
    extern __shared__ char smraw[];
    __half* buf   = (__half*)smraw;                   // 128*136*2 = 34816
    float*  msg   = (float*)smraw;                    // 64*132*4 = 33792 (aliases buf)
    uint2*  w2f   = (uint2*)(smraw + 34816);          // 32768
    float*  b1_s  = (float*)(smraw + 67584);          // 128
    float*  b2_s  = b1_s + 128;
    float*  C_s   = b2_s + 128;
    int*    src_s = (int*)(C_s + 128);
    int*    dst_s = src_s + 128;

    int tid = threadIdx.x;
    int wid = tid >> 5;
    int lid = tid & 31;
    int gid = lid >> 2;
    int tg  = lid & 3;
    int lrow = lid & 15;
    int lcol = (lid >> 4) << 3;

    if (tid < 128) { b1_s[tid] = b1[tid]; b2_s[tid] = b2[tid]; }
    for (int i = tid; i < 2048; i += 256)
        ((uint4*)w2f)[i] = ((const uint4*)g_w2f[layer])[i];
    const uint2* w1f = g_w1f[layer];   // read direct (L1-resident, 16 KB)
    __syncthreads();

    int mbase = (wid & 3) * 32;
    int nb    = (wid >> 2) * 8;

    for (int t = blockIdx.x; t < NTILES; t += gridDim.x) {
        int e0 = t * EPT;
        if (tid < 128) {
            src_s[tid] = g_srcp[e0 + tid];
            dst_s[tid] = g_dstp[e0 + tid];
            C_s[tid]   = g_Cp[e0 + tid];
        }
        // ea tile -> buf cols 0..63
        for (int i = tid; i < 1024; i += 256) {
            int r = i >> 3, c8 = i & 7;
            uint4 v = ((const uint4*)(g_ea + (size_t)(e0 + r) * GPAD))[c8];
            *(uint4*)&buf[r * BUF_STR + c8 * 8] = v;
        }
        __syncthreads();

        float4 acc[2][8];
        #pragma unroll
        for (int mi = 0; mi < 2; mi++)
            #pragma unroll
            for (int ni = 0; ni < 8; ni++)
                acc[mi][ni] = make_float4(0.f, 0.f, 0.f, 0.f);

        // GEMM1: K=64 (reads buf cols 0..63; w1 frags direct from global)
        #pragma unroll
        for (int kt = 0; kt < 4; kt++) {
            uint32_t a0[4], a1[4];
            ldsm4(a0, &buf[(mbase + lrow) * BUF_STR + kt * 16 + lcol]);
            ldsm4(a1, &buf[(mbase + 16 + lrow) * BUF_STR + kt * 16 + lcol]);
            #pragma unroll
            for (int ni = 0; ni < 8; ni++) {
                uint2 b = w1f[((nb + ni) * 4 + kt) * 32 + lid];
                mma16816(acc[0][ni], a0, b);
                mma16816(acc[1][ni], a1, b);
            }
        }
        __syncthreads();   // all warps done reading ea before hid overwrites buf

        // ssp -> fp16 HID (buf cols 0..127)
        #pragma unroll
        for (int mi = 0; mi < 2; mi++) {
            int ra = mbase + mi * 16 + gid;
            int rb = ra + 8;
            #pragma unroll
            for (int ni = 0; ni < 8; ni++) {
                int c0 = (nb + ni) * 8 + 2 * tg;
                float4 v = acc[mi][ni];
                float ba = b1_s[c0], bb = b1_s[c0 + 1];
                *(uint32_t*)&buf[ra * BUF_STR + c0] =
                    f2h2(sspf_fast(v.x + ba), sspf_fast(v.y + bb));
                *(uint32_t*)&buf[rb * BUF_STR + c0] =
                    f2h2(sspf_fast(v.z + ba), sspf_fast(v.w + bb));
            }
        }
        __syncthreads();

        #pragma unroll
        for (int mi = 0; mi < 2; mi++)
            #pragma unroll
            for (int ni = 0; ni < 8; ni++)
                acc[mi][ni] = make_float4(0.f, 0.f, 0.f, 0.f);

        // GEMM2: K=128
        #pragma unroll
        for (int kt = 0; kt < 8; kt++) {
            uint32_t a0[4], a1[4];
            ldsm4(a0, &buf[(mbase + lrow) * BUF_STR + kt * 16 + lcol]);
            ldsm4(a1, &buf[(mbase + 16 + lrow) * BUF_STR + kt * 16 + lcol]);
            #pragma unroll
            for (int ni = 0; ni < 8; ni++) {
                uint2 b = w2f[((nb + ni) * 8 + kt) * 32 + lid];
                mma16816(acc[0][ni], a0, b);
                mma16816(acc[1][ni], a1, b);
            }
        }
        __syncthreads();   // hid consumed; msg may alias buf

        // epilogue: stage (C2+b2)*C; reducer multiplies by xf[src] (coalesced)
        #pragma unroll
        for (int mi = 0; mi < 2; mi++) {
            int ra = mbase + mi * 16 + gid;
            int rb = ra + 8;
            int ba = (wid & 3) * 16 + gid;
            int bbr = ba + 8;
            float Ca = C_s[ra], Cb = C_s[rb];
            #pragma unroll
            for (int ni = 0; ni < 8; ni++) {
                int c0 = (nb + ni) * 8 + 2 * tg;
                float4 v = acc[mi][ni];
                float2 bv = *(const float2*)&b2_s[c0];
                *(float2*)&msg[ba * MSTR + c0] =
                    make_float2((v.x + bv.x) * Ca, (v.y + bv.y) * Ca);
                *(float2*)&msg[bbr * MSTR + c0] =
                    make_float2((v.z + bv.x) * Cb, (v.w + bv.y) * Cb);
            }
            __syncthreads();
            {
                int cg = tid & 31;
                int chunk = tid >> 5;
                int b0 = chunk * 8;
                int r0 = (chunk >> 1) * 32 + mi * 16 + (chunk & 1) * 8;
                float4 run = make_float4(0.f, 0.f, 0.f, 0.f);
                int cur = dst_s[r0];
                #pragma unroll
                for (int j = 0; j < 8; j++) {
                    int dd = dst_s[r0 + j];
                    float4 m = *(float4*)&msg[(b0 + j) * MSTR + cg * 4];
                    float4 xv = *(const float4*)&g_xf[(size_t)src_s[r0 + j] * 128 + cg * 4];
                    if (dd != cur) {
                        atomicAdd((float4*)&g_agg[(size_t)cur * 128 + cg * 4], run);
                        run = make_float4(0.f, 0.f, 0.f, 0.f);
                        cur = dd;
                    }
                    run.x += m.x * xv.x; run.y += m.y * xv.y;
                    run.z += m.z * xv.z; run.w += m.w * xv.w;
                }
                atomicAdd((float4*)&g_agg[(size_t)cur * 128 + cg * 4], run);
            }
            __syncthreads();
        }
    }
}

// ---------------- fused node kernel (persistent; zeroes g_agg) -------------
__global__ __launch_bounds__(256, 1) void node_fused_kernel(
        int layer, const float* __restrict__ bA, const float* __restrict__ bB,
        int do_c) {
    extern __shared__ char smraw[];
    __half* in_s = (__half*)smraw;
    __half* x_s  = (__half*)(smraw + 34816);
    uint2*  wAf  = (uint2*)(smraw + 69632);
    uint2*  wBf  = (uint2*)(smraw + 102400);
    uint2*  wCf  = (uint2*)(smraw + 135168);
    float*  bA_s = (float*)(smraw + 167936);
    float*  bB_s = bA_s + 128;

    int tid = threadIdx.x;
    int wid = tid >> 5;
    int lid = tid & 31;
    int gid = lid >> 2;
    int tg  = lid & 3;
    int lrow = lid & 15;
    int lcol = (lid >> 4) << 3;

    if (tid < 128) { bA_s[tid] = bA[tid]; bB_s[tid] = bB[tid]; }
    for (int i = tid; i < 2048; i += 256) {
        ((uint4*)wAf)[i] = ((const uint4*)g_wAf[layer])[i];
        ((uint4*)wBf)[i] = ((const uint4*)g_wBf[layer])[i];
        if (do_c)
            ((uint4*)wCf)[i] = ((const uint4*)g_wCf[layer + 1])[i];
    }
    __syncthreads();

    int mbase = (wid & 3) * 32;
    int nb    = (wid >> 2) * 8;

    for (int tile = blockIdx.x; tile < NODE_TILES; tile += gridDim.x) {
        int n0 = tile * 128;
        for (int i = tid; i < 128 * 32; i += 256) {
            int r = i >> 5, c4 = i & 31;
            float4 v = make_float4(0.f, 0.f, 0.f, 0.f);
            if (n0 + r < N_NODES) {
                v = ((const float4*)&g_agg[(size_t)(n0 + r) * 128])[c4];
                ((float4*)&g_agg[(size_t)(n0 + r) * 128])[c4] =
                    make_float4(0.f, 0.f, 0.f, 0.f);
            }
            *(uint2*)&in_s[r * BUF_STR + c4 * 4] = make_uint2(f2h2(v.x, v.y), f2h2(v.z, v.w));
        }
        __syncthreads();

        float4 acc[2][8];
        // ---- GEMM A ----
        #pragma unroll
        for (int mi = 0; mi < 2; mi++)
            #pragma unroll
            for (int ni = 0; ni < 8; ni++)
                acc[mi][ni] = make_float4(0.f, 0.f, 0.f, 0.f);
        #pragma unroll
        for (int kt = 0; kt < 8; kt++) {
            uint32_t a0[4], a1[4];
            ldsm4(a0, &in_s[(mbase + lrow) * BUF_STR + kt * 16 + lcol]);
            ldsm4(a1, &in_s[(mbase + 16 + lrow) * BUF_STR + kt * 16 + lcol]);
            #pragma unroll
            for (int ni = 0; ni < 8; ni++) {
                uint2 b = wAf[((nb + ni) * 8 + kt) * 32 + lid];
                mma16816(acc[0][ni], a0, b);
                mma16816(acc[1][ni], a1, b);
            }
        }
        #pragma unroll
        for (int mi = 0; mi < 2; mi++) {
            int ra = mbase + mi * 16 + gid;
            int rb = ra + 8;
            #pragma unroll
            for (int ni = 0; ni < 8; ni++) {
                int c0 = (nb + ni) * 8 + 2 * tg;
                float4 v = acc[mi][ni];
                float ba = bA_s[c0], bb = bA_s[c0 + 1];
                *(uint32_t*)&x_s[ra * BUF_STR + c0] =
                    f2h2(sspf_fast(v.x + ba), sspf_fast(v.y + bb));
                *(uint32_t*)&x_s[rb * BUF_STR + c0] =
                    f2h2(sspf_fast(v.z + ba), sspf_fast(v.w + bb));
            }
        }
        __syncthreads();

        // ---- GEMM B: h += x @ wB + bB ----
        #pragma unroll
        for (int mi = 0; mi < 2; mi++)
            #pragma unroll
            for (int ni = 0; ni < 8; ni++)
                acc[mi][ni] = make_float4(0.f, 0.f, 0.f, 0.f);
        #pragma unroll
        for (int kt = 0; kt < 8; kt++) {
            uint32_t a0[4], a1[4];
            ldsm4(a0, &x_s[(mbase + lrow) * BUF_STR + kt * 16 + lcol]);
            ldsm4(a1, &x_s[(mbase + 16 + lrow) * BUF_STR + kt * 16 + lcol]);
            #pragma unroll
            for (int ni = 0; ni < 8; ni++) {
                uint2 b = wBf[((nb + ni) * 8 + kt) * 32 + lid];
                mma16816(acc[0][ni], a0, b);
                mma16816(acc[1][ni], a1, b);
            }
        }
        #pragma unroll
        for (int mi = 0; mi < 2; mi++) {
            int ra = mbase + mi * 16 + gid;
            int rb = ra + 8;
            int na = n0 + ra, nbn = n0 + rb;
            #pragma unroll
            for (int ni = 0; ni < 8; ni++) {
                int c0 = (nb + ni) * 8 + 2 * tg;
                float4 v = acc[mi][ni];
                float ba = bB_s[c0], bb = bB_s[c0 + 1];
                float hx = 0.f, hy = 0.f, hz = 0.f, hw = 0.f;
                if (na < N_NODES) {
                    float2 hv = *(float2*)&g_h[(size_t)na * 128 + c0];
                    hx = hv.x + v.x + ba;
                    hy = hv.y + v.y + bb;
                    *(float2*)&g_h[(size_t)na * 128 + c0] = make_float2(hx, hy);
                }
                if (nbn < N_NODES) {
                    float2 hv = *(float2*)&g_h[(size_t)nbn * 128 + c0];
                    hz = hv.x + v.z + ba;
                    hw = hv.y + v.w + bb;
                    *(float2*)&g_h[(size_t)nbn * 128 + c0] = make_float2(hz, hw);
                }
                *(uint32_t*)&in_s[ra * BUF_STR + c0] = f2h2(hx, hy);
                *(uint32_t*)&in_s[rb * BUF_STR + c0] = f2h2(hz, hw);
            }
        }
        __syncthreads();

        if (do_c) {
            // ---- GEMM C: xf = h @ wC ----
            #pragma unroll
            for (int mi = 0; mi < 2; mi++)
                #pragma unroll
                for (int ni = 0; ni < 8; ni++)
                    acc[mi][ni] = make_float4(0.f, 0.f, 0.f, 0.f);
            #pragma unroll
            for (int kt = 0; kt < 8; kt++) {
                uint32_t a0[4], a1[4];
                ldsm4(a0, &in_s[(mbase + lrow) * BUF_STR + kt * 16 + lcol]);
                ldsm4(a1, &in_s[(mbase + 16 + lrow) * BUF_STR + kt * 16 + lcol]);
                #pragma unroll
                for (int ni = 0; ni < 8; ni++) {
                    uint2 b = wCf[((nb + ni) * 8 + kt) * 32 + lid];
                    mma16816(acc[0][ni], a0, b);
                    mma16816(acc[1][ni], a1, b);
                }
            }
            #pragma unroll
            for (int mi = 0; mi < 2; mi++) {
                int ra = mbase + mi * 16 + gid;
                int rb = ra + 8;
                int na = n0 + ra, nbn = n0 + rb;
                #pragma unroll
                for (int ni = 0; ni < 8; ni++) {
                    int c0 = (nb + ni) * 8 + 2 * tg;
                    float4 v = acc[mi][ni];
                    if (na < N_NODES)
                        *(float2*)&g_xf[(size_t)na * 128 + c0] = make_float2(v.x, v.y);
                    if (nbn < N_NODES)
                        *(float2*)&g_xf[(size_t)nbn * 128 + c0] = make_float2(v.z, v.w);
                }
            }
        }
        __syncthreads();
    }
}

// ---------------- output head ----------------
__global__ __launch_bounds__(128) void out_kernel(
        const float* __restrict__ w1, const float* __restrict__ b1,
        const float* __restrict__ w2, const float* __restrict__ b2,
        const int* __restrict__ batch) {
    constexpr int NT = 16;
    extern __shared__ float sm[];
    float* w1_s = sm;
    float* w2_s = sm + 16384;
    __shared__ float in_s[NT * 128];
    __shared__ float x_s[NT * 128];
    int tid = threadIdx.x;
    for (int i = tid; i < 4096; i += 128) {
        ((float4*)w1_s)[i] = tf32r4(((const float4*)w1)[i]);
        ((float4*)w2_s)[i] = tf32r4(((const float4*)w2)[i]);
    }
    int n0 = blockIdx.x * NT;
    for (int i = tid; i < NT * 128 / 4; i += 128)
        ((float4*)in_s)[i] = tf32r4(((const float4*)&g_h[(size_t)n0 * 128])[i]);
    __syncthreads();
    float acc[NT];
    float bb1 = b1[tid];
    #pragma unroll
    for (int e = 0; e < NT; e++) acc[e] = bb1;
    #pragma unroll 4
    for (int k = 0; k < 128; k++) {
        float wv = w1_s[k * 128 + tid];
        #pragma unroll
        for (int e = 0; e < NT; e++)
            acc[e] = fmaf(in_s[e * 128 + k], wv, acc[e]);
    }
    #pragma unroll
    for (int e = 0; e < NT; e++)
        x_s[e * 128 + tid] = tf32r(sspf(acc[e]));
    __syncthreads();
    float bb2 = b2[tid];
    #pragma unroll
    for (int e = 0; e < NT; e++) acc[e] = bb2;
    #pragma unroll 4
    for (int k = 0; k < 128; k++) {
        float wv = w2_s[k * 128 + tid];
        #pragma unroll
        for (int e = 0; e < NT; e++)
            acc[e] = fmaf(x_s[e * 128 + k], wv, acc[e]);
    }
    #pragma unroll
    for (int e = 0; e < NT; e++) {
        int b = batch[n0 + e];
        atomicAdd(&g_sums[b * 128 + tid], acc[e]);
        if (tid == 0) atomicAdd(&g_cnt[b], 1.0f);
    }
}

__global__ void finalize_kernel(float* __restrict__ out) {
    int i = blockIdx.x * blockDim.x + threadIdx.x;
    if (i >= NGRAPH * HDIM) return;
    out[i] = g_sums[i] / fmaxf(g_cnt[i >> 7], 1.0f);
}

// ---------------- launcher ----------------
extern "C" void kernel_launch(void* const* d_in, const int* in_sizes, int n_in,
                              void* d_out, int out_size) {
    const int*   z       = (const int*)d_in[0];
    const float* pos     = (const float*)d_in[1];
    const int*   ei      = (const int*)d_in[2];
    const int*   batch   = (const int*)d_in[3];
    const float* emb     = (const float*)d_in[4];
    const float* mlp_w1  = (const float*)d_in[5];
    const float* mlp_b1  = (const float*)d_in[6];
    const float* mlp_w2  = (const float*)d_in[7];
    const float* mlp_b2  = (const float*)d_in[8];
    const float* conv_w1 = (const float*)d_in[9];
    const float* conv_w2 = (const float*)d_in[10];
    const float* conv_b2 = (const float*)d_in[11];
    const float* lin_w   = (const float*)d_in[12];
    const float* lin_b   = (const float*)d_in[13];
    const float* out1_w  = (const float*)d_in[14];
    const float* out1_b  = (const float*)d_in[15];
    const float* out2_w  = (const float*)d_in[16];
    const float* out2_b  = (const float*)d_in[17];
    float* out = (float*)d_out;

    const int* src = ei;
    const int* dst = ei + N_EDGES;

    const int EDGE_SMEM = 70144;
    const int NODE_SMEM = 168960;
    const int MV_SMEM   = 16384 * 4;
    const int NU_SMEM   = 32768 * 4;

    cudaFuncSetAttribute(edge_mma_kernel, cudaFuncAttributeMaxDynamicSharedMemorySize, EDGE_SMEM);
    cudaFuncSetAttribute(node_fused_kernel, cudaFuncAttributeMaxDynamicSharedMemorySize, NODE_SMEM);
    cudaFuncSetAttribute(matvec_kernel, cudaFuncAttributeMaxDynamicSharedMemorySize, MV_SMEM);
    cudaFuncSetAttribute(out_kernel, cudaFuncAttributeMaxDynamicSharedMemorySize, NU_SMEM);

    init_h_kernel<<<(N_NODES * HDIM + 255) / 256, 256>>>(z, emb);
    dist_kernel<<<(N_EDGES + 255) / 256, 256>>>(src, dst, pos);
    zero_hist_kernel<<<(N_NODES + 255) / 256, 256>>>();
    hist_kernel<<<(N_EDGES + 255) / 256, 256>>>(dst);
    scan_kernel<<<1, 1024>>>();
    scatter_kernel<<<(N_EDGES + 255) / 256, 256>>>(src, dst);
    gauss_kernel<<<N_EDGES / 256, 256>>>();
    build_frags_kernel<<<(NLAYERS * 4096 + 255) / 256, 256>>>(
        mlp_w1, mlp_w2, conv_w2, lin_w, conv_w1);
    zero_agg_kernel<<<(N_NODES * HDIM + 255) / 256, 256>>>();

    matvec_kernel<<<N_NODES / 16, 128, MV_SMEM>>>(conv_w1);   // xf for layer 0

    for (int l = 0; l < NLAYERS; l++) {
        edge_mma_kernel<<<444, 256, EDGE_SMEM>>>(
            l, mlp_b1 + (size_t)l * 128, mlp_b2 + (size_t)l * 128);
        int do_c = (l < NLAYERS - 1) ? 1 : 0;
        node_fused_kernel<<<148, 256, NODE_SMEM>>>(
            l, conv_b2 + (size_t)l * 128, lin_b + (size_t)l * 128, do_c);
    }

    zero_sums_kernel<<<(NGRAPH * HDIM + 255) / 256, 256>>>();
    out_kernel<<<N_NODES / 16, 128, NU_SMEM>>>(out1_w, out1_b, out2_w, out2_b, batch);
    finalize_kernel<<<(NGRAPH * HDIM + 255) / 256, 256>>>(out);
}

// round 10
// speedup vs baseline: 1.3529x; 1.3529x over previous
#include <cuda_runtime.h>
#include <cuda_fp16.h>
#include <math.h>
#include <stdint.h>

#define N_NODES 20000
#define N_EDGES 640000
#define HDIM    128
#define GDIM    50
#define GPAD    64
#define NLAYERS 6
#define NGRAPH  64
#define CUTOFF  10.0f
#define LOG2F_  0.69314718055994531f
#define PI_     3.14159265358979323846f

#define EPT     128
#define NTILES  (N_EDGES / EPT)
#define EA_STR  72
#define HID_STR 136
#define MSTR    132
#define NODE_TILES ((N_NODES + 127) / 128)

// ---------------- device scratch ----------------
static __device__ __align__(16) float  g_h[N_NODES * HDIM];
static __device__ __align__(16) float  g_xf[N_NODES * HDIM];
static __device__ __align__(16) float  g_agg[N_NODES * HDIM];
static __device__ __align__(16) float  g_d[N_EDGES];
static __device__ __align__(16) float  g_C[N_EDGES];
static __device__ __align__(16) __half g_ea[(size_t)N_EDGES * GPAD]; // PERMUTED order
static __device__ __align__(16) float  g_sums[NGRAPH * HDIM];
static __device__ float g_cnt[NGRAPH];
static __device__ int   g_hist[N_NODES];
static __device__ int   g_perm[N_EDGES];
static __device__ int   g_srcp[N_EDGES];
static __device__ int   g_dstp[N_EDGES];
static __device__ float g_Cp[N_EDGES];
// prebuilt fp16 B-fragments (m16n8k16 layout), all layers
static __device__ __align__(16) uint2 g_w1f[NLAYERS][2048];
static __device__ __align__(16) uint2 g_w2f[NLAYERS][4096];
static __device__ __align__(16) uint2 g_wAf[NLAYERS][4096];
static __device__ __align__(16) uint2 g_wBf[NLAYERS][4096];
static __device__ __align__(16) uint2 g_wCf[NLAYERS][4096];

// ---------------- helpers ----------------
__device__ __forceinline__ float tf32r(float x) {
    uint32_t r;
    asm("cvt.rna.tf32.f32 %0, %1;" : "=r"(r) : "f"(x));
    return __uint_as_float(r);
}
__device__ __forceinline__ float4 tf32r4(float4 v) {
    v.x = tf32r(v.x); v.y = tf32r(v.y); v.z = tf32r(v.z); v.w = tf32r(v.w);
    return v;
}
__device__ __forceinline__ float sspf(float x) {
    return fmaxf(x, 0.f) + log1pf(expf(-fabsf(x))) - LOG2F_;
}
__device__ __forceinline__ float sspf_fast(float x) {
    return fmaxf(x, 0.f) + __logf(1.f + __expf(-fabsf(x))) - LOG2F_;
}
__device__ __forceinline__ uint32_t smem_u32(const void* p) {
    uint32_t a;
    asm("{ .reg .u64 t; cvta.to.shared.u64 t, %1; cvt.u32.u64 %0, t; }" : "=r"(a) : "l"(p));
    return a;
}
__device__ __forceinline__ uint32_t f2h2(float lo, float hi) {
    __half2 h = __floats2half2_rn(lo, hi);
    return *reinterpret_cast<uint32_t*>(&h);
}
__device__ __forceinline__ void mma16816(float4& d, const uint32_t a[4], uint2 b) {
    asm volatile(
        "mma.sync.aligned.m16n8k16.row.col.f32.f16.f16.f32 "
        "{%0,%1,%2,%3}, {%4,%5,%6,%7}, {%8,%9}, {%0,%1,%2,%3};\n"
        : "+f"(d.x), "+f"(d.y), "+f"(d.z), "+f"(d.w)
        : "r"(a[0]), "r"(a[1]), "r"(a[2]), "r"(a[3]), "r"(b.x), "r"(b.y));
}
__device__ __forceinline__ void ldsm4(uint32_t r[4], const void* p) {
    uint32_t a = smem_u32(p);
    asm volatile("ldmatrix.sync.aligned.m8n8.x4.shared.b16 {%0,%1,%2,%3}, [%4];"
        : "=r"(r[0]), "=r"(r[1]), "=r"(r[2]), "=r"(r[3]) : "r"(a));
}

// ---------------- precompute ----------------
__global__ void init_h_kernel(const int* __restrict__ z, const float* __restrict__ emb) {
    int i = blockIdx.x * blockDim.x + threadIdx.x;
    if (i >= N_NODES * HDIM) return;
    int n = i >> 7, j = i & 127;
    g_h[i] = emb[z[n] * HDIM + j];
}

__global__ void dist_kernel(const int* __restrict__ src, const int* __restrict__ dst,
                            const float* __restrict__ pos) {
    int e = blockIdx.x * blockDim.x + threadIdx.x;
    if (e >= N_EDGES) return;
    int s = src[e], t = dst[e];
    float dx = pos[s * 3 + 0] - pos[t * 3 + 0];
    float dy = pos[s * 3 + 1] - pos[t * 3 + 1];
    float dz = pos[s * 3 + 2] - pos[t * 3 + 2];
    float d = sqrtf(dx * dx + dy * dy + dz * dz);
    g_d[e] = d;
    g_C[e] = 0.5f * (cosf(d * (PI_ / CUTOFF)) + 1.0f);
}

__global__ void zero_hist_kernel() {
    int i = blockIdx.x * blockDim.x + threadIdx.x;
    if (i < N_NODES) g_hist[i] = 0;
}
__global__ void hist_kernel(const int* __restrict__ dst) {
    int e = blockIdx.x * blockDim.x + threadIdx.x;
    if (e < N_EDGES) atomicAdd(&g_hist[dst[e]], 1);
}
__global__ void scan_kernel() {
    __shared__ int s[1024];
    int t = threadIdx.x;
    const int CH = (N_NODES + 1023) / 1024;
    int base = t * CH;
    int sum = 0;
    for (int i = 0; i < CH; i++) {
        int idx = base + i;
        if (idx < N_NODES) sum += g_hist[idx];
    }
    s[t] = sum;
    __syncthreads();
    for (int off = 1; off < 1024; off <<= 1) {
        int v = (t >= off) ? s[t - off] : 0;
        __syncthreads();
        s[t] += v;
        __syncthreads();
    }
    int run = (t > 0) ? s[t - 1] : 0;
    for (int i = 0; i < CH; i++) {
        int idx = base + i;
        if (idx < N_NODES) { int c = g_hist[idx]; g_hist[idx] = run; run += c; }
    }
}
__global__ void scatter_kernel(const int* __restrict__ src, const int* __restrict__ dst) {
    int e = blockIdx.x * blockDim.x + threadIdx.x;
    if (e >= N_EDGES) return;
    int d = dst[e];
    int p = atomicAdd(&g_hist[d], 1);
    g_perm[p] = e;
    g_srcp[p] = src[e];
    g_dstp[p] = d;
    g_Cp[p]   = g_C[e];
}

// gaussian table: only the ±6-center window around d is nonzero in fp16
// (exp(-12*diff^2) underflows fp16 rounding beyond it) — bit-identical to
// evaluating all 50 centers, at 13 exps/edge instead of 50.
__global__ __launch_bounds__(256) void gauss_kernel() {
    __shared__ __half buf[256][GPAD];      // 32 KB
    int tid = threadIdx.x;
    int e = blockIdx.x * 256 + tid;
    const float step  = CUTOFF / (GDIM - 1);
    const float coeff = -0.5f / (step * step);
    #pragma unroll
    for (int j = 0; j < 8; j++)
        ((uint4*)buf[tid])[j] = make_uint4(0, 0, 0, 0);

    float d  = g_d[g_perm[e]];
    int c0 = (int)rintf(d / step);
    #pragma unroll
    for (int k = -6; k <= 6; k++) {
        int c = c0 + k;
        if (c >= 0 && c < GDIM) {
            float diff = d - c * step;
            buf[tid][c] = __float2half_rn(__expf(coeff * diff * diff));
        }
    }
    __syncthreads();
    size_t e0 = (size_t)blockIdx.x * 256;
    for (int i = tid; i < 256 * 8; i += 256) {
        int r = i >> 3, j = i & 7;
        ((uint4*)&g_ea[(e0 + r) * GPAD])[j] = ((uint4*)buf[r])[j];
    }
}

// build all fp16 B-fragments once (m16n8k16 layout)
__device__ __forceinline__ uint2 frag_of(const float* w, int k0, int n) {
    return make_uint2(f2h2(w[k0 * 128 + n], w[(k0 + 1) * 128 + n]),
                      f2h2(w[(k0 + 8) * 128 + n], w[(k0 + 9) * 128 + n]));
}
__global__ void build_frags_kernel(const float* __restrict__ mlp_w1,
                                   const float* __restrict__ mlp_w2,
                                   const float* __restrict__ conv_w2,
                                   const float* __restrict__ lin_w,
                                   const float* __restrict__ conv_w1) {
    int i = blockIdx.x * blockDim.x + threadIdx.x;
    if (i >= NLAYERS * 4096) return;
    int l = i / 4096, j = i % 4096;
    int lane = j & 31;
    int g_ = lane >> 2, t_ = lane & 3;
    {
        int kt = (j >> 5) & 7, nt = j >> 8;
        int k0 = kt * 16 + 2 * t_, n = nt * 8 + g_;
        g_w2f[l][j] = frag_of(mlp_w2 + (size_t)l * 16384, k0, n);
        g_wAf[l][j] = frag_of(conv_w2 + (size_t)l * 16384, k0, n);
        g_wBf[l][j] = frag_of(lin_w + (size_t)l * 16384, k0, n);
        g_wCf[l][j] = frag_of(conv_w1 + (size_t)l * 16384, k0, n);
    }
    if (j < 2048) {
        int kt = (j >> 5) & 3, nt = j >> 7;
        int k0 = kt * 16 + 2 * t_, n = nt * 8 + g_;
        const float* w1 = mlp_w1 + (size_t)l * GDIM * 128;
        float v0 = (k0     < GDIM) ? w1[k0 * 128 + n]       : 0.f;
        float v1 = (k0 + 1 < GDIM) ? w1[(k0 + 1) * 128 + n] : 0.f;
        float v2 = (k0 + 8 < GDIM) ? w1[(k0 + 8) * 128 + n] : 0.f;
        float v3 = (k0 + 9 < GDIM) ? w1[(k0 + 9) * 128 + n] : 0.f;
        g_w1f[l][j] = make_uint2(f2h2(v0, v1), f2h2(v2, v3));
    }
}

// ---------------- initial xf = h @ conv_w1[0] ----------------
__global__ __launch_bounds__(128) void matvec_kernel(const float* __restrict__ w) {
    constexpr int NT = 16;
    extern __shared__ float w_s[];
    __shared__ float in_s[NT * 128];
    int tid = threadIdx.x;
    for (int i = tid; i < 16384 / 4; i += 128)
        ((float4*)w_s)[i] = tf32r4(((const float4*)w)[i]);
    int n0 = blockIdx.x * NT;
    for (int i = tid; i < NT * 128 / 4; i += 128)
        ((float4*)in_s)[i] = tf32r4(((const float4*)&g_h[(size_t)n0 * 128])[i]);
    __syncthreads();
    float acc[NT];
    #pragma unroll
    for (int e = 0; e < NT; e++) acc[e] = 0.f;
    #pragma unroll 4
    for (int k = 0; k < 128; k++) {
        float wv = w_s[k * 128 + tid];
        #pragma unroll
        for (int e = 0; e < NT; e++)
            acc[e] = fmaf(in_s[e * 128 + k], wv, acc[e]);
    }
    #pragma unroll
    for (int e = 0; e < NT; e++)
        g_xf[(size_t)(n0 + e) * 128 + tid] = acc[e];
}

__global__ void zero_agg_kernel() {
    int i = blockIdx.x * blockDim.x + threadIdx.x;
    if (i < N_NODES * HDIM) g_agg[i] = 0.f;
}
__global__ void zero_sums_kernel() {
    int i = blockIdx.x * blockDim.x + threadIdx.x;
    if (i < NGRAPH * HDIM) g_sums[i] = 0.f;
    if (i < NGRAPH) g_cnt[i] = 0.f;
}

// ---------------- fp16 MMA edge kernel (2 blocks/SM, ea prefetch) ----------
__global__ __launch_bounds__(256, 2) void edge_mma_kernel(
        int layer, const float* __restrict__ b1, const float* __restrict__ b2) {
    extern __shared__ char smraw[];
    __half* ea_s  = (__half*)smraw;                   // 18432
    __half* hid_s = (__half*)(smraw + 18432);         // 34816
    float*  msg   = (float*)(smraw + 18432);          // 33792, aliases hid ONLY
    uint2*  w1f   = (uint2*)(smraw + 53248);          // 16384
    uint2*  w2f   = (uint2*)(smraw + 69632);          // 32768
    float*  b1_s  = (float*)(smraw + 102400);
    float*  b2_s  = b1_s + 128;
    float*  C_s   = b2_s + 128;
    int*    src_s = (int*)(C_s + 128);
    int*    dst_s = src_s + 128;

    int tid = threadIdx.x;
    int wid = tid >> 5;
    int lid = tid & 31;
    int gid = lid >> 2;
    int tg  = lid & 3;
    int lrow = lid & 15;
    int lcol = (lid >> 4) << 3;

    if (tid < 128) { b1_s[tid] = b1[tid]; b2_s[tid] = b2[tid]; }
    for (int i = tid; i < 1024; i += 256)
        ((uint4*)w1f)[i] = ((const uint4*)g_w1f[layer])[i];
    for (int i = tid; i < 2048; i += 256)
        ((uint4*)w2f)[i] = ((const uint4*)g_w2f[layer])[i];
    __syncthreads();

    int mbase = (wid & 3) * 32;
    int nb    = (wid >> 2) * 8;

    // prefetch first tile into registers
    uint4 pf[4];
    int psrc = 0, pdst = 0;
    float pC = 0.f;
    int t = blockIdx.x;
    if (t < NTILES) {
        int e0 = t * EPT;
        #pragma unroll
        for (int j = 0; j < 4; j++) {
            int i = tid + 256 * j;
            int r = i >> 3, c8 = i & 7;
            pf[j] = ((const uint4*)(g_ea + (size_t)(e0 + r) * GPAD))[c8];
        }
        if (tid < 128) {
            psrc = g_srcp[e0 + tid];
            pdst = g_dstp[e0 + tid];
            pC   = g_Cp[e0 + tid];
        }
    }

    for (; t < NTILES; t += gridDim.x) {
        // commit prefetched tile
        #pragma unroll
        for (int j = 0; j < 4; j++) {
            int i = tid + 256 * j;
            int r = i >> 3, c8 = i & 7;
            *(uint4*)&ea_s[r * EA_STR + c8 * 8] = pf[j];
        }
        if (tid < 128) { src_s[tid] = psrc; dst_s[tid] = pdst; C_s[tid] = pC; }
        __syncthreads();

        float4 acc[2][8];
        #pragma unroll
        for (int mi = 0; mi < 2; mi++)
            #pragma unroll
            for (int ni = 0; ni < 8; ni++)
                acc[mi][ni] = make_float4(0.f, 0.f, 0.f, 0.f);

        // GEMM1: K=64
        #pragma unroll
        for (int kt = 0; kt < 4; kt++) {
            uint32_t a0[4], a1[4];
            ldsm4(a0, &ea_s[(mbase + lrow) * EA_STR + kt * 16 + lcol]);
            ldsm4(a1, &ea_s[(mbase + 16 + lrow) * EA_STR + kt * 16 + lcol]);
            #pragma unroll
            for (int ni = 0; ni < 8; ni++) {
                uint2 b = w1f[((nb + ni) * 4 + kt) * 32 + lid];
                mma16816(acc[0][ni], a0, b);
                mma16816(acc[1][ni], a1, b);
            }
        }

        // ssp -> fp16 HID
        #pragma unroll
        for (int mi = 0; mi < 2; mi++) {
            int ra = mbase + mi * 16 + gid;
            int rb = ra + 8;
            #pragma unroll
            for (int ni = 0; ni < 8; ni++) {
                int c0 = (nb + ni) * 8 + 2 * tg;
                float4 v = acc[mi][ni];
                float ba = b1_s[c0], bb = b1_s[c0 + 1];
                *(uint32_t*)&hid_s[ra * HID_STR + c0] =
                    f2h2(sspf_fast(v.x + ba), sspf_fast(v.y + bb));
                *(uint32_t*)&hid_s[rb * HID_STR + c0] =
                    f2h2(sspf_fast(v.z + ba), sspf_fast(v.w + bb));
            }
        }
        __syncthreads();   // ea_s dead from here

        // issue prefetch for the next tile (overlaps GEMM2 + epilogue)
        int tn = t + gridDim.x;
        if (tn < NTILES) {
            int e0n = tn * EPT;
            #pragma unroll
            for (int j = 0; j < 4; j++) {
                int i = tid + 256 * j;
                int r = i >> 3, c8 = i & 7;
                pf[j] = ((const uint4*)(g_ea + (size_t)(e0n + r) * GPAD))[c8];
            }
            if (tid < 128) {
                psrc = g_srcp[e0n + tid];
                pdst = g_dstp[e0n + tid];
                pC   = g_Cp[e0n + tid];
            }
        }

        #pragma unroll
        for (int mi = 0; mi < 2; mi++)
            #pragma unroll
            for (int ni = 0; ni < 8; ni++)
                acc[mi][ni] = make_float4(0.f, 0.f, 0.f, 0.f);

        // GEMM2: K=128
        #pragma unroll
        for (int kt = 0; kt < 8; kt++) {
            uint32_t a0[4], a1[4];
            ldsm4(a0, &hid_s[(mbase + lrow) * HID_STR + kt * 16 + lcol]);
            ldsm4(a1, &hid_s[(mbase + 16 + lrow) * HID_STR + kt * 16 + lcol]);
            #pragma unroll
            for (int ni = 0; ni < 8; ni++) {
                uint2 b = w2f[((nb + ni) * 8 + kt) * 32 + lid];
                mma16816(acc[0][ni], a0, b);
                mma16816(acc[1][ni], a1, b);
            }
        }
        __syncthreads();   // hid consumed; msg aliases hid

        // epilogue: stage (C2+b2)*C; reducer multiplies by xf[src] (coalesced)
        #pragma unroll
        for (int mi = 0; mi < 2; mi++) {
            int ra = mbase + mi * 16 + gid;
            int rb = ra + 8;
            int ba = (wid & 3) * 16 + gid;
            int bbr = ba + 8;
            float Ca = C_s[ra], Cb = C_s[rb];
            #pragma unroll
            for (int ni = 0; ni < 8; ni++) {
                int c0 = (nb + ni) * 8 + 2 * tg;
                float4 v = acc[mi][ni];
                float2 bv = *(const float2*)&b2_s[c0];
                *(float2*)&msg[ba * MSTR + c0] =
                    make_float2((v.x + bv.x) * Ca, (v.y + bv.y) * Ca);
                *(float2*)&msg[bbr * MSTR + c0] =
                    make_float2((v.z + bv.x) * Cb, (v.w + bv.y) * Cb);
            }
            __syncthreads();
            {
                int cg = tid & 31;
                int chunk = tid >> 5;
                int b0 = chunk * 8;
                int r0 = (chunk >> 1) * 32 + mi * 16 + (chunk & 1) * 8;
                float4 run = make_float4(0.f, 0.f, 0.f, 0.f);
                int cur = dst_s[r0];
                #pragma unroll
                for (int j = 0; j < 8; j++) {
                    int dd = dst_s[r0 + j];
                    float4 m = *(float4*)&msg[(b0 + j) * MSTR + cg * 4];
                    float4 xv = *(const float4*)&g_xf[(size_t)src_s[r0 + j] * 128 + cg * 4];
                    if (dd != cur) {
                        atomicAdd((float4*)&g_agg[(size_t)cur * 128 + cg * 4], run);
                        run = make_float4(0.f, 0.f, 0.f, 0.f);
                        cur = dd;
                    }
                    run.x += m.x * xv.x; run.y += m.y * xv.y;
                    run.z += m.z * xv.z; run.w += m.w * xv.w;
                }
                atomicAdd((float4*)&g_agg[(size_t)cur * 128 + cg * 4], run);
            }
            __syncthreads();
        }
    }
}

// ---------------- fused node kernel (persistent; zeroes g_agg) -------------
__global__ __launch_bounds__(256, 1) void node_fused_kernel(
        int layer, const float* __restrict__ bA, const float* __restrict__ bB,
        int do_c) {
    extern __shared__ char smraw[];
    __half* in_s = (__half*)smraw;
    __half* x_s  = (__half*)(smraw + 34816);
    uint2*  wAf  = (uint2*)(smraw + 69632);
    uint2*  wBf  = (uint2*)(smraw + 102400);
    uint2*  wCf  = (uint2*)(smraw + 135168);
    float*  bA_s = (float*)(smraw + 167936);
    float*  bB_s = bA_s + 128;

    int tid = threadIdx.x;
    int wid = tid >> 5;
    int lid = tid & 31;
    int gid = lid >> 2;
    int tg  = lid & 3;
    int lrow = lid & 15;
    int lcol = (lid >> 4) << 3;

    if (tid < 128) { bA_s[tid] = bA[tid]; bB_s[tid] = bB[tid]; }
    for (int i = tid; i < 2048; i += 256) {
        ((uint4*)wAf)[i] = ((const uint4*)g_wAf[layer])[i];
        ((uint4*)wBf)[i] = ((const uint4*)g_wBf[layer])[i];
        if (do_c)
            ((uint4*)wCf)[i] = ((const uint4*)g_wCf[layer + 1])[i];
    }
    __syncthreads();

    int mbase = (wid & 3) * 32;
    int nb    = (wid >> 2) * 8;

    for (int tile = blockIdx.x; tile < NODE_TILES; tile += gridDim.x) {
        int n0 = tile * 128;
        for (int i = tid; i < 128 * 32; i += 256) {
            int r = i >> 5, c4 = i & 31;
            float4 v = make_float4(0.f, 0.f, 0.f, 0.f);
            if (n0 + r < N_NODES) {
                v = ((const float4*)&g_agg[(size_t)(n0 + r) * 128])[c4];
                ((float4*)&g_agg[(size_t)(n0 + r) * 128])[c4] =
                    make_float4(0.f, 0.f, 0.f, 0.f);
            }
            *(uint2*)&in_s[r * HID_STR + c4 * 4] = make_uint2(f2h2(v.x, v.y), f2h2(v.z, v.w));
        }
        __syncthreads();

        float4 acc[2][8];
        // ---- GEMM A ----
        #pragma unroll
        for (int mi = 0; mi < 2; mi++)
            #pragma unroll
            for (int ni = 0; ni < 8; ni++)
                acc[mi][ni] = make_float4(0.f, 0.f, 0.f, 0.f);
        #pragma unroll
        for (int kt = 0; kt < 8; kt++) {
            uint32_t a0[4], a1[4];
            ldsm4(a0, &in_s[(mbase + lrow) * HID_STR + kt * 16 + lcol]);
            ldsm4(a1, &in_s[(mbase + 16 + lrow) * HID_STR + kt * 16 + lcol]);
            #pragma unroll
            for (int ni = 0; ni < 8; ni++) {
                uint2 b = wAf[((nb + ni) * 8 + kt) * 32 + lid];
                mma16816(acc[0][ni], a0, b);
                mma16816(acc[1][ni], a1, b);
            }
        }
        #pragma unroll
        for (int mi = 0; mi < 2; mi++) {
            int ra = mbase + mi * 16 + gid;
            int rb = ra + 8;
            #pragma unroll
            for (int ni = 0; ni < 8; ni++) {
                int c0 = (nb + ni) * 8 + 2 * tg;
                float4 v = acc[mi][ni];
                float ba = bA_s[c0], bb = bA_s[c0 + 1];
                *(uint32_t*)&x_s[ra * HID_STR + c0] =
                    f2h2(sspf_fast(v.x + ba), sspf_fast(v.y + bb));
                *(uint32_t*)&x_s[rb * HID_STR + c0] =
                    f2h2(sspf_fast(v.z + ba), sspf_fast(v.w + bb));
            }
        }
        __syncthreads();

        // ---- GEMM B: h += x @ wB + bB ----
        #pragma unroll
        for (int mi = 0; mi < 2; mi++)
            #pragma unroll
            for (int ni = 0; ni < 8; ni++)
                acc[mi][ni] = make_float4(0.f, 0.f, 0.f, 0.f);
        #pragma unroll
        for (int kt = 0; kt < 8; kt++) {
            uint32_t a0[4], a1[4];
            ldsm4(a0, &x_s[(mbase + lrow) * HID_STR + kt * 16 + lcol]);
            ldsm4(a1, &x_s[(mbase + 16 + lrow) * HID_STR + kt * 16 + lcol]);
            #pragma unroll
            for (int ni = 0; ni < 8; ni++) {
                uint2 b = wBf[((nb + ni) * 8 + kt) * 32 + lid];
                mma16816(acc[0][ni], a0, b);
                mma16816(acc[1][ni], a1, b);
            }
        }
        #pragma unroll
        for (int mi = 0; mi < 2; mi++) {
            int ra = mbase + mi * 16 + gid;
            int rb = ra + 8;
            int na = n0 + ra, nbn = n0 + rb;
            #pragma unroll
            for (int ni = 0; ni < 8; ni++) {
                int c0 = (nb + ni) * 8 + 2 * tg;
                float4 v = acc[mi][ni];
                float ba = bB_s[c0], bb = bB_s[c0 + 1];
                float hx = 0.f, hy = 0.f, hz = 0.f, hw = 0.f;
                if (na < N_NODES) {
                    float2 hv = *(float2*)&g_h[(size_t)na * 128 + c0];
                    hx = hv.x + v.x + ba;
                    hy = hv.y + v.y + bb;
                    *(float2*)&g_h[(size_t)na * 128 + c0] = make_float2(hx, hy);
                }
                if (nbn < N_NODES) {
                    float2 hv = *(float2*)&g_h[(size_t)nbn * 128 + c0];
                    hz = hv.x + v.z + ba;
                    hw = hv.y + v.w + bb;
                    *(float2*)&g_h[(size_t)nbn * 128 + c0] = make_float2(hz, hw);
                }
                *(uint32_t*)&in_s[ra * HID_STR + c0] = f2h2(hx, hy);
                *(uint32_t*)&in_s[rb * HID_STR + c0] = f2h2(hz, hw);
            }
        }
        __syncthreads();

        if (do_c) {
            // ---- GEMM C: xf = h @ wC ----
            #pragma unroll
            for (int mi = 0; mi < 2; mi++)
                #pragma unroll
                for (int ni = 0; ni < 8; ni++)
                    acc[mi][ni] = make_float4(0.f, 0.f, 0.f, 0.f);
            #pragma unroll
            for (int kt = 0; kt < 8; kt++) {
                uint32_t a0[4], a1[4];
                ldsm4(a0, &in_s[(mbase + lrow) * HID_STR + kt * 16 + lcol]);
                ldsm4(a1, &in_s[(mbase + 16 + lrow) * HID_STR + kt * 16 + lcol]);
                #pragma unroll
                for (int ni = 0; ni < 8; ni++) {
                    uint2 b = wCf[((nb + ni) * 8 + kt) * 32 + lid];
                    mma16816(acc[0][ni], a0, b);
                    mma16816(acc[1][ni], a1, b);
                }
            }
            #pragma unroll
            for (int mi = 0; mi < 2; mi++) {
                int ra = mbase + mi * 16 + gid;
                int rb = ra + 8;
                int na = n0 + ra, nbn = n0 + rb;
                #pragma unroll
                for (int ni = 0; ni < 8; ni++) {
                    int c0 = (nb + ni) * 8 + 2 * tg;
                    float4 v = acc[mi][ni];
                    if (na < N_NODES)
                        *(float2*)&g_xf[(size_t)na * 128 + c0] = make_float2(v.x, v.y);
                    if (nbn < N_NODES)
                        *(float2*)&g_xf[(size_t)nbn * 128 + c0] = make_float2(v.z, v.w);
                }
            }
        }
        __syncthreads();
    }
}

// ---------------- output head ----------------
__global__ __launch_bounds__(128) void out_kernel(
        const float* __restrict__ w1, const float* __restrict__ b1,
        const float* __restrict__ w2, const float* __restrict__ b2,
        const int* __restrict__ batch) {
    constexpr int NT = 16;
    extern __shared__ float sm[];
    float* w1_s = sm;
    float* w2_s = sm + 16384;
    __shared__ float in_s[NT * 128];
    __shared__ float x_s[NT * 128];
    int tid = threadIdx.x;
    for (int i = tid; i < 4096; i += 128) {
        ((float4*)w1_s)[i] = tf32r4(((const float4*)w1)[i]);
        ((float4*)w2_s)[i] = tf32r4(((const float4*)w2)[i]);
    }
    int n0 = blockIdx.x * NT;
    for (int i = tid; i < NT * 128 / 4; i += 128)
        ((float4*)in_s)[i] = tf32r4(((const float4*)&g_h[(size_t)n0 * 128])[i]);
    __syncthreads();
    float acc[NT];
    float bb1 = b1[tid];
    #pragma unroll
    for (int e = 0; e < NT; e++) acc[e] = bb1;
    #pragma unroll 4
    for (int k = 0; k < 128; k++) {
        float wv = w1_s[k * 128 + tid];
        #pragma unroll
        for (int e = 0; e < NT; e++)
            acc[e] = fmaf(in_s[e * 128 + k], wv, acc[e]);
    }
    #pragma unroll
    for (int e = 0; e < NT; e++)
        x_s[e * 128 + tid] = tf32r(sspf(acc[e]));
    __syncthreads();
    float bb2 = b2[tid];
    #pragma unroll
    for (int e = 0; e < NT; e++) acc[e] = bb2;
    #pragma unroll 4
    for (int k = 0; k < 128; k++) {
        float wv = w2_s[k * 128 + tid];
        #pragma unroll
        for (int e = 0; e < NT; e++)
            acc[e] = fmaf(x_s[e * 128 + k], wv, acc[e]);
    }
    #pragma unroll
    for (int e = 0; e < NT; e++) {
        int b = batch[n0 + e];
        atomicAdd(&g_sums[b * 128 + tid], acc[e]);
        if (tid == 0) atomicAdd(&g_cnt[b], 1.0f);
    }
}

__global__ void finalize_kernel(float* __restrict__ out) {
    int i = blockIdx.x * blockDim.x + threadIdx.x;
    if (i >= NGRAPH * HDIM) return;
    out[i] = g_sums[i] / fmaxf(g_cnt[i >> 7], 1.0f);
}

// ---------------- launcher ----------------
extern "C" void kernel_launch(void* const* d_in, const int* in_sizes, int n_in,
                              void* d_out, int out_size) {
    const int*   z       = (const int*)d_in[0];
    const float* pos     = (const float*)d_in[1];
    const int*   ei      = (const int*)d_in[2];
    const int*   batch   = (const int*)d_in[3];
    const float* emb     = (const float*)d_in[4];
    const float* mlp_w1  = (const float*)d_in[5];
    const float* mlp_b1  = (const float*)d_in[6];
    const float* mlp_w2  = (const float*)d_in[7];
    const float* mlp_b2  = (const float*)d_in[8];
    const float* conv_w1 = (const float*)d_in[9];
    const float* conv_w2 = (const float*)d_in[10];
    const float* conv_b2 = (const float*)d_in[11];
    const float* lin_w   = (const float*)d_in[12];
    const float* lin_b   = (const float*)d_in[13];
    const float* out1_w  = (const float*)d_in[14];
    const float* out1_b  = (const float*)d_in[15];
    const float* out2_w  = (const float*)d_in[16];
    const float* out2_b  = (const float*)d_in[17];
    float* out = (float*)d_out;

    const int* src = ei;
    const int* dst = ei + N_EDGES;

    const int EDGE_SMEM = 104960;
    const int NODE_SMEM = 168960;
    const int MV_SMEM   = 16384 * 4;
    const int NU_SMEM   = 32768 * 4;

    cudaFuncSetAttribute(edge_mma_kernel, cudaFuncAttributeMaxDynamicSharedMemorySize, EDGE_SMEM);
    cudaFuncSetAttribute(node_fused_kernel, cudaFuncAttributeMaxDynamicSharedMemorySize, NODE_SMEM);
    cudaFuncSetAttribute(matvec_kernel, cudaFuncAttributeMaxDynamicSharedMemorySize, MV_SMEM);
    cudaFuncSetAttribute(out_kernel, cudaFuncAttributeMaxDynamicSharedMemorySize, NU_SMEM);

    init_h_kernel<<<(N_NODES * HDIM + 255) / 256, 256>>>(z, emb);
    dist_kernel<<<(N_EDGES + 255) / 256, 256>>>(src, dst, pos);
    zero_hist_kernel<<<(N_NODES + 255) / 256, 256>>>();
    hist_kernel<<<(N_EDGES + 255) / 256, 256>>>(dst);
    scan_kernel<<<1, 1024>>>();
    scatter_kernel<<<(N_EDGES + 255) / 256, 256>>>(src, dst);
    gauss_kernel<<<N_EDGES / 256, 256>>>();
    build_frags_kernel<<<(NLAYERS * 4096 + 255) / 256, 256>>>(
        mlp_w1, mlp_w2, conv_w2, lin_w, conv_w1);
    zero_agg_kernel<<<(N_NODES * HDIM + 255) / 256, 256>>>();

    matvec_kernel<<<N_NODES / 16, 128, MV_SMEM>>>(conv_w1);   // xf for layer 0

    for (int l = 0; l < NLAYERS; l++) {
        edge_mma_kernel<<<296, 256, EDGE_SMEM>>>(
            l, mlp_b1 + (size_t)l * 128, mlp_b2 + (size_t)l * 128);
        int do_c = (l < NLAYERS - 1) ? 1 : 0;
        node_fused_kernel<<<148, 256, NODE_SMEM>>>(
            l, conv_b2 + (size_t)l * 128, lin_b + (size_t)l * 128, do_c);
    }

    zero_sums_kernel<<<(NGRAPH * HDIM + 255) / 256, 256>>>();
    out_kernel<<<N_NODES / 16, 128, NU_SMEM>>>(out1_w, out1_b, out2_w, out2_b, batch);
    finalize_kernel<<<(NGRAPH * HDIM + 255) / 256, 256>>>(out);
}

// round 11
// speedup vs baseline: 1.4161x; 1.0467x over previous
#include <cuda_runtime.h>
#include <cuda_fp16.h>
#include <math.h>
#include <stdint.h>

#define N_NODES 20000
#define N_EDGES 640000
#define HDIM    128
#define GDIM    50
#define GPAD    64
#define NLAYERS 6
#define NGRAPH  64
#define CUTOFF  10.0f
#define LOG2F_  0.69314718055994531f
#define PI_     3.14159265358979323846f

#define EPT     128
#define NTILES  (N_EDGES / EPT)
#define EA_STR  72
#define HID_STR 136
#define NODE_TILES ((N_NODES + 127) / 128)

// ---------------- device scratch ----------------
static __device__ __align__(16) float  g_h[N_NODES * HDIM];
static __device__ __align__(16) float  g_xf[N_NODES * HDIM];
static __device__ __align__(16) float  g_agg[N_NODES * HDIM];
static __device__ __align__(16) float  g_d[N_EDGES];
static __device__ __align__(16) float  g_C[N_EDGES];
static __device__ __align__(16) __half g_ea[(size_t)N_EDGES * GPAD]; // PERMUTED order
static __device__ __align__(16) float  g_sums[NGRAPH * HDIM];
static __device__ float g_cnt[NGRAPH];
static __device__ int   g_hist[N_NODES];
static __device__ int   g_perm[N_EDGES];
static __device__ int   g_srcp[N_EDGES];
static __device__ int   g_dstp[N_EDGES];
static __device__ float g_Cp[N_EDGES];
// prebuilt fp16 B-fragments (m16n8k16 layout), all layers
static __device__ __align__(16) uint2 g_w1f[NLAYERS][2048];
static __device__ __align__(16) uint2 g_w2f[NLAYERS][4096];
static __device__ __align__(16) uint2 g_wAf[NLAYERS][4096];
static __device__ __align__(16) uint2 g_wBf[NLAYERS][4096];
static __device__ __align__(16) uint2 g_wCf[NLAYERS][4096];

// ---------------- helpers ----------------
__device__ __forceinline__ float tf32r(float x) {
    uint32_t r;
    asm("cvt.rna.tf32.f32 %0, %1;" : "=r"(r) : "f"(x));
    return __uint_as_float(r);
}
__device__ __forceinline__ float4 tf32r4(float4 v) {
    v.x = tf32r(v.x); v.y = tf32r(v.y); v.z = tf32r(v.z); v.w = tf32r(v.w);
    return v;
}
__device__ __forceinline__ float sspf(float x) {
    return fmaxf(x, 0.f) + log1pf(expf(-fabsf(x))) - LOG2F_;
}
__device__ __forceinline__ float sspf_fast(float x) {
    return fmaxf(x, 0.f) + __logf(1.f + __expf(-fabsf(x))) - LOG2F_;
}
__device__ __forceinline__ uint32_t smem_u32(const void* p) {
    uint32_t a;
    asm("{ .reg .u64 t; cvta.to.shared.u64 t, %1; cvt.u32.u64 %0, t; }" : "=r"(a) : "l"(p));
    return a;
}
__device__ __forceinline__ uint32_t f2h2(float lo, float hi) {
    __half2 h = __floats2half2_rn(lo, hi);
    return *reinterpret_cast<uint32_t*>(&h);
}
__device__ __forceinline__ void mma16816(float4& d, const uint32_t a[4], uint2 b) {
    asm volatile(
        "mma.sync.aligned.m16n8k16.row.col.f32.f16.f16.f32 "
        "{%0,%1,%2,%3}, {%4,%5,%6,%7}, {%8,%9}, {%0,%1,%2,%3};\n"
        : "+f"(d.x), "+f"(d.y), "+f"(d.z), "+f"(d.w)
        : "r"(a[0]), "r"(a[1]), "r"(a[2]), "r"(a[3]), "r"(b.x), "r"(b.y));
}
__device__ __forceinline__ void ldsm4(uint32_t r[4], const void* p) {
    uint32_t a = smem_u32(p);
    asm volatile("ldmatrix.sync.aligned.m8n8.x4.shared.b16 {%0,%1,%2,%3}, [%4];"
        : "=r"(r[0]), "=r"(r[1]), "=r"(r[2]), "=r"(r[3]) : "r"(a));
}

// ---------------- precompute ----------------
__global__ void init_h_kernel(const int* __restrict__ z, const float* __restrict__ emb) {
    int i = blockIdx.x * blockDim.x + threadIdx.x;
    if (i >= N_NODES * HDIM) return;
    int n = i >> 7, j = i & 127;
    g_h[i] = emb[z[n] * HDIM + j];
}

__global__ void dist_kernel(const int* __restrict__ src, const int* __restrict__ dst,
                            const float* __restrict__ pos) {
    int e = blockIdx.x * blockDim.x + threadIdx.x;
    if (e >= N_EDGES) return;
    int s = src[e], t = dst[e];
    float dx = pos[s * 3 + 0] - pos[t * 3 + 0];
    float dy = pos[s * 3 + 1] - pos[t * 3 + 1];
    float dz = pos[s * 3 + 2] - pos[t * 3 + 2];
    float d = sqrtf(dx * dx + dy * dy + dz * dz);
    g_d[e] = d;
    g_C[e] = 0.5f * (cosf(d * (PI_ / CUTOFF)) + 1.0f);
}

__global__ void zero_hist_kernel() {
    int i = blockIdx.x * blockDim.x + threadIdx.x;
    if (i < N_NODES) g_hist[i] = 0;
}
__global__ void hist_kernel(const int* __restrict__ dst) {
    int e = blockIdx.x * blockDim.x + threadIdx.x;
    if (e < N_EDGES) atomicAdd(&g_hist[dst[e]], 1);
}
__global__ void scan_kernel() {
    __shared__ int s[1024];
    int t = threadIdx.x;
    const int CH = (N_NODES + 1023) / 1024;
    int base = t * CH;
    int sum = 0;
    for (int i = 0; i < CH; i++) {
        int idx = base + i;
        if (idx < N_NODES) sum += g_hist[idx];
    }
    s[t] = sum;
    __syncthreads();
    for (int off = 1; off < 1024; off <<= 1) {
        int v = (t >= off) ? s[t - off] : 0;
        __syncthreads();
        s[t] += v;
        __syncthreads();
    }
    int run = (t > 0) ? s[t - 1] : 0;
    for (int i = 0; i < CH; i++) {
        int idx = base + i;
        if (idx < N_NODES) { int c = g_hist[idx]; g_hist[idx] = run; run += c; }
    }
}
__global__ void scatter_kernel(const int* __restrict__ src, const int* __restrict__ dst) {
    int e = blockIdx.x * blockDim.x + threadIdx.x;
    if (e >= N_EDGES) return;
    int d = dst[e];
    int p = atomicAdd(&g_hist[d], 1);
    g_perm[p] = e;
    g_srcp[p] = src[e];
    g_dstp[p] = d;
    g_Cp[p]   = g_C[e];
}

// gaussian table: ±6-center window (bit-identical to full evaluation in fp16)
__global__ __launch_bounds__(256) void gauss_kernel() {
    __shared__ __half buf[256][GPAD];
    int tid = threadIdx.x;
    int e = blockIdx.x * 256 + tid;
    const float step  = CUTOFF / (GDIM - 1);
    const float coeff = -0.5f / (step * step);
    #pragma unroll
    for (int j = 0; j < 8; j++)
        ((uint4*)buf[tid])[j] = make_uint4(0, 0, 0, 0);

    float d  = g_d[g_perm[e]];
    int c0 = (int)rintf(d / step);
    #pragma unroll
    for (int k = -6; k <= 6; k++) {
        int c = c0 + k;
        if (c >= 0 && c < GDIM) {
            float diff = d - c * step;
            buf[tid][c] = __float2half_rn(__expf(coeff * diff * diff));
        }
    }
    __syncthreads();
    size_t e0 = (size_t)blockIdx.x * 256;
    for (int i = tid; i < 256 * 8; i += 256) {
        int r = i >> 3, j = i & 7;
        ((uint4*)&g_ea[(e0 + r) * GPAD])[j] = ((uint4*)buf[r])[j];
    }
}

// build all fp16 B-fragments once (m16n8k16 layout)
__device__ __forceinline__ uint2 frag_of(const float* w, int k0, int n) {
    return make_uint2(f2h2(w[k0 * 128 + n], w[(k0 + 1) * 128 + n]),
                      f2h2(w[(k0 + 8) * 128 + n], w[(k0 + 9) * 128 + n]));
}
__global__ void build_frags_kernel(const float* __restrict__ mlp_w1,
                                   const float* __restrict__ mlp_w2,
                                   const float* __restrict__ conv_w2,
                                   const float* __restrict__ lin_w,
                                   const float* __restrict__ conv_w1) {
    int i = blockIdx.x * blockDim.x + threadIdx.x;
    if (i >= NLAYERS * 4096) return;
    int l = i / 4096, j = i % 4096;
    int lane = j & 31;
    int g_ = lane >> 2, t_ = lane & 3;
    {
        int kt = (j >> 5) & 7, nt = j >> 8;
        int k0 = kt * 16 + 2 * t_, n = nt * 8 + g_;
        g_w2f[l][j] = frag_of(mlp_w2 + (size_t)l * 16384, k0, n);
        g_wAf[l][j] = frag_of(conv_w2 + (size_t)l * 16384, k0, n);
        g_wBf[l][j] = frag_of(lin_w + (size_t)l * 16384, k0, n);
        g_wCf[l][j] = frag_of(conv_w1 + (size_t)l * 16384, k0, n);
    }
    if (j < 2048) {
        int kt = (j >> 5) & 3, nt = j >> 7;
        int k0 = kt * 16 + 2 * t_, n = nt * 8 + g_;
        const float* w1 = mlp_w1 + (size_t)l * GDIM * 128;
        float v0 = (k0     < GDIM) ? w1[k0 * 128 + n]       : 0.f;
        float v1 = (k0 + 1 < GDIM) ? w1[(k0 + 1) * 128 + n] : 0.f;
        float v2 = (k0 + 8 < GDIM) ? w1[(k0 + 8) * 128 + n] : 0.f;
        float v3 = (k0 + 9 < GDIM) ? w1[(k0 + 9) * 128 + n] : 0.f;
        g_w1f[l][j] = make_uint2(f2h2(v0, v1), f2h2(v2, v3));
    }
}

// ---------------- initial xf = h @ conv_w1[0] ----------------
__global__ __launch_bounds__(128) void matvec_kernel(const float* __restrict__ w) {
    constexpr int NT = 16;
    extern __shared__ float w_s[];
    __shared__ float in_s[NT * 128];
    int tid = threadIdx.x;
    for (int i = tid; i < 16384 / 4; i += 128)
        ((float4*)w_s)[i] = tf32r4(((const float4*)w)[i]);
    int n0 = blockIdx.x * NT;
    for (int i = tid; i < NT * 128 / 4; i += 128)
        ((float4*)in_s)[i] = tf32r4(((const float4*)&g_h[(size_t)n0 * 128])[i]);
    __syncthreads();
    float acc[NT];
    #pragma unroll
    for (int e = 0; e < NT; e++) acc[e] = 0.f;
    #pragma unroll 4
    for (int k = 0; k < 128; k++) {
        float wv = w_s[k * 128 + tid];
        #pragma unroll
        for (int e = 0; e < NT; e++)
            acc[e] = fmaf(in_s[e * 128 + k], wv, acc[e]);
    }
    #pragma unroll
    for (int e = 0; e < NT; e++)
        g_xf[(size_t)(n0 + e) * 128 + tid] = acc[e];
}

__global__ void zero_agg_kernel() {
    int i = blockIdx.x * blockDim.x + threadIdx.x;
    if (i < N_NODES * HDIM) g_agg[i] = 0.f;
}
__global__ void zero_sums_kernel() {
    int i = blockIdx.x * blockDim.x + threadIdx.x;
    if (i < NGRAPH * HDIM) g_sums[i] = 0.f;
    if (i < NGRAPH) g_cnt[i] = 0.f;
}

// ---------------- fp16 MMA edge kernel (2/SM, prefetch, 1-pass epilogue) ---
__global__ __launch_bounds__(256, 2) void edge_mma_kernel(
        int layer, const float* __restrict__ b1, const float* __restrict__ b2) {
    extern __shared__ char smraw[];
    __half* ea_s  = (__half*)smraw;                   // 18432
    __half* hid_s = (__half*)(smraw + 18432);         // 34816
    __half* msg_h = hid_s;                            // aliases hid (post-GEMM2)
    uint2*  w1f   = (uint2*)(smraw + 53248);          // 16384
    uint2*  w2f   = (uint2*)(smraw + 69632);          // 32768
    float*  b1_s  = (float*)(smraw + 102400);
    float*  b2_s  = b1_s + 128;
    float*  C_s   = b2_s + 128;
    int*    src_s = (int*)(C_s + 128);
    int*    dst_s = src_s + 128;

    int tid = threadIdx.x;
    int wid = tid >> 5;
    int lid = tid & 31;
    int gid = lid >> 2;
    int tg  = lid & 3;
    int lrow = lid & 15;
    int lcol = (lid >> 4) << 3;

    if (tid < 128) { b1_s[tid] = b1[tid]; b2_s[tid] = b2[tid]; }
    for (int i = tid; i < 1024; i += 256)
        ((uint4*)w1f)[i] = ((const uint4*)g_w1f[layer])[i];
    for (int i = tid; i < 2048; i += 256)
        ((uint4*)w2f)[i] = ((const uint4*)g_w2f[layer])[i];
    __syncthreads();

    int mbase = (wid & 3) * 32;
    int nb    = (wid >> 2) * 8;

    // prefetch first tile into registers
    uint4 pf[4];
    int psrc = 0, pdst = 0;
    float pC = 0.f;
    int t = blockIdx.x;
    if (t < NTILES) {
        int e0 = t * EPT;
        #pragma unroll
        for (int j = 0; j < 4; j++) {
            int i = tid + 256 * j;
            int r = i >> 3, c8 = i & 7;
            pf[j] = ((const uint4*)(g_ea + (size_t)(e0 + r) * GPAD))[c8];
        }
        if (tid < 128) {
            psrc = g_srcp[e0 + tid];
            pdst = g_dstp[e0 + tid];
            pC   = g_Cp[e0 + tid];
        }
    }

    for (; t < NTILES; t += gridDim.x) {
        // commit prefetched tile
        #pragma unroll
        for (int j = 0; j < 4; j++) {
            int i = tid + 256 * j;
            int r = i >> 3, c8 = i & 7;
            *(uint4*)&ea_s[r * EA_STR + c8 * 8] = pf[j];
        }
        if (tid < 128) { src_s[tid] = psrc; dst_s[tid] = pdst; C_s[tid] = pC; }
        __syncthreads();

        float4 acc[2][8];
        #pragma unroll
        for (int mi = 0; mi < 2; mi++)
            #pragma unroll
            for (int ni = 0; ni < 8; ni++)
                acc[mi][ni] = make_float4(0.f, 0.f, 0.f, 0.f);

        // GEMM1: K=64
        #pragma unroll
        for (int kt = 0; kt < 4; kt++) {
            uint32_t a0[4], a1[4];
            ldsm4(a0, &ea_s[(mbase + lrow) * EA_STR + kt * 16 + lcol]);
            ldsm4(a1, &ea_s[(mbase + 16 + lrow) * EA_STR + kt * 16 + lcol]);
            #pragma unroll
            for (int ni = 0; ni < 8; ni++) {
                uint2 b = w1f[((nb + ni) * 4 + kt) * 32 + lid];
                mma16816(acc[0][ni], a0, b);
                mma16816(acc[1][ni], a1, b);
            }
        }

        // ssp -> fp16 HID
        #pragma unroll
        for (int mi = 0; mi < 2; mi++) {
            int ra = mbase + mi * 16 + gid;
            int rb = ra + 8;
            #pragma unroll
            for (int ni = 0; ni < 8; ni++) {
                int c0 = (nb + ni) * 8 + 2 * tg;
                float4 v = acc[mi][ni];
                float ba = b1_s[c0], bb = b1_s[c0 + 1];
                *(uint32_t*)&hid_s[ra * HID_STR + c0] =
                    f2h2(sspf_fast(v.x + ba), sspf_fast(v.y + bb));
                *(uint32_t*)&hid_s[rb * HID_STR + c0] =
                    f2h2(sspf_fast(v.z + ba), sspf_fast(v.w + bb));
            }
        }
        __syncthreads();   // ea_s dead from here

        // prefetch next tile (overlaps GEMM2 + epilogue)
        int tn = t + gridDim.x;
        if (tn < NTILES) {
            int e0n = tn * EPT;
            #pragma unroll
            for (int j = 0; j < 4; j++) {
                int i = tid + 256 * j;
                int r = i >> 3, c8 = i & 7;
                pf[j] = ((const uint4*)(g_ea + (size_t)(e0n + r) * GPAD))[c8];
            }
            if (tid < 128) {
                psrc = g_srcp[e0n + tid];
                pdst = g_dstp[e0n + tid];
                pC   = g_Cp[e0n + tid];
            }
        }

        #pragma unroll
        for (int mi = 0; mi < 2; mi++)
            #pragma unroll
            for (int ni = 0; ni < 8; ni++)
                acc[mi][ni] = make_float4(0.f, 0.f, 0.f, 0.f);

        // GEMM2: K=128
        #pragma unroll
        for (int kt = 0; kt < 8; kt++) {
            uint32_t a0[4], a1[4];
            ldsm4(a0, &hid_s[(mbase + lrow) * HID_STR + kt * 16 + lcol]);
            ldsm4(a1, &hid_s[(mbase + 16 + lrow) * HID_STR + kt * 16 + lcol]);
            #pragma unroll
            for (int ni = 0; ni < 8; ni++) {
                uint2 b = w2f[((nb + ni) * 8 + kt) * 32 + lid];
                mma16816(acc[0][ni], a0, b);
                mma16816(acc[1][ni], a1, b);
            }
        }
        __syncthreads();   // hid consumed; msg_h aliases it

        // single-pass epilogue: stage ALL 128 rows as fp16 msg = (C2+b2)*C
        #pragma unroll
        for (int mi = 0; mi < 2; mi++) {
            int ra = mbase + mi * 16 + gid;
            int rb = ra + 8;
            float Ca = C_s[ra], Cb = C_s[rb];
            #pragma unroll
            for (int ni = 0; ni < 8; ni++) {
                int c0 = (nb + ni) * 8 + 2 * tg;
                float4 v = acc[mi][ni];
                float2 bv = *(const float2*)&b2_s[c0];
                *(uint32_t*)&msg_h[ra * HID_STR + c0] =
                    f2h2((v.x + bv.x) * Ca, (v.y + bv.y) * Ca);
                *(uint32_t*)&msg_h[rb * HID_STR + c0] =
                    f2h2((v.z + bv.x) * Cb, (v.w + bv.y) * Cb);
            }
        }
        __syncthreads();

        // segmented reduce over 16-row chunks, fp32 accumulate, float4 atomics
        {
            int cg = tid & 31;
            int chunk = tid >> 5;              // 0..7, 16 rows each
            int r0 = chunk * 16;
            float4 run = make_float4(0.f, 0.f, 0.f, 0.f);
            int cur = dst_s[r0];
            #pragma unroll
            for (int j = 0; j < 16; j++) {
                int dd = dst_s[r0 + j];
                uint2 mh = *(uint2*)&msg_h[(r0 + j) * HID_STR + cg * 4];
                float2 m01 = __half22float2(*(__half2*)&mh.x);
                float2 m23 = __half22float2(*(__half2*)&mh.y);
                float4 xv = *(const float4*)&g_xf[(size_t)src_s[r0 + j] * 128 + cg * 4];
                if (dd != cur) {
                    atomicAdd((float4*)&g_agg[(size_t)cur * 128 + cg * 4], run);
                    run = make_float4(0.f, 0.f, 0.f, 0.f);
                    cur = dd;
                }
                run.x += m01.x * xv.x; run.y += m01.y * xv.y;
                run.z += m23.x * xv.z; run.w += m23.y * xv.w;
            }
            atomicAdd((float4*)&g_agg[(size_t)cur * 128 + cg * 4], run);
        }
        __syncthreads();
    }
}

// ---------------- fused node kernel (persistent; zeroes g_agg) -------------
__global__ __launch_bounds__(256, 1) void node_fused_kernel(
        int layer, const float* __restrict__ bA, const float* __restrict__ bB,
        int do_c) {
    extern __shared__ char smraw[];
    __half* in_s = (__half*)smraw;
    __half* x_s  = (__half*)(smraw + 34816);
    uint2*  wAf  = (uint2*)(smraw + 69632);
    uint2*  wBf  = (uint2*)(smraw + 102400);
    uint2*  wCf  = (uint2*)(smraw + 135168);
    float*  bA_s = (float*)(smraw + 167936);
    float*  bB_s = bA_s + 128;

    int tid = threadIdx.x;
    int wid = tid >> 5;
    int lid = tid & 31;
    int gid = lid >> 2;
    int tg  = lid & 3;
    int lrow = lid & 15;
    int lcol = (lid >> 4) << 3;

    if (tid < 128) { bA_s[tid] = bA[tid]; bB_s[tid] = bB[tid]; }
    for (int i = tid; i < 2048; i += 256) {
        ((uint4*)wAf)[i] = ((const uint4*)g_wAf[layer])[i];
        ((uint4*)wBf)[i] = ((const uint4*)g_wBf[layer])[i];
        if (do_c)
            ((uint4*)wCf)[i] = ((const uint4*)g_wCf[layer + 1])[i];
    }
    __syncthreads();

    int mbase = (wid & 3) * 32;
    int nb    = (wid >> 2) * 8;

    for (int tile = blockIdx.x; tile < NODE_TILES; tile += gridDim.x) {
        int n0 = tile * 128;
        for (int i = tid; i < 128 * 32; i += 256) {
            int r = i >> 5, c4 = i & 31;
            float4 v = make_float4(0.f, 0.f, 0.f, 0.f);
            if (n0 + r < N_NODES) {
                v = ((const float4*)&g_agg[(size_t)(n0 + r) * 128])[c4];
                ((float4*)&g_agg[(size_t)(n0 + r) * 128])[c4] =
                    make_float4(0.f, 0.f, 0.f, 0.f);
            }
            *(uint2*)&in_s[r * HID_STR + c4 * 4] = make_uint2(f2h2(v.x, v.y), f2h2(v.z, v.w));
        }
        __syncthreads();

        float4 acc[2][8];
        // ---- GEMM A ----
        #pragma unroll
        for (int mi = 0; mi < 2; mi++)
            #pragma unroll
            for (int ni = 0; ni < 8; ni++)
                acc[mi][ni] = make_float4(0.f, 0.f, 0.f, 0.f);
        #pragma unroll
        for (int kt = 0; kt < 8; kt++) {
            uint32_t a0[4], a1[4];
            ldsm4(a0, &in_s[(mbase + lrow) * HID_STR + kt * 16 + lcol]);
            ldsm4(a1, &in_s[(mbase + 16 + lrow) * HID_STR + kt * 16 + lcol]);
            #pragma unroll
            for (int ni = 0; ni < 8; ni++) {
                uint2 b = wAf[((nb + ni) * 8 + kt) * 32 + lid];
                mma16816(acc[0][ni], a0, b);
                mma16816(acc[1][ni], a1, b);
            }
        }
        #pragma unroll
        for (int mi = 0; mi < 2; mi++) {
            int ra = mbase + mi * 16 + gid;
            int rb = ra + 8;
            #pragma unroll
            for (int ni = 0; ni < 8; ni++) {
                int c0 = (nb + ni) * 8 + 2 * tg;
                float4 v = acc[mi][ni];
                float ba = bA_s[c0], bb = bA_s[c0 + 1];
                *(uint32_t*)&x_s[ra * HID_STR + c0] =
                    f2h2(sspf_fast(v.x + ba), sspf_fast(v.y + bb));
                *(uint32_t*)&x_s[rb * HID_STR + c0] =
                    f2h2(sspf_fast(v.z + ba), sspf_fast(v.w + bb));
            }
        }
        __syncthreads();

        // ---- GEMM B: h += x @ wB + bB ----
        #pragma unroll
        for (int mi = 0; mi < 2; mi++)
            #pragma unroll
            for (int ni = 0; ni < 8; ni++)
                acc[mi][ni] = make_float4(0.f, 0.f, 0.f, 0.f);
        #pragma unroll
        for (int kt = 0; kt < 8; kt++) {
            uint32_t a0[4], a1[4];
            ldsm4(a0, &x_s[(mbase + lrow) * HID_STR + kt * 16 + lcol]);
            ldsm4(a1, &x_s[(mbase + 16 + lrow) * HID_STR + kt * 16 + lcol]);
            #pragma unroll
            for (int ni = 0; ni < 8; ni++) {
                uint2 b = wBf[((nb + ni) * 8 + kt) * 32 + lid];
                mma16816(acc[0][ni], a0, b);
                mma16816(acc[1][ni], a1, b);
            }
        }
        #pragma unroll
        for (int mi = 0; mi < 2; mi++) {
            int ra = mbase + mi * 16 + gid;
            int rb = ra + 8;
            int na = n0 + ra, nbn = n0 + rb;
            #pragma unroll
            for (int ni = 0; ni < 8; ni++) {
                int c0 = (nb + ni) * 8 + 2 * tg;
                float4 v = acc[mi][ni];
                float ba = bB_s[c0], bb = bB_s[c0 + 1];
                float hx = 0.f, hy = 0.f, hz = 0.f, hw = 0.f;
                if (na < N_NODES) {
                    float2 hv = *(float2*)&g_h[(size_t)na * 128 + c0];
                    hx = hv.x + v.x + ba;
                    hy = hv.y + v.y + bb;
                    *(float2*)&g_h[(size_t)na * 128 + c0] = make_float2(hx, hy);
                }
                if (nbn < N_NODES) {
                    float2 hv = *(float2*)&g_h[(size_t)nbn * 128 + c0];
                    hz = hv.x + v.z + ba;
                    hw = hv.y + v.w + bb;
                    *(float2*)&g_h[(size_t)nbn * 128 + c0] = make_float2(hz, hw);
                }
                *(uint32_t*)&in_s[ra * HID_STR + c0] = f2h2(hx, hy);
                *(uint32_t*)&in_s[rb * HID_STR + c0] = f2h2(hz, hw);
            }
        }
        __syncthreads();

        if (do_c) {
            // ---- GEMM C: xf = h @ wC ----
            #pragma unroll
            for (int mi = 0; mi < 2; mi++)
                #pragma unroll
                for (int ni = 0; ni < 8; ni++)
                    acc[mi][ni] = make_float4(0.f, 0.f, 0.f, 0.f);
            #pragma unroll
            for (int kt = 0; kt < 8; kt++) {
                uint32_t a0[4], a1[4];
                ldsm4(a0, &in_s[(mbase + lrow) * HID_STR + kt * 16 + lcol]);
                ldsm4(a1, &in_s[(mbase + 16 + lrow) * HID_STR + kt * 16 + lcol]);
                #pragma unroll
                for (int ni = 0; ni < 8; ni++) {
                    uint2 b = wCf[((nb + ni) * 8 + kt) * 32 + lid];
                    mma16816(acc[0][ni], a0, b);
                    mma16816(acc[1][ni], a1, b);
                }
            }
            #pragma unroll
            for (int mi = 0; mi < 2; mi++) {
                int ra = mbase + mi * 16 + gid;
                int rb = ra + 8;
                int na = n0 + ra, nbn = n0 + rb;
                #pragma unroll
                for (int ni = 0; ni < 8; ni++) {
                    int c0 = (nb + ni) * 8 + 2 * tg;
                    float4 v = acc[mi][ni];
                    if (na < N_NODES)
                        *(float2*)&g_xf[(size_t)na * 128 + c0] = make_float2(v.x, v.y);
                    if (nbn < N_NODES)
                        *(float2*)&g_xf[(size_t)nbn * 128 + c0] = make_float2(v.z, v.w);
                }
            }
        }
        __syncthreads();
    }
}

// ---------------- output head ----------------
__global__ __launch_bounds__(128) void out_kernel(
        const float* __restrict__ w1, const float* __restrict__ b1,
        const float* __restrict__ w2, const float* __restrict__ b2,
        const int* __restrict__ batch) {
    constexpr int NT = 16;
    extern __shared__ float sm[];
    float* w1_s = sm;
    float* w2_s = sm + 16384;
    __shared__ float in_s[NT * 128];
    __shared__ float x_s[NT * 128];
    int tid = threadIdx.x;
    for (int i = tid; i < 4096; i += 128) {
        ((float4*)w1_s)[i] = tf32r4(((const float4*)w1)[i]);
        ((float4*)w2_s)[i] = tf32r4(((const float4*)w2)[i]);
    }
    int n0 = blockIdx.x * NT;
    for (int i = tid; i < NT * 128 / 4; i += 128)
        ((float4*)in_s)[i] = tf32r4(((const float4*)&g_h[(size_t)n0 * 128])[i]);
    __syncthreads();
    float acc[NT];
    float bb1 = b1[tid];
    #pragma unroll
    for (int e = 0; e < NT; e++) acc[e] = bb1;
    #pragma unroll 4
    for (int k = 0; k < 128; k++) {
        float wv = w1_s[k * 128 + tid];
        #pragma unroll
        for (int e = 0; e < NT; e++)
            acc[e] = fmaf(in_s[e * 128 + k], wv, acc[e]);
    }
    #pragma unroll
    for (int e = 0; e < NT; e++)
        x_s[e * 128 + tid] = tf32r(sspf(acc[e]));
    __syncthreads();
    float bb2 = b2[tid];
    #pragma unroll
    for (int e = 0; e < NT; e++) acc[e] = bb2;
    #pragma unroll 4
    for (int k = 0; k < 128; k++) {
        float wv = w2_s[k * 128 + tid];
        #pragma unroll
        for (int e = 0; e < NT; e++)
            acc[e] = fmaf(x_s[e * 128 + k], wv, acc[e]);
    }
    #pragma unroll
    for (int e = 0; e < NT; e++) {
        int b = batch[n0 + e];
        atomicAdd(&g_sums[b * 128 + tid], acc[e]);
        if (tid == 0) atomicAdd(&g_cnt[b], 1.0f);
    }
}

__global__ void finalize_kernel(float* __restrict__ out) {
    int i = blockIdx.x * blockDim.x + threadIdx.x;
    if (i >= NGRAPH * HDIM) return;
    out[i] = g_sums[i] / fmaxf(g_cnt[i >> 7], 1.0f);
}

// ---------------- launcher ----------------
extern "C" void kernel_launch(void* const* d_in, const int* in_sizes, int n_in,
                              void* d_out, int out_size) {
    const int*   z       = (const int*)d_in[0];
    const float* pos     = (const float*)d_in[1];
    const int*   ei      = (const int*)d_in[2];
    const int*   batch   = (const int*)d_in[3];
    const float* emb     = (const float*)d_in[4];
    const float* mlp_w1  = (const float*)d_in[5];
    const float* mlp_b1  = (const float*)d_in[6];
    const float* mlp_w2  = (const float*)d_in[7];
    const float* mlp_b2  = (const float*)d_in[8];
    const float* conv_w1 = (const float*)d_in[9];
    const float* conv_w2 = (const float*)d_in[10];
    const float* conv_b2 = (const float*)d_in[11];
    const float* lin_w   = (const float*)d_in[12];
    const float* lin_b   = (const float*)d_in[13];
    const float* out1_w  = (const float*)d_in[14];
    const float* out1_b  = (const float*)d_in[15];
    const float* out2_w  = (const float*)d_in[16];
    const float* out2_b  = (const float*)d_in[17];
    float* out = (float*)d_out;

    const int* src = ei;
    const int* dst = ei + N_EDGES;

    const int EDGE_SMEM = 104960;
    const int NODE_SMEM = 168960;
    const int MV_SMEM   = 16384 * 4;
    const int NU_SMEM   = 32768 * 4;

    cudaFuncSetAttribute(edge_mma_kernel, cudaFuncAttributeMaxDynamicSharedMemorySize, EDGE_SMEM);
    cudaFuncSetAttribute(node_fused_kernel, cudaFuncAttributeMaxDynamicSharedMemorySize, NODE_SMEM);
    cudaFuncSetAttribute(matvec_kernel, cudaFuncAttributeMaxDynamicSharedMemorySize, MV_SMEM);
    cudaFuncSetAttribute(out_kernel, cudaFuncAttributeMaxDynamicSharedMemorySize, NU_SMEM);

    init_h_kernel<<<(N_NODES * HDIM + 255) / 256, 256>>>(z, emb);
    dist_kernel<<<(N_EDGES + 255) / 256, 256>>>(src, dst, pos);
    zero_hist_kernel<<<(N_NODES + 255) / 256, 256>>>();
    hist_kernel<<<(N_EDGES + 255) / 256, 256>>>(dst);
    scan_kernel<<<1, 1024>>>();
    scatter_kernel<<<(N_EDGES + 255) / 256, 256>>>(src, dst);
    gauss_kernel<<<N_EDGES / 256, 256>>>();
    build_frags_kernel<<<(NLAYERS * 4096 + 255) / 256, 256>>>(
        mlp_w1, mlp_w2, conv_w2, lin_w, conv_w1);
    zero_agg_kernel<<<(N_NODES * HDIM + 255) / 256, 256>>>();

    matvec_kernel<<<N_NODES / 16, 128, MV_SMEM>>>(conv_w1);   // xf for layer 0

    for (int l = 0; l < NLAYERS; l++) {
        edge_mma_kernel<<<296, 256, EDGE_SMEM>>>(
            l, mlp_b1 + (size_t)l * 128, mlp_b2 + (size_t)l * 128);
        int do_c = (l < NLAYERS - 1) ? 1 : 0;
        node_fused_kernel<<<148, 256, NODE_SMEM>>>(
            l, conv_b2 + (size_t)l * 128, lin_b + (size_t)l * 128, do_c);
    }

    zero_sums_kernel<<<(NGRAPH * HDIM + 255) / 256, 256>>>();
    out_kernel<<<N_NODES / 16, 128, NU_SMEM>>>(out1_w, out1_b, out2_w, out2_b, batch);
    finalize_kernel<<<(NGRAPH * HDIM + 255) / 256, 256>>>(out);
}

// round 12
// speedup vs baseline: 1.5322x; 1.0820x over previous
#include <cuda_runtime.h>
#include <cuda_fp16.h>
#include <math.h>
#include <stdint.h>

#define N_NODES 20000
#define N_EDGES 640000
#define HDIM    128
#define GDIM    50
#define GPAD    64
#define NLAYERS 6
#define NGRAPH  64
#define CUTOFF  10.0f
#define LOG2F_  0.69314718055994531f
#define PI_     3.14159265358979323846f

#define EPT     128
#define NTILES  (N_EDGES / EPT)
#define EA_STR  72
#define HID_STR 136
#define NODE_TILES ((N_NODES + 127) / 128)

// ---------------- device scratch ----------------
static __device__ __align__(16) float  g_h[N_NODES * HDIM];
static __device__ __align__(16) float  g_xf[N_NODES * HDIM];
static __device__ __align__(16) float  g_agg[N_NODES * HDIM];
static __device__ __align__(16) float  g_d[N_EDGES];
static __device__ __align__(16) float  g_C[N_EDGES];
static __device__ __align__(16) __half g_ea[(size_t)N_EDGES * GPAD]; // PERMUTED order
static __device__ __align__(16) float  g_sums[NGRAPH * HDIM];
static __device__ float g_cnt[NGRAPH];
static __device__ int   g_hist[N_NODES];
static __device__ int   g_perm[N_EDGES];
static __device__ int   g_srcp[N_EDGES];
static __device__ int   g_dstp[N_EDGES];
static __device__ float g_Cp[N_EDGES];
// prebuilt fp16 B-fragments (m16n8k16 layout)
static __device__ __align__(16) uint2 g_w1f[NLAYERS][2048];
static __device__ __align__(16) uint2 g_w2f[NLAYERS][4096];
static __device__ __align__(16) uint2 g_wAf[NLAYERS][4096];
static __device__ __align__(16) uint2 g_wBf[NLAYERS][4096];
static __device__ __align__(16) uint2 g_wCf[NLAYERS][4096];
static __device__ __align__(16) uint2 g_wO1f[4096];
static __device__ __align__(16) uint2 g_wO2f[4096];

// ---------------- helpers ----------------
__device__ __forceinline__ float tf32r(float x) {
    uint32_t r;
    asm("cvt.rna.tf32.f32 %0, %1;" : "=r"(r) : "f"(x));
    return __uint_as_float(r);
}
__device__ __forceinline__ float4 tf32r4(float4 v) {
    v.x = tf32r(v.x); v.y = tf32r(v.y); v.z = tf32r(v.z); v.w = tf32r(v.w);
    return v;
}
__device__ __forceinline__ float sspf(float x) {
    return fmaxf(x, 0.f) + log1pf(expf(-fabsf(x))) - LOG2F_;
}
__device__ __forceinline__ float sspf_fast(float x) {
    return fmaxf(x, 0.f) + __logf(1.f + __expf(-fabsf(x))) - LOG2F_;
}
__device__ __forceinline__ uint32_t smem_u32(const void* p) {
    uint32_t a;
    asm("{ .reg .u64 t; cvta.to.shared.u64 t, %1; cvt.u32.u64 %0, t; }" : "=r"(a) : "l"(p));
    return a;
}
__device__ __forceinline__ uint32_t f2h2(float lo, float hi) {
    __half2 h = __floats2half2_rn(lo, hi);
    return *reinterpret_cast<uint32_t*>(&h);
}
__device__ __forceinline__ void mma16816(float4& d, const uint32_t a[4], uint2 b) {
    asm volatile(
        "mma.sync.aligned.m16n8k16.row.col.f32.f16.f16.f32 "
        "{%0,%1,%2,%3}, {%4,%5,%6,%7}, {%8,%9}, {%0,%1,%2,%3};\n"
        : "+f"(d.x), "+f"(d.y), "+f"(d.z), "+f"(d.w)
        : "r"(a[0]), "r"(a[1]), "r"(a[2]), "r"(a[3]), "r"(b.x), "r"(b.y));
}
__device__ __forceinline__ void ldsm4(uint32_t r[4], const void* p) {
    uint32_t a = smem_u32(p);
    asm volatile("ldmatrix.sync.aligned.m8n8.x4.shared.b16 {%0,%1,%2,%3}, [%4];"
        : "=r"(r[0]), "=r"(r[1]), "=r"(r[2]), "=r"(r[3]) : "r"(a));
}

// ---------------- precompute ----------------
__global__ void init_h_kernel(const int* __restrict__ z, const float* __restrict__ emb) {
    int i = blockIdx.x * blockDim.x + threadIdx.x;
    if (i >= N_NODES * HDIM) return;
    int n = i >> 7, j = i & 127;
    g_h[i] = emb[z[n] * HDIM + j];
}

__global__ void dist_kernel(const int* __restrict__ src, const int* __restrict__ dst,
                            const float* __restrict__ pos) {
    int e = blockIdx.x * blockDim.x + threadIdx.x;
    if (e >= N_EDGES) return;
    int s = src[e], t = dst[e];
    float dx = pos[s * 3 + 0] - pos[t * 3 + 0];
    float dy = pos[s * 3 + 1] - pos[t * 3 + 1];
    float dz = pos[s * 3 + 2] - pos[t * 3 + 2];
    float d = sqrtf(dx * dx + dy * dy + dz * dz);
    g_d[e] = d;
    g_C[e] = 0.5f * (cosf(d * (PI_ / CUTOFF)) + 1.0f);
}

__global__ void zero_hist_kernel() {
    int i = blockIdx.x * blockDim.x + threadIdx.x;
    if (i < N_NODES) g_hist[i] = 0;
}
__global__ void hist_kernel(const int* __restrict__ dst) {
    int e = blockIdx.x * blockDim.x + threadIdx.x;
    if (e < N_EDGES) atomicAdd(&g_hist[dst[e]], 1);
}
__global__ void scan_kernel() {
    __shared__ int s[1024];
    int t = threadIdx.x;
    const int CH = (N_NODES + 1023) / 1024;
    int base = t * CH;
    int sum = 0;
    for (int i = 0; i < CH; i++) {
        int idx = base + i;
        if (idx < N_NODES) sum += g_hist[idx];
    }
    s[t] = sum;
    __syncthreads();
    for (int off = 1; off < 1024; off <<= 1) {
        int v = (t >= off) ? s[t - off] : 0;
        __syncthreads();
        s[t] += v;
        __syncthreads();
    }
    int run = (t > 0) ? s[t - 1] : 0;
    for (int i = 0; i < CH; i++) {
        int idx = base + i;
        if (idx < N_NODES) { int c = g_hist[idx]; g_hist[idx] = run; run += c; }
    }
}
__global__ void scatter_kernel(const int* __restrict__ src, const int* __restrict__ dst) {
    int e = blockIdx.x * blockDim.x + threadIdx.x;
    if (e >= N_EDGES) return;
    int d = dst[e];
    int p = atomicAdd(&g_hist[d], 1);
    g_perm[p] = e;
    g_srcp[p] = src[e];
    g_dstp[p] = d;
    g_Cp[p]   = g_C[e];
}

// zero sums + count nodes per graph (batch is input-constant)
__global__ void sums_init_kernel(const int* __restrict__ batch) {
    int i = blockIdx.x * blockDim.x + threadIdx.x;
    if (i < NGRAPH * HDIM) g_sums[i] = 0.f;
    if (i < NGRAPH) g_cnt[i] = 0.f;
}
__global__ void cnt_kernel(const int* __restrict__ batch) {
    int n = blockIdx.x * blockDim.x + threadIdx.x;
    if (n < N_NODES) atomicAdd(&g_cnt[batch[n]], 1.0f);
}

// gaussian table: ±6-center window (bit-identical to full evaluation in fp16)
__global__ __launch_bounds__(256) void gauss_kernel() {
    __shared__ __half buf[256][GPAD];
    int tid = threadIdx.x;
    int e = blockIdx.x * 256 + tid;
    const float step  = CUTOFF / (GDIM - 1);
    const float coeff = -0.5f / (step * step);
    #pragma unroll
    for (int j = 0; j < 8; j++)
        ((uint4*)buf[tid])[j] = make_uint4(0, 0, 0, 0);

    float d  = g_d[g_perm[e]];
    int c0 = (int)rintf(d / step);
    #pragma unroll
    for (int k = -6; k <= 6; k++) {
        int c = c0 + k;
        if (c >= 0 && c < GDIM) {
            float diff = d - c * step;
            buf[tid][c] = __float2half_rn(__expf(coeff * diff * diff));
        }
    }
    __syncthreads();
    size_t e0 = (size_t)blockIdx.x * 256;
    for (int i = tid; i < 256 * 8; i += 256) {
        int r = i >> 3, j = i & 7;
        ((uint4*)&g_ea[(e0 + r) * GPAD])[j] = ((uint4*)buf[r])[j];
    }
}

// build all fp16 B-fragments once (m16n8k16 layout)
__device__ __forceinline__ uint2 frag_of(const float* w, int k0, int n) {
    return make_uint2(f2h2(w[k0 * 128 + n], w[(k0 + 1) * 128 + n]),
                      f2h2(w[(k0 + 8) * 128 + n], w[(k0 + 9) * 128 + n]));
}
__global__ void build_frags_kernel(const float* __restrict__ mlp_w1,
                                   const float* __restrict__ mlp_w2,
                                   const float* __restrict__ conv_w2,
                                   const float* __restrict__ lin_w,
                                   const float* __restrict__ conv_w1,
                                   const float* __restrict__ out1_w,
                                   const float* __restrict__ out2_w) {
    int i = blockIdx.x * blockDim.x + threadIdx.x;
    if (i >= NLAYERS * 4096) return;
    int l = i / 4096, j = i % 4096;
    int lane = j & 31;
    int g_ = lane >> 2, t_ = lane & 3;
    {
        int kt = (j >> 5) & 7, nt = j >> 8;
        int k0 = kt * 16 + 2 * t_, n = nt * 8 + g_;
        g_w2f[l][j] = frag_of(mlp_w2 + (size_t)l * 16384, k0, n);
        g_wAf[l][j] = frag_of(conv_w2 + (size_t)l * 16384, k0, n);
        g_wBf[l][j] = frag_of(lin_w + (size_t)l * 16384, k0, n);
        g_wCf[l][j] = frag_of(conv_w1 + (size_t)l * 16384, k0, n);
        if (l == 0) {
            g_wO1f[j] = frag_of(out1_w, k0, n);
            g_wO2f[j] = frag_of(out2_w, k0, n);
        }
    }
    if (j < 2048) {
        int kt = (j >> 5) & 3, nt = j >> 7;
        int k0 = kt * 16 + 2 * t_, n = nt * 8 + g_;
        const float* w1 = mlp_w1 + (size_t)l * GDIM * 128;
        float v0 = (k0     < GDIM) ? w1[k0 * 128 + n]       : 0.f;
        float v1 = (k0 + 1 < GDIM) ? w1[(k0 + 1) * 128 + n] : 0.f;
        float v2 = (k0 + 8 < GDIM) ? w1[(k0 + 8) * 128 + n] : 0.f;
        float v3 = (k0 + 9 < GDIM) ? w1[(k0 + 9) * 128 + n] : 0.f;
        g_w1f[l][j] = make_uint2(f2h2(v0, v1), f2h2(v2, v3));
    }
}

// ---------------- initial xf = h @ conv_w1[0] ----------------
__global__ __launch_bounds__(128) void matvec_kernel(const float* __restrict__ w) {
    constexpr int NT = 16;
    extern __shared__ float w_s[];
    __shared__ float in_s[NT * 128];
    int tid = threadIdx.x;
    for (int i = tid; i < 16384 / 4; i += 128)
        ((float4*)w_s)[i] = tf32r4(((const float4*)w)[i]);
    int n0 = blockIdx.x * NT;
    for (int i = tid; i < NT * 128 / 4; i += 128)
        ((float4*)in_s)[i] = tf32r4(((const float4*)&g_h[(size_t)n0 * 128])[i]);
    __syncthreads();
    float acc[NT];
    #pragma unroll
    for (int e = 0; e < NT; e++) acc[e] = 0.f;
    #pragma unroll 4
    for (int k = 0; k < 128; k++) {
        float wv = w_s[k * 128 + tid];
        #pragma unroll
        for (int e = 0; e < NT; e++)
            acc[e] = fmaf(in_s[e * 128 + k], wv, acc[e]);
    }
    #pragma unroll
    for (int e = 0; e < NT; e++)
        g_xf[(size_t)(n0 + e) * 128 + tid] = acc[e];
}

__global__ void zero_agg_kernel() {
    int i = blockIdx.x * blockDim.x + threadIdx.x;
    if (i < N_NODES * HDIM) g_agg[i] = 0.f;
}

// ---------------- fp16 MMA edge kernel (2/SM, prefetch, 1-pass epilogue) ---
__global__ __launch_bounds__(256, 2) void edge_mma_kernel(
        int layer, const float* __restrict__ b1, const float* __restrict__ b2) {
    extern __shared__ char smraw[];
    __half* ea_s  = (__half*)smraw;                   // 18432
    __half* hid_s = (__half*)(smraw + 18432);         // 34816
    __half* msg_h = hid_s;                            // aliases hid (post-GEMM2)
    uint2*  w1f   = (uint2*)(smraw + 53248);          // 16384
    uint2*  w2f   = (uint2*)(smraw + 69632);          // 32768
    float*  b1_s  = (float*)(smraw + 102400);
    float*  b2_s  = b1_s + 128;
    float*  C_s   = b2_s + 128;
    int*    src_s = (int*)(C_s + 128);
    int*    dst_s = src_s + 128;

    int tid = threadIdx.x;
    int wid = tid >> 5;
    int lid = tid & 31;
    int gid = lid >> 2;
    int tg  = lid & 3;
    int lrow = lid & 15;
    int lcol = (lid >> 4) << 3;

    if (tid < 128) { b1_s[tid] = b1[tid]; b2_s[tid] = b2[tid]; }
    for (int i = tid; i < 1024; i += 256)
        ((uint4*)w1f)[i] = ((const uint4*)g_w1f[layer])[i];
    for (int i = tid; i < 2048; i += 256)
        ((uint4*)w2f)[i] = ((const uint4*)g_w2f[layer])[i];
    __syncthreads();

    int mbase = (wid & 3) * 32;
    int nb    = (wid >> 2) * 8;

    uint4 pf[4];
    int psrc = 0, pdst = 0;
    float pC = 0.f;
    int t = blockIdx.x;
    if (t < NTILES) {
        int e0 = t * EPT;
        #pragma unroll
        for (int j = 0; j < 4; j++) {
            int i = tid + 256 * j;
            int r = i >> 3, c8 = i & 7;
            pf[j] = ((const uint4*)(g_ea + (size_t)(e0 + r) * GPAD))[c8];
        }
        if (tid < 128) {
            psrc = g_srcp[e0 + tid];
            pdst = g_dstp[e0 + tid];
            pC   = g_Cp[e0 + tid];
        }
    }

    for (; t < NTILES; t += gridDim.x) {
        #pragma unroll
        for (int j = 0; j < 4; j++) {
            int i = tid + 256 * j;
            int r = i >> 3, c8 = i & 7;
            *(uint4*)&ea_s[r * EA_STR + c8 * 8] = pf[j];
        }
        if (tid < 128) { src_s[tid] = psrc; dst_s[tid] = pdst; C_s[tid] = pC; }
        __syncthreads();

        float4 acc[2][8];
        #pragma unroll
        for (int mi = 0; mi < 2; mi++)
            #pragma unroll
            for (int ni = 0; ni < 8; ni++)
                acc[mi][ni] = make_float4(0.f, 0.f, 0.f, 0.f);

        // GEMM1: K=64
        #pragma unroll
        for (int kt = 0; kt < 4; kt++) {
            uint32_t a0[4], a1[4];
            ldsm4(a0, &ea_s[(mbase + lrow) * EA_STR + kt * 16 + lcol]);
            ldsm4(a1, &ea_s[(mbase + 16 + lrow) * EA_STR + kt * 16 + lcol]);
            #pragma unroll
            for (int ni = 0; ni < 8; ni++) {
                uint2 b = w1f[((nb + ni) * 4 + kt) * 32 + lid];
                mma16816(acc[0][ni], a0, b);
                mma16816(acc[1][ni], a1, b);
            }
        }

        // ssp -> fp16 HID
        #pragma unroll
        for (int mi = 0; mi < 2; mi++) {
            int ra = mbase + mi * 16 + gid;
            int rb = ra + 8;
            #pragma unroll
            for (int ni = 0; ni < 8; ni++) {
                int c0 = (nb + ni) * 8 + 2 * tg;
                float4 v = acc[mi][ni];
                float ba = b1_s[c0], bb = b1_s[c0 + 1];
                *(uint32_t*)&hid_s[ra * HID_STR + c0] =
                    f2h2(sspf_fast(v.x + ba), sspf_fast(v.y + bb));
                *(uint32_t*)&hid_s[rb * HID_STR + c0] =
                    f2h2(sspf_fast(v.z + ba), sspf_fast(v.w + bb));
            }
        }
        __syncthreads();   // ea_s dead from here

        int tn = t + gridDim.x;
        if (tn < NTILES) {
            int e0n = tn * EPT;
            #pragma unroll
            for (int j = 0; j < 4; j++) {
                int i = tid + 256 * j;
                int r = i >> 3, c8 = i & 7;
                pf[j] = ((const uint4*)(g_ea + (size_t)(e0n + r) * GPAD))[c8];
            }
            if (tid < 128) {
                psrc = g_srcp[e0n + tid];
                pdst = g_dstp[e0n + tid];
                pC   = g_Cp[e0n + tid];
            }
        }

        #pragma unroll
        for (int mi = 0; mi < 2; mi++)
            #pragma unroll
            for (int ni = 0; ni < 8; ni++)
                acc[mi][ni] = make_float4(0.f, 0.f, 0.f, 0.f);

        // GEMM2: K=128
        #pragma unroll
        for (int kt = 0; kt < 8; kt++) {
            uint32_t a0[4], a1[4];
            ldsm4(a0, &hid_s[(mbase + lrow) * HID_STR + kt * 16 + lcol]);
            ldsm4(a1, &hid_s[(mbase + 16 + lrow) * HID_STR + kt * 16 + lcol]);
            #pragma unroll
            for (int ni = 0; ni < 8; ni++) {
                uint2 b = w2f[((nb + ni) * 8 + kt) * 32 + lid];
                mma16816(acc[0][ni], a0, b);
                mma16816(acc[1][ni], a1, b);
            }
        }
        __syncthreads();   // hid consumed; msg_h aliases it

        // single-pass epilogue: stage ALL 128 rows as fp16 msg = (C2+b2)*C
        #pragma unroll
        for (int mi = 0; mi < 2; mi++) {
            int ra = mbase + mi * 16 + gid;
            int rb = ra + 8;
            float Ca = C_s[ra], Cb = C_s[rb];
            #pragma unroll
            for (int ni = 0; ni < 8; ni++) {
                int c0 = (nb + ni) * 8 + 2 * tg;
                float4 v = acc[mi][ni];
                float2 bv = *(const float2*)&b2_s[c0];
                *(uint32_t*)&msg_h[ra * HID_STR + c0] =
                    f2h2((v.x + bv.x) * Ca, (v.y + bv.y) * Ca);
                *(uint32_t*)&msg_h[rb * HID_STR + c0] =
                    f2h2((v.z + bv.x) * Cb, (v.w + bv.y) * Cb);
            }
        }
        __syncthreads();

        // segmented reduce over 16-row chunks, fp32 accumulate, float4 atomics
        {
            int cg = tid & 31;
            int chunk = tid >> 5;
            int r0 = chunk * 16;
            float4 run = make_float4(0.f, 0.f, 0.f, 0.f);
            int cur = dst_s[r0];
            #pragma unroll
            for (int j = 0; j < 16; j++) {
                int dd = dst_s[r0 + j];
                uint2 mh = *(uint2*)&msg_h[(r0 + j) * HID_STR + cg * 4];
                float2 m01 = __half22float2(*(__half2*)&mh.x);
                float2 m23 = __half22float2(*(__half2*)&mh.y);
                float4 xv = *(const float4*)&g_xf[(size_t)src_s[r0 + j] * 128 + cg * 4];
                if (dd != cur) {
                    atomicAdd((float4*)&g_agg[(size_t)cur * 128 + cg * 4], run);
                    run = make_float4(0.f, 0.f, 0.f, 0.f);
                    cur = dd;
                }
                run.x += m01.x * xv.x; run.y += m01.y * xv.y;
                run.z += m23.x * xv.z; run.w += m23.y * xv.w;
            }
            atomicAdd((float4*)&g_agg[(size_t)cur * 128 + cg * 4], run);
        }
        __syncthreads();
    }
}

// ---------------- fused node kernel (persistent; zeroes g_agg; l=5 also
// computes the output head into g_sums) --------------------------------------
__global__ __launch_bounds__(256, 1) void node_fused_kernel(
        int layer, const float* __restrict__ bA, const float* __restrict__ bB,
        const float* __restrict__ bO1, const float* __restrict__ bO2,
        const int* __restrict__ batch, int do_c) {
    extern __shared__ char smraw[];
    __half* in_s = (__half*)smraw;                     // 34816
    __half* x_s  = (__half*)(smraw + 34816);           // 34816
    uint2*  wAf  = (uint2*)(smraw + 69632);            // 32768
    uint2*  wBf  = (uint2*)(smraw + 102400);           // 32768
    uint2*  wCf  = (uint2*)(smraw + 135168);           // 32768 (conv_w1[l+1] or out1)
    uint2*  wDf  = (uint2*)(smraw + 167936);           // 32768 (out2, l=5 only)
    float*  bA_s = (float*)(smraw + 200704);           // 128
    float*  bB_s = bA_s + 128;
    float*  bO1_s = bB_s + 128;
    float*  bO2_s = bO1_s + 128;
    int*    batch_s = (int*)(bO2_s + 128);             // 128

    int tid = threadIdx.x;
    int wid = tid >> 5;
    int lid = tid & 31;
    int gid = lid >> 2;
    int tg  = lid & 3;
    int lrow = lid & 15;
    int lcol = (lid >> 4) << 3;
    int do_out = !do_c;

    if (tid < 128) {
        bA_s[tid] = bA[tid]; bB_s[tid] = bB[tid];
        if (do_out) { bO1_s[tid] = bO1[tid]; bO2_s[tid] = bO2[tid]; }
    }
    for (int i = tid; i < 2048; i += 256) {
        ((uint4*)wAf)[i] = ((const uint4*)g_wAf[layer])[i];
        ((uint4*)wBf)[i] = ((const uint4*)g_wBf[layer])[i];
        if (do_c) {
            ((uint4*)wCf)[i] = ((const uint4*)g_wCf[layer + 1])[i];
        } else {
            ((uint4*)wCf)[i] = ((const uint4*)g_wO1f)[i];
            ((uint4*)wDf)[i] = ((const uint4*)g_wO2f)[i];
        }
    }
    __syncthreads();

    int mbase = (wid & 3) * 32;
    int nb    = (wid >> 2) * 8;

    for (int tile = blockIdx.x; tile < NODE_TILES; tile += gridDim.x) {
        int n0 = tile * 128;
        for (int i = tid; i < 128 * 32; i += 256) {
            int r = i >> 5, c4 = i & 31;
            float4 v = make_float4(0.f, 0.f, 0.f, 0.f);
            if (n0 + r < N_NODES) {
                v = ((const float4*)&g_agg[(size_t)(n0 + r) * 128])[c4];
                ((float4*)&g_agg[(size_t)(n0 + r) * 128])[c4] =
                    make_float4(0.f, 0.f, 0.f, 0.f);
            }
            *(uint2*)&in_s[r * HID_STR + c4 * 4] = make_uint2(f2h2(v.x, v.y), f2h2(v.z, v.w));
        }
        if (do_out && tid < 128)
            batch_s[tid] = (n0 + tid < N_NODES) ? batch[n0 + tid] : 0;
        __syncthreads();

        float4 acc[2][8];
        // ---- GEMM A: x = ssp(agg @ wA + bA) ----
        #pragma unroll
        for (int mi = 0; mi < 2; mi++)
            #pragma unroll
            for (int ni = 0; ni < 8; ni++)
                acc[mi][ni] = make_float4(0.f, 0.f, 0.f, 0.f);
        #pragma unroll
        for (int kt = 0; kt < 8; kt++) {
            uint32_t a0[4], a1[4];
            ldsm4(a0, &in_s[(mbase + lrow) * HID_STR + kt * 16 + lcol]);
            ldsm4(a1, &in_s[(mbase + 16 + lrow) * HID_STR + kt * 16 + lcol]);
            #pragma unroll
            for (int ni = 0; ni < 8; ni++) {
                uint2 b = wAf[((nb + ni) * 8 + kt) * 32 + lid];
                mma16816(acc[0][ni], a0, b);
                mma16816(acc[1][ni], a1, b);
            }
        }
        #pragma unroll
        for (int mi = 0; mi < 2; mi++) {
            int ra = mbase + mi * 16 + gid;
            int rb = ra + 8;
            #pragma unroll
            for (int ni = 0; ni < 8; ni++) {
                int c0 = (nb + ni) * 8 + 2 * tg;
                float4 v = acc[mi][ni];
                float ba = bA_s[c0], bb = bA_s[c0 + 1];
                *(uint32_t*)&x_s[ra * HID_STR + c0] =
                    f2h2(sspf_fast(v.x + ba), sspf_fast(v.y + bb));
                *(uint32_t*)&x_s[rb * HID_STR + c0] =
                    f2h2(sspf_fast(v.z + ba), sspf_fast(v.w + bb));
            }
        }
        __syncthreads();

        // ---- GEMM B: h += x @ wB + bB ----
        #pragma unroll
        for (int mi = 0; mi < 2; mi++)
            #pragma unroll
            for (int ni = 0; ni < 8; ni++)
                acc[mi][ni] = make_float4(0.f, 0.f, 0.f, 0.f);
        #pragma unroll
        for (int kt = 0; kt < 8; kt++) {
            uint32_t a0[4], a1[4];
            ldsm4(a0, &x_s[(mbase + lrow) * HID_STR + kt * 16 + lcol]);
            ldsm4(a1, &x_s[(mbase + 16 + lrow) * HID_STR + kt * 16 + lcol]);
            #pragma unroll
            for (int ni = 0; ni < 8; ni++) {
                uint2 b = wBf[((nb + ni) * 8 + kt) * 32 + lid];
                mma16816(acc[0][ni], a0, b);
                mma16816(acc[1][ni], a1, b);
            }
        }
        #pragma unroll
        for (int mi = 0; mi < 2; mi++) {
            int ra = mbase + mi * 16 + gid;
            int rb = ra + 8;
            int na = n0 + ra, nbn = n0 + rb;
            #pragma unroll
            for (int ni = 0; ni < 8; ni++) {
                int c0 = (nb + ni) * 8 + 2 * tg;
                float4 v = acc[mi][ni];
                float ba = bB_s[c0], bb = bB_s[c0 + 1];
                float hx = 0.f, hy = 0.f, hz = 0.f, hw = 0.f;
                if (na < N_NODES) {
                    float2 hv = *(float2*)&g_h[(size_t)na * 128 + c0];
                    hx = hv.x + v.x + ba;
                    hy = hv.y + v.y + bb;
                    *(float2*)&g_h[(size_t)na * 128 + c0] = make_float2(hx, hy);
                }
                if (nbn < N_NODES) {
                    float2 hv = *(float2*)&g_h[(size_t)nbn * 128 + c0];
                    hz = hv.x + v.z + ba;
                    hw = hv.y + v.w + bb;
                    *(float2*)&g_h[(size_t)nbn * 128 + c0] = make_float2(hz, hw);
                }
                *(uint32_t*)&in_s[ra * HID_STR + c0] = f2h2(hx, hy);
                *(uint32_t*)&in_s[rb * HID_STR + c0] = f2h2(hz, hw);
            }
        }
        __syncthreads();

        if (do_c) {
            // ---- GEMM C: xf = h @ wC ----
            #pragma unroll
            for (int mi = 0; mi < 2; mi++)
                #pragma unroll
                for (int ni = 0; ni < 8; ni++)
                    acc[mi][ni] = make_float4(0.f, 0.f, 0.f, 0.f);
            #pragma unroll
            for (int kt = 0; kt < 8; kt++) {
                uint32_t a0[4], a1[4];
                ldsm4(a0, &in_s[(mbase + lrow) * HID_STR + kt * 16 + lcol]);
                ldsm4(a1, &in_s[(mbase + 16 + lrow) * HID_STR + kt * 16 + lcol]);
                #pragma unroll
                for (int ni = 0; ni < 8; ni++) {
                    uint2 b = wCf[((nb + ni) * 8 + kt) * 32 + lid];
                    mma16816(acc[0][ni], a0, b);
                    mma16816(acc[1][ni], a1, b);
                }
            }
            #pragma unroll
            for (int mi = 0; mi < 2; mi++) {
                int ra = mbase + mi * 16 + gid;
                int rb = ra + 8;
                int na = n0 + ra, nbn = n0 + rb;
                #pragma unroll
                for (int ni = 0; ni < 8; ni++) {
                    int c0 = (nb + ni) * 8 + 2 * tg;
                    float4 v = acc[mi][ni];
                    if (na < N_NODES)
                        *(float2*)&g_xf[(size_t)na * 128 + c0] = make_float2(v.x, v.y);
                    if (nbn < N_NODES)
                        *(float2*)&g_xf[(size_t)nbn * 128 + c0] = make_float2(v.z, v.w);
                }
            }
        } else {
            // ---- output head: x = ssp(h @ out1 + bO1) ----
            #pragma unroll
            for (int mi = 0; mi < 2; mi++)
                #pragma unroll
                for (int ni = 0; ni < 8; ni++)
                    acc[mi][ni] = make_float4(0.f, 0.f, 0.f, 0.f);
            #pragma unroll
            for (int kt = 0; kt < 8; kt++) {
                uint32_t a0[4], a1[4];
                ldsm4(a0, &in_s[(mbase + lrow) * HID_STR + kt * 16 + lcol]);
                ldsm4(a1, &in_s[(mbase + 16 + lrow) * HID_STR + kt * 16 + lcol]);
                #pragma unroll
                for (int ni = 0; ni < 8; ni++) {
                    uint2 b = wCf[((nb + ni) * 8 + kt) * 32 + lid];
                    mma16816(acc[0][ni], a0, b);
                    mma16816(acc[1][ni], a1, b);
                }
            }
            #pragma unroll
            for (int mi = 0; mi < 2; mi++) {
                int ra = mbase + mi * 16 + gid;
                int rb = ra + 8;
                #pragma unroll
                for (int ni = 0; ni < 8; ni++) {
                    int c0 = (nb + ni) * 8 + 2 * tg;
                    float4 v = acc[mi][ni];
                    float ba = bO1_s[c0], bb = bO1_s[c0 + 1];
                    *(uint32_t*)&x_s[ra * HID_STR + c0] =
                        f2h2(sspf_fast(v.x + ba), sspf_fast(v.y + bb));
                    *(uint32_t*)&x_s[rb * HID_STR + c0] =
                        f2h2(sspf_fast(v.z + ba), sspf_fast(v.w + bb));
                }
            }
            __syncthreads();

            // ---- output head: out = x @ out2 + bO2 -> g_sums[batch] ----
            #pragma unroll
            for (int mi = 0; mi < 2; mi++)
                #pragma unroll
                for (int ni = 0; ni < 8; ni++)
                    acc[mi][ni] = make_float4(0.f, 0.f, 0.f, 0.f);
            #pragma unroll
            for (int kt = 0; kt < 8; kt++) {
                uint32_t a0[4], a1[4];
                ldsm4(a0, &x_s[(mbase + lrow) * HID_STR + kt * 16 + lcol]);
                ldsm4(a1, &x_s[(mbase + 16 + lrow) * HID_STR + kt * 16 + lcol]);
                #pragma unroll
                for (int ni = 0; ni < 8; ni++) {
                    uint2 b = wDf[((nb + ni) * 8 + kt) * 32 + lid];
                    mma16816(acc[0][ni], a0, b);
                    mma16816(acc[1][ni], a1, b);
                }
            }
            #pragma unroll
            for (int mi = 0; mi < 2; mi++) {
                int ra = mbase + mi * 16 + gid;
                int rb = ra + 8;
                int na = n0 + ra, nbn = n0 + rb;
                #pragma unroll
                for (int ni = 0; ni < 8; ni++) {
                    int c0 = (nb + ni) * 8 + 2 * tg;
                    float4 v = acc[mi][ni];
                    float2 bv = *(const float2*)&bO2_s[c0];
                    if (na < N_NODES) {
                        float2 o = make_float2(v.x + bv.x, v.y + bv.y);
                        atomicAdd((float2*)&g_sums[batch_s[ra] * 128 + c0], o);
                    }
                    if (nbn < N_NODES) {
                        float2 o = make_float2(v.z + bv.x, v.w + bv.y);
                        atomicAdd((float2*)&g_sums[batch_s[rb] * 128 + c0], o);
                    }
                }
            }
        }
        __syncthreads();
    }
}

__global__ void finalize_kernel(float* __restrict__ out) {
    int i = blockIdx.x * blockDim.x + threadIdx.x;
    if (i >= NGRAPH * HDIM) return;
    out[i] = g_sums[i] / fmaxf(g_cnt[i >> 7], 1.0f);
}

// ---------------- launcher ----------------
extern "C" void kernel_launch(void* const* d_in, const int* in_sizes, int n_in,
                              void* d_out, int out_size) {
    const int*   z       = (const int*)d_in[0];
    const float* pos     = (const float*)d_in[1];
    const int*   ei      = (const int*)d_in[2];
    const int*   batch   = (const int*)d_in[3];
    const float* emb     = (const float*)d_in[4];
    const float* mlp_w1  = (const float*)d_in[5];
    const float* mlp_b1  = (const float*)d_in[6];
    const float* mlp_w2  = (const float*)d_in[7];
    const float* mlp_b2  = (const float*)d_in[8];
    const float* conv_w1 = (const float*)d_in[9];
    const float* conv_w2 = (const float*)d_in[10];
    const float* conv_b2 = (const float*)d_in[11];
    const float* lin_w   = (const float*)d_in[12];
    const float* lin_b   = (const float*)d_in[13];
    const float* out1_w  = (const float*)d_in[14];
    const float* out1_b  = (const float*)d_in[15];
    const float* out2_w  = (const float*)d_in[16];
    const float* out2_b  = (const float*)d_in[17];
    float* out = (float*)d_out;

    const int* src = ei;
    const int* dst = ei + N_EDGES;

    const int EDGE_SMEM = 104960;
    const int NODE_SMEM = 203264;
    const int MV_SMEM   = 16384 * 4;

    cudaFuncSetAttribute(edge_mma_kernel, cudaFuncAttributeMaxDynamicSharedMemorySize, EDGE_SMEM);
    cudaFuncSetAttribute(node_fused_kernel, cudaFuncAttributeMaxDynamicSharedMemorySize, NODE_SMEM);
    cudaFuncSetAttribute(matvec_kernel, cudaFuncAttributeMaxDynamicSharedMemorySize, MV_SMEM);

    init_h_kernel<<<(N_NODES * HDIM + 255) / 256, 256>>>(z, emb);
    dist_kernel<<<(N_EDGES + 255) / 256, 256>>>(src, dst, pos);
    zero_hist_kernel<<<(N_NODES + 255) / 256, 256>>>();
    hist_kernel<<<(N_EDGES + 255) / 256, 256>>>(dst);
    scan_kernel<<<1, 1024>>>();
    scatter_kernel<<<(N_EDGES + 255) / 256, 256>>>(src, dst);
    gauss_kernel<<<N_EDGES / 256, 256>>>();
    build_frags_kernel<<<(NLAYERS * 4096 + 255) / 256, 256>>>(
        mlp_w1, mlp_w2, conv_w2, lin_w, conv_w1, out1_w, out2_w);
    zero_agg_kernel<<<(N_NODES * HDIM + 255) / 256, 256>>>();
    sums_init_kernel<<<(NGRAPH * HDIM + 255) / 256, 256>>>(batch);
    cnt_kernel<<<(N_NODES + 255) / 256, 256>>>(batch);

    matvec_kernel<<<N_NODES / 16, 128, MV_SMEM>>>(conv_w1);   // xf for layer 0

    for (int l = 0; l < NLAYERS; l++) {
        edge_mma_kernel<<<296, 256, EDGE_SMEM>>>(
            l, mlp_b1 + (size_t)l * 128, mlp_b2 + (size_t)l * 128);
        int do_c = (l < NLAYERS - 1) ? 1 : 0;
        node_fused_kernel<<<148, 256, NODE_SMEM>>>(
            l, conv_b2 + (size_t)l * 128, lin_b + (size_t)l * 128,
            out1_b, out2_b, batch, do_c);
    }

    finalize_kernel<<<(NGRAPH * HDIM + 255) / 256, 256>>>(out);
}

// round 13
// speedup vs baseline: 1.6989x; 1.1088x over previous
#include <cuda_runtime.h>
#include <cuda_fp16.h>
#include <math.h>
#include <stdint.h>

#define N_NODES 20000
#define N_EDGES 640000
#define HDIM    128
#define GDIM    50
#define NLAYERS 6
#define NGRAPH  64
#define CUTOFF  10.0f
#define LOG2F_  0.69314718055994531f
#define PI_     3.14159265358979323846f

#define EPT     128
#define NTILES  (N_EDGES / EPT)
#define EA_STR  72
#define HID_STR 136
#define NODE_TILES ((N_NODES + 127) / 128)

// ---------------- device scratch ----------------
static __device__ __align__(16) float  g_h[N_NODES * HDIM];
static __device__ __align__(16) float  g_xf[N_NODES * HDIM];
static __device__ __align__(16) float  g_agg[N_NODES * HDIM];
static __device__ __align__(16) float  g_d[N_EDGES];
static __device__ __align__(16) float  g_C[N_EDGES];
static __device__ __align__(16) float  g_sums[NGRAPH * HDIM];
static __device__ float g_cnt[NGRAPH];
static __device__ int   g_hist[N_NODES];
static __device__ int   g_srcp[N_EDGES];
static __device__ int   g_dstp[N_EDGES];
static __device__ float g_Cp[N_EDGES];
static __device__ float g_dp[N_EDGES];
// prebuilt fp16 B-fragments (m16n8k16 layout)
static __device__ __align__(16) uint2 g_w1f[NLAYERS][2048];
static __device__ __align__(16) uint2 g_w2f[NLAYERS][4096];
static __device__ __align__(16) uint2 g_wAf[NLAYERS][4096];
static __device__ __align__(16) uint2 g_wBf[NLAYERS][4096];
static __device__ __align__(16) uint2 g_wCf[NLAYERS][4096];
static __device__ __align__(16) uint2 g_wO1f[4096];
static __device__ __align__(16) uint2 g_wO2f[4096];

// ---------------- helpers ----------------
__device__ __forceinline__ float sspf_fast(float x) {
    return fmaxf(x, 0.f) + __logf(1.f + __expf(-fabsf(x))) - LOG2F_;
}
__device__ __forceinline__ uint32_t smem_u32(const void* p) {
    uint32_t a;
    asm("{ .reg .u64 t; cvta.to.shared.u64 t, %1; cvt.u32.u64 %0, t; }" : "=r"(a) : "l"(p));
    return a;
}
__device__ __forceinline__ uint32_t f2h2(float lo, float hi) {
    __half2 h = __floats2half2_rn(lo, hi);
    return *reinterpret_cast<uint32_t*>(&h);
}
__device__ __forceinline__ void mma16816(float4& d, const uint32_t a[4], uint2 b) {
    asm volatile(
        "mma.sync.aligned.m16n8k16.row.col.f32.f16.f16.f32 "
        "{%0,%1,%2,%3}, {%4,%5,%6,%7}, {%8,%9}, {%0,%1,%2,%3};\n"
        : "+f"(d.x), "+f"(d.y), "+f"(d.z), "+f"(d.w)
        : "r"(a[0]), "r"(a[1]), "r"(a[2]), "r"(a[3]), "r"(b.x), "r"(b.y));
}
__device__ __forceinline__ void ldsm4(uint32_t r[4], const void* p) {
    uint32_t a = smem_u32(p);
    asm volatile("ldmatrix.sync.aligned.m8n8.x4.shared.b16 {%0,%1,%2,%3}, [%4];"
        : "=r"(r[0]), "=r"(r[1]), "=r"(r[2]), "=r"(r[3]) : "r"(a));
}

// ---------------- precompute ----------------
__global__ void init_h_kernel(const int* __restrict__ z, const float* __restrict__ emb) {
    int i = blockIdx.x * blockDim.x + threadIdx.x;
    if (i >= N_NODES * HDIM) return;
    int n = i >> 7, j = i & 127;
    g_h[i] = emb[z[n] * HDIM + j];
}

// zero hist + sums + cnt in one pass
__global__ void misc_init_kernel() {
    int i = blockIdx.x * blockDim.x + threadIdx.x;
    if (i < N_NODES) g_hist[i] = 0;
    if (i < NGRAPH * HDIM) g_sums[i] = 0.f;
    if (i < NGRAPH) g_cnt[i] = 0.f;
}
__global__ void cnt_kernel(const int* __restrict__ batch) {
    int n = blockIdx.x * blockDim.x + threadIdx.x;
    if (n < N_NODES) atomicAdd(&g_cnt[batch[n]], 1.0f);
}

// distance + cutoff + dst histogram in one pass
__global__ void dist_hist_kernel(const int* __restrict__ src, const int* __restrict__ dst,
                                 const float* __restrict__ pos) {
    int e = blockIdx.x * blockDim.x + threadIdx.x;
    if (e >= N_EDGES) return;
    int s = src[e], t = dst[e];
    float dx = pos[s * 3 + 0] - pos[t * 3 + 0];
    float dy = pos[s * 3 + 1] - pos[t * 3 + 1];
    float dz = pos[s * 3 + 2] - pos[t * 3 + 2];
    float d = sqrtf(dx * dx + dy * dy + dz * dz);
    g_d[e] = d;
    g_C[e] = 0.5f * (cosf(d * (PI_ / CUTOFF)) + 1.0f);
    atomicAdd(&g_hist[t], 1);
}

__global__ void scan_kernel() {
    __shared__ int s[1024];
    int t = threadIdx.x;
    const int CH = (N_NODES + 1023) / 1024;
    int base = t * CH;
    int sum = 0;
    for (int i = 0; i < CH; i++) {
        int idx = base + i;
        if (idx < N_NODES) sum += g_hist[idx];
    }
    s[t] = sum;
    __syncthreads();
    for (int off = 1; off < 1024; off <<= 1) {
        int v = (t >= off) ? s[t - off] : 0;
        __syncthreads();
        s[t] += v;
        __syncthreads();
    }
    int run = (t > 0) ? s[t - 1] : 0;
    for (int i = 0; i < CH; i++) {
        int idx = base + i;
        if (idx < N_NODES) { int c = g_hist[idx]; g_hist[idx] = run; run += c; }
    }
}
__global__ void scatter_kernel(const int* __restrict__ src, const int* __restrict__ dst) {
    int e = blockIdx.x * blockDim.x + threadIdx.x;
    if (e >= N_EDGES) return;
    int d = dst[e];
    int p = atomicAdd(&g_hist[d], 1);
    g_srcp[p] = src[e];
    g_dstp[p] = d;
    g_Cp[p]   = g_C[e];
    g_dp[p]   = g_d[e];
}

// build all fp16 B-fragments once (m16n8k16 layout)
__device__ __forceinline__ uint2 frag_of(const float* w, int k0, int n) {
    return make_uint2(f2h2(w[k0 * 128 + n], w[(k0 + 1) * 128 + n]),
                      f2h2(w[(k0 + 8) * 128 + n], w[(k0 + 9) * 128 + n]));
}
__global__ void build_frags_kernel(const float* __restrict__ mlp_w1,
                                   const float* __restrict__ mlp_w2,
                                   const float* __restrict__ conv_w2,
                                   const float* __restrict__ lin_w,
                                   const float* __restrict__ conv_w1,
                                   const float* __restrict__ out1_w,
                                   const float* __restrict__ out2_w) {
    int i = blockIdx.x * blockDim.x + threadIdx.x;
    if (i >= NLAYERS * 4096) return;
    int l = i / 4096, j = i % 4096;
    int lane = j & 31;
    int g_ = lane >> 2, t_ = lane & 3;
    {
        int kt = (j >> 5) & 7, nt = j >> 8;
        int k0 = kt * 16 + 2 * t_, n = nt * 8 + g_;
        g_w2f[l][j] = frag_of(mlp_w2 + (size_t)l * 16384, k0, n);
        g_wAf[l][j] = frag_of(conv_w2 + (size_t)l * 16384, k0, n);
        g_wBf[l][j] = frag_of(lin_w + (size_t)l * 16384, k0, n);
        g_wCf[l][j] = frag_of(conv_w1 + (size_t)l * 16384, k0, n);
        if (l == 0) {
            g_wO1f[j] = frag_of(out1_w, k0, n);
            g_wO2f[j] = frag_of(out2_w, k0, n);
        }
    }
    if (j < 2048) {
        int kt = (j >> 5) & 3, nt = j >> 7;
        int k0 = kt * 16 + 2 * t_, n = nt * 8 + g_;
        const float* w1 = mlp_w1 + (size_t)l * GDIM * 128;
        float v0 = (k0     < GDIM) ? w1[k0 * 128 + n]       : 0.f;
        float v1 = (k0 + 1 < GDIM) ? w1[(k0 + 1) * 128 + n] : 0.f;
        float v2 = (k0 + 8 < GDIM) ? w1[(k0 + 8) * 128 + n] : 0.f;
        float v3 = (k0 + 9 < GDIM) ? w1[(k0 + 9) * 128 + n] : 0.f;
        g_w1f[l][j] = make_uint2(f2h2(v0, v1), f2h2(v2, v3));
    }
}

__global__ void zero_agg_kernel() {
    int i = blockIdx.x * blockDim.x + threadIdx.x;
    if (i < N_NODES * HDIM) g_agg[i] = 0.f;
}

// ---------------- initial xf = h @ conv_w1[0]  (fp16 MMA) -------------------
__global__ __launch_bounds__(256, 2) void xf0_kernel() {
    extern __shared__ char smraw[];
    __half* in_s = (__half*)smraw;             // 34816
    uint2*  wf   = (uint2*)(smraw + 34816);    // 32768
    int tid = threadIdx.x;
    int wid = tid >> 5;
    int lid = tid & 31;
    int gid = lid >> 2;
    int tg  = lid & 3;
    int lrow = lid & 15;
    int lcol = (lid >> 4) << 3;

    for (int i = tid; i < 2048; i += 256)
        ((uint4*)wf)[i] = ((const uint4*)g_wCf[0])[i];

    int n0 = blockIdx.x * 128;
    for (int i = tid; i < 128 * 32; i += 256) {
        int r = i >> 5, c4 = i & 31;
        float4 v = make_float4(0.f, 0.f, 0.f, 0.f);
        if (n0 + r < N_NODES)
            v = ((const float4*)&g_h[(size_t)(n0 + r) * 128])[c4];
        *(uint2*)&in_s[r * HID_STR + c4 * 4] = make_uint2(f2h2(v.x, v.y), f2h2(v.z, v.w));
    }
    __syncthreads();

    int mbase = (wid & 3) * 32;
    int nb    = (wid >> 2) * 8;
    float4 acc[2][8];
    #pragma unroll
    for (int mi = 0; mi < 2; mi++)
        #pragma unroll
        for (int ni = 0; ni < 8; ni++)
            acc[mi][ni] = make_float4(0.f, 0.f, 0.f, 0.f);
    #pragma unroll
    for (int kt = 0; kt < 8; kt++) {
        uint32_t a0[4], a1[4];
        ldsm4(a0, &in_s[(mbase + lrow) * HID_STR + kt * 16 + lcol]);
        ldsm4(a1, &in_s[(mbase + 16 + lrow) * HID_STR + kt * 16 + lcol]);
        #pragma unroll
        for (int ni = 0; ni < 8; ni++) {
            uint2 b = wf[((nb + ni) * 8 + kt) * 32 + lid];
            mma16816(acc[0][ni], a0, b);
            mma16816(acc[1][ni], a1, b);
        }
    }
    #pragma unroll
    for (int mi = 0; mi < 2; mi++) {
        int ra = mbase + mi * 16 + gid;
        int rb = ra + 8;
        int na = n0 + ra, nbn = n0 + rb;
        #pragma unroll
        for (int ni = 0; ni < 8; ni++) {
            int c0 = (nb + ni) * 8 + 2 * tg;
            float4 v = acc[mi][ni];
            if (na < N_NODES)
                *(float2*)&g_xf[(size_t)na * 128 + c0] = make_float2(v.x, v.y);
            if (nbn < N_NODES)
                *(float2*)&g_xf[(size_t)nbn * 128 + c0] = make_float2(v.z, v.w);
        }
    }
}

// ---------------- fp16 MMA edge kernel (2/SM, in-kernel gaussians) ---------
__global__ __launch_bounds__(256, 2) void edge_mma_kernel(
        int layer, const float* __restrict__ b1, const float* __restrict__ b2) {
    extern __shared__ char smraw[];
    __half* ea_s  = (__half*)smraw;                   // 18432
    __half* hid_s = (__half*)(smraw + 18432);         // 34816
    __half* msg_h = hid_s;                            // aliases hid (post-GEMM2)
    uint2*  w1f   = (uint2*)(smraw + 53248);          // 16384
    uint2*  w2f   = (uint2*)(smraw + 69632);          // 32768
    float*  b1_s  = (float*)(smraw + 102400);
    float*  b2_s  = b1_s + 128;
    float*  C_s   = b2_s + 128;
    int*    src_s = (int*)(C_s + 128);
    int*    dst_s = src_s + 128;

    int tid = threadIdx.x;
    int wid = tid >> 5;
    int lid = tid & 31;
    int gid = lid >> 2;
    int tg  = lid & 3;
    int lrow = lid & 15;
    int lcol = (lid >> 4) << 3;

    const float step  = CUTOFF / (GDIM - 1);
    const float inv_step = (GDIM - 1) / CUTOFF;
    const float coeff = -0.5f / (step * step);

    if (tid < 128) { b1_s[tid] = b1[tid]; b2_s[tid] = b2[tid]; }
    for (int i = tid; i < 1024; i += 256)
        ((uint4*)w1f)[i] = ((const uint4*)g_w1f[layer])[i];
    for (int i = tid; i < 2048; i += 256)
        ((uint4*)w2f)[i] = ((const uint4*)g_w2f[layer])[i];
    __syncthreads();

    int mbase = (wid & 3) * 32;
    int nb    = (wid >> 2) * 8;

    // prefetch first tile scalars
    int psrc = 0, pdst = 0;
    float pC = 0.f, pd = 0.f;
    int t = blockIdx.x;
    if (t < NTILES && tid < 128) {
        int e0 = t * EPT;
        psrc = g_srcp[e0 + tid];
        pdst = g_dstp[e0 + tid];
        pC   = g_Cp[e0 + tid];
        pd   = g_dp[e0 + tid];
    }

    for (; t < NTILES; t += gridDim.x) {
        // commit scalars + compute gaussian row in-kernel (±6-center window,
        // bit-identical to the full 50-center evaluation in fp16)
        if (tid < 128) {
            src_s[tid] = psrc; dst_s[tid] = pdst; C_s[tid] = pC;
            uint4 z4 = make_uint4(0, 0, 0, 0);
            #pragma unroll
            for (int j = 0; j < 8; j++)
                *(uint4*)&ea_s[tid * EA_STR + j * 8] = z4;
            int c0 = (int)rintf(pd * inv_step);
            #pragma unroll
            for (int k = -6; k <= 6; k++) {
                int c = c0 + k;
                if (c >= 0 && c < GDIM) {
                    float diff = pd - c * step;
                    ea_s[tid * EA_STR + c] = __float2half_rn(__expf(coeff * diff * diff));
                }
            }
        }
        __syncthreads();

        float4 acc[2][8];
        #pragma unroll
        for (int mi = 0; mi < 2; mi++)
            #pragma unroll
            for (int ni = 0; ni < 8; ni++)
                acc[mi][ni] = make_float4(0.f, 0.f, 0.f, 0.f);

        // GEMM1: K=64
        #pragma unroll
        for (int kt = 0; kt < 4; kt++) {
            uint32_t a0[4], a1[4];
            ldsm4(a0, &ea_s[(mbase + lrow) * EA_STR + kt * 16 + lcol]);
            ldsm4(a1, &ea_s[(mbase + 16 + lrow) * EA_STR + kt * 16 + lcol]);
            #pragma unroll
            for (int ni = 0; ni < 8; ni++) {
                uint2 b = w1f[((nb + ni) * 4 + kt) * 32 + lid];
                mma16816(acc[0][ni], a0, b);
                mma16816(acc[1][ni], a1, b);
            }
        }

        // ssp -> fp16 HID
        #pragma unroll
        for (int mi = 0; mi < 2; mi++) {
            int ra = mbase + mi * 16 + gid;
            int rb = ra + 8;
            #pragma unroll
            for (int ni = 0; ni < 8; ni++) {
                int c0 = (nb + ni) * 8 + 2 * tg;
                float4 v = acc[mi][ni];
                float ba = b1_s[c0], bb = b1_s[c0 + 1];
                *(uint32_t*)&hid_s[ra * HID_STR + c0] =
                    f2h2(sspf_fast(v.x + ba), sspf_fast(v.y + bb));
                *(uint32_t*)&hid_s[rb * HID_STR + c0] =
                    f2h2(sspf_fast(v.z + ba), sspf_fast(v.w + bb));
            }
        }
        __syncthreads();   // ea_s dead from here

        // prefetch next tile scalars (overlaps GEMM2 + epilogue)
        int tn = t + gridDim.x;
        if (tn < NTILES && tid < 128) {
            int e0n = tn * EPT;
            psrc = g_srcp[e0n + tid];
            pdst = g_dstp[e0n + tid];
            pC   = g_Cp[e0n + tid];
            pd   = g_dp[e0n + tid];
        }

        #pragma unroll
        for (int mi = 0; mi < 2; mi++)
            #pragma unroll
            for (int ni = 0; ni < 8; ni++)
                acc[mi][ni] = make_float4(0.f, 0.f, 0.f, 0.f);

        // GEMM2: K=128
        #pragma unroll
        for (int kt = 0; kt < 8; kt++) {
            uint32_t a0[4], a1[4];
            ldsm4(a0, &hid_s[(mbase + lrow) * HID_STR + kt * 16 + lcol]);
            ldsm4(a1, &hid_s[(mbase + 16 + lrow) * HID_STR + kt * 16 + lcol]);
            #pragma unroll
            for (int ni = 0; ni < 8; ni++) {
                uint2 b = w2f[((nb + ni) * 8 + kt) * 32 + lid];
                mma16816(acc[0][ni], a0, b);
                mma16816(acc[1][ni], a1, b);
            }
        }
        __syncthreads();   // hid consumed; msg_h aliases it

        // single-pass epilogue: stage ALL 128 rows as fp16 msg = (C2+b2)*C
        #pragma unroll
        for (int mi = 0; mi < 2; mi++) {
            int ra = mbase + mi * 16 + gid;
            int rb = ra + 8;
            float Ca = C_s[ra], Cb = C_s[rb];
            #pragma unroll
            for (int ni = 0; ni < 8; ni++) {
                int c0 = (nb + ni) * 8 + 2 * tg;
                float4 v = acc[mi][ni];
                float2 bv = *(const float2*)&b2_s[c0];
                *(uint32_t*)&msg_h[ra * HID_STR + c0] =
                    f2h2((v.x + bv.x) * Ca, (v.y + bv.y) * Ca);
                *(uint32_t*)&msg_h[rb * HID_STR + c0] =
                    f2h2((v.z + bv.x) * Cb, (v.w + bv.y) * Cb);
            }
        }
        __syncthreads();

        // segmented reduce over 16-row chunks, fp32 accumulate, float4 atomics
        {
            int cg = tid & 31;
            int chunk = tid >> 5;
            int r0 = chunk * 16;
            float4 run = make_float4(0.f, 0.f, 0.f, 0.f);
            int cur = dst_s[r0];
            #pragma unroll
            for (int j = 0; j < 16; j++) {
                int dd = dst_s[r0 + j];
                uint2 mh = *(uint2*)&msg_h[(r0 + j) * HID_STR + cg * 4];
                float2 m01 = __half22float2(*(__half2*)&mh.x);
                float2 m23 = __half22float2(*(__half2*)&mh.y);
                float4 xv = *(const float4*)&g_xf[(size_t)src_s[r0 + j] * 128 + cg * 4];
                if (dd != cur) {
                    atomicAdd((float4*)&g_agg[(size_t)cur * 128 + cg * 4], run);
                    run = make_float4(0.f, 0.f, 0.f, 0.f);
                    cur = dd;
                }
                run.x += m01.x * xv.x; run.y += m01.y * xv.y;
                run.z += m23.x * xv.z; run.w += m23.y * xv.w;
            }
            atomicAdd((float4*)&g_agg[(size_t)cur * 128 + cg * 4], run);
        }
        __syncthreads();
    }
}

// ---------------- fused node kernel (persistent; zeroes g_agg; l=5 also
// computes the output head into g_sums) --------------------------------------
__global__ __launch_bounds__(256, 1) void node_fused_kernel(
        int layer, const float* __restrict__ bA, const float* __restrict__ bB,
        const float* __restrict__ bO1, const float* __restrict__ bO2,
        const int* __restrict__ batch, int do_c) {
    extern __shared__ char smraw[];
    __half* in_s = (__half*)smraw;                     // 34816
    __half* x_s  = (__half*)(smraw + 34816);           // 34816
    uint2*  wAf  = (uint2*)(smraw + 69632);            // 32768
    uint2*  wBf  = (uint2*)(smraw + 102400);           // 32768
    uint2*  wCf  = (uint2*)(smraw + 135168);           // 32768
    uint2*  wDf  = (uint2*)(smraw + 167936);           // 32768
    float*  bA_s = (float*)(smraw + 200704);
    float*  bB_s = bA_s + 128;
    float*  bO1_s = bB_s + 128;
    float*  bO2_s = bO1_s + 128;
    int*    batch_s = (int*)(bO2_s + 128);

    int tid = threadIdx.x;
    int wid = tid >> 5;
    int lid = tid & 31;
    int gid = lid >> 2;
    int tg  = lid & 3;
    int lrow = lid & 15;
    int lcol = (lid >> 4) << 3;
    int do_out = !do_c;

    if (tid < 128) {
        bA_s[tid] = bA[tid]; bB_s[tid] = bB[tid];
        if (do_out) { bO1_s[tid] = bO1[tid]; bO2_s[tid] = bO2[tid]; }
    }
    for (int i = tid; i < 2048; i += 256) {
        ((uint4*)wAf)[i] = ((const uint4*)g_wAf[layer])[i];
        ((uint4*)wBf)[i] = ((const uint4*)g_wBf[layer])[i];
        if (do_c) {
            ((uint4*)wCf)[i] = ((const uint4*)g_wCf[layer + 1])[i];
        } else {
            ((uint4*)wCf)[i] = ((const uint4*)g_wO1f)[i];
            ((uint4*)wDf)[i] = ((const uint4*)g_wO2f)[i];
        }
    }
    __syncthreads();

    int mbase = (wid & 3) * 32;
    int nb    = (wid >> 2) * 8;

    for (int tile = blockIdx.x; tile < NODE_TILES; tile += gridDim.x) {
        int n0 = tile * 128;
        for (int i = tid; i < 128 * 32; i += 256) {
            int r = i >> 5, c4 = i & 31;
            float4 v = make_float4(0.f, 0.f, 0.f, 0.f);
            if (n0 + r < N_NODES) {
                v = ((const float4*)&g_agg[(size_t)(n0 + r) * 128])[c4];
                ((float4*)&g_agg[(size_t)(n0 + r) * 128])[c4] =
                    make_float4(0.f, 0.f, 0.f, 0.f);
            }
            *(uint2*)&in_s[r * HID_STR + c4 * 4] = make_uint2(f2h2(v.x, v.y), f2h2(v.z, v.w));
        }
        if (do_out && tid < 128)
            batch_s[tid] = (n0 + tid < N_NODES) ? batch[n0 + tid] : 0;
        __syncthreads();

        float4 acc[2][8];
        // ---- GEMM A: x = ssp(agg @ wA + bA) ----
        #pragma unroll
        for (int mi = 0; mi < 2; mi++)
            #pragma unroll
            for (int ni = 0; ni < 8; ni++)
                acc[mi][ni] = make_float4(0.f, 0.f, 0.f, 0.f);
        #pragma unroll
        for (int kt = 0; kt < 8; kt++) {
            uint32_t a0[4], a1[4];
            ldsm4(a0, &in_s[(mbase + lrow) * HID_STR + kt * 16 + lcol]);
            ldsm4(a1, &in_s[(mbase + 16 + lrow) * HID_STR + kt * 16 + lcol]);
            #pragma unroll
            for (int ni = 0; ni < 8; ni++) {
                uint2 b = wAf[((nb + ni) * 8 + kt) * 32 + lid];
                mma16816(acc[0][ni], a0, b);
                mma16816(acc[1][ni], a1, b);
            }
        }
        #pragma unroll
        for (int mi = 0; mi < 2; mi++) {
            int ra = mbase + mi * 16 + gid;
            int rb = ra + 8;
            #pragma unroll
            for (int ni = 0; ni < 8; ni++) {
                int c0 = (nb + ni) * 8 + 2 * tg;
                float4 v = acc[mi][ni];
                float ba = bA_s[c0], bb = bA_s[c0 + 1];
                *(uint32_t*)&x_s[ra * HID_STR + c0] =
                    f2h2(sspf_fast(v.x + ba), sspf_fast(v.y + bb));
                *(uint32_t*)&x_s[rb * HID_STR + c0] =
                    f2h2(sspf_fast(v.z + ba), sspf_fast(v.w + bb));
            }
        }
        __syncthreads();

        // ---- GEMM B: h += x @ wB + bB ----
        #pragma unroll
        for (int mi = 0; mi < 2; mi++)
            #pragma unroll
            for (int ni = 0; ni < 8; ni++)
                acc[mi][ni] = make_float4(0.f, 0.f, 0.f, 0.f);
        #pragma unroll
        for (int kt = 0; kt < 8; kt++) {
            uint32_t a0[4], a1[4];
            ldsm4(a0, &x_s[(mbase + lrow) * HID_STR + kt * 16 + lcol]);
            ldsm4(a1, &x_s[(mbase + 16 + lrow) * HID_STR + kt * 16 + lcol]);
            #pragma unroll
            for (int ni = 0; ni < 8; ni++) {
                uint2 b = wBf[((nb + ni) * 8 + kt) * 32 + lid];
                mma16816(acc[0][ni], a0, b);
                mma16816(acc[1][ni], a1, b);
            }
        }
        #pragma unroll
        for (int mi = 0; mi < 2; mi++) {
            int ra = mbase + mi * 16 + gid;
            int rb = ra + 8;
            int na = n0 + ra, nbn = n0 + rb;
            #pragma unroll
            for (int ni = 0; ni < 8; ni++) {
                int c0 = (nb + ni) * 8 + 2 * tg;
                float4 v = acc[mi][ni];
                float ba = bB_s[c0], bb = bB_s[c0 + 1];
                float hx = 0.f, hy = 0.f, hz = 0.f, hw = 0.f;
                if (na < N_NODES) {
                    float2 hv = *(float2*)&g_h[(size_t)na * 128 + c0];
                    hx = hv.x + v.x + ba;
                    hy = hv.y + v.y + bb;
                    *(float2*)&g_h[(size_t)na * 128 + c0] = make_float2(hx, hy);
                }
                if (nbn < N_NODES) {
                    float2 hv = *(float2*)&g_h[(size_t)nbn * 128 + c0];
                    hz = hv.x + v.z + ba;
                    hw = hv.y + v.w + bb;
                    *(float2*)&g_h[(size_t)nbn * 128 + c0] = make_float2(hz, hw);
                }
                *(uint32_t*)&in_s[ra * HID_STR + c0] = f2h2(hx, hy);
                *(uint32_t*)&in_s[rb * HID_STR + c0] = f2h2(hz, hw);
            }
        }
        __syncthreads();

        if (do_c) {
            // ---- GEMM C: xf = h @ wC ----
            #pragma unroll
            for (int mi = 0; mi < 2; mi++)
                #pragma unroll
                for (int ni = 0; ni < 8; ni++)
                    acc[mi][ni] = make_float4(0.f, 0.f, 0.f, 0.f);
            #pragma unroll
            for (int kt = 0; kt < 8; kt++) {
                uint32_t a0[4], a1[4];
                ldsm4(a0, &in_s[(mbase + lrow) * HID_STR + kt * 16 + lcol]);
                ldsm4(a1, &in_s[(mbase + 16 + lrow) * HID_STR + kt * 16 + lcol]);
                #pragma unroll
                for (int ni = 0; ni < 8; ni++) {
                    uint2 b = wCf[((nb + ni) * 8 + kt) * 32 + lid];
                    mma16816(acc[0][ni], a0, b);
                    mma16816(acc[1][ni], a1, b);
                }
            }
            #pragma unroll
            for (int mi = 0; mi < 2; mi++) {
                int ra = mbase + mi * 16 + gid;
                int rb = ra + 8;
                int na = n0 + ra, nbn = n0 + rb;
                #pragma unroll
                for (int ni = 0; ni < 8; ni++) {
                    int c0 = (nb + ni) * 8 + 2 * tg;
                    float4 v = acc[mi][ni];
                    if (na < N_NODES)
                        *(float2*)&g_xf[(size_t)na * 128 + c0] = make_float2(v.x, v.y);
                    if (nbn < N_NODES)
                        *(float2*)&g_xf[(size_t)nbn * 128 + c0] = make_float2(v.z, v.w);
                }
            }
        } else {
            // ---- output head: x = ssp(h @ out1 + bO1) ----
            #pragma unroll
            for (int mi = 0; mi < 2; mi++)
                #pragma unroll
                for (int ni = 0; ni < 8; ni++)
                    acc[mi][ni] = make_float4(0.f, 0.f, 0.f, 0.f);
            #pragma unroll
            for (int kt = 0; kt < 8; kt++) {
                uint32_t a0[4], a1[4];
                ldsm4(a0, &in_s[(mbase + lrow) * HID_STR + kt * 16 + lcol]);
                ldsm4(a1, &in_s[(mbase + 16 + lrow) * HID_STR + kt * 16 + lcol]);
                #pragma unroll
                for (int ni = 0; ni < 8; ni++) {
                    uint2 b = wCf[((nb + ni) * 8 + kt) * 32 + lid];
                    mma16816(acc[0][ni], a0, b);
                    mma16816(acc[1][ni], a1, b);
                }
            }
            #pragma unroll
            for (int mi = 0; mi < 2; mi++) {
                int ra = mbase + mi * 16 + gid;
                int rb = ra + 8;
                #pragma unroll
                for (int ni = 0; ni < 8; ni++) {
                    int c0 = (nb + ni) * 8 + 2 * tg;
                    float4 v = acc[mi][ni];
                    float ba = bO1_s[c0], bb = bO1_s[c0 + 1];
                    *(uint32_t*)&x_s[ra * HID_STR + c0] =
                        f2h2(sspf_fast(v.x + ba), sspf_fast(v.y + bb));
                    *(uint32_t*)&x_s[rb * HID_STR + c0] =
                        f2h2(sspf_fast(v.z + ba), sspf_fast(v.w + bb));
                }
            }
            __syncthreads();

            // ---- output head: out = x @ out2 + bO2 -> g_sums[batch] ----
            #pragma unroll
            for (int mi = 0; mi < 2; mi++)
                #pragma unroll
                for (int ni = 0; ni < 8; ni++)
                    acc[mi][ni] = make_float4(0.f, 0.f, 0.f, 0.f);
            #pragma unroll
            for (int kt = 0; kt < 8; kt++) {
                uint32_t a0[4], a1[4];
                ldsm4(a0, &x_s[(mbase + lrow) * HID_STR + kt * 16 + lcol]);
                ldsm4(a1, &x_s[(mbase + 16 + lrow) * HID_STR + kt * 16 + lcol]);
                #pragma unroll
                for (int ni = 0; ni < 8; ni++) {
                    uint2 b = wDf[((nb + ni) * 8 + kt) * 32 + lid];
                    mma16816(acc[0][ni], a0, b);
                    mma16816(acc[1][ni], a1, b);
                }
            }
            #pragma unroll
            for (int mi = 0; mi < 2; mi++) {
                int ra = mbase + mi * 16 + gid;
                int rb = ra + 8;
                int na = n0 + ra, nbn = n0 + rb;
                #pragma unroll
                for (int ni = 0; ni < 8; ni++) {
                    int c0 = (nb + ni) * 8 + 2 * tg;
                    float4 v = acc[mi][ni];
                    float2 bv = *(const float2*)&bO2_s[c0];
                    if (na < N_NODES) {
                        float2 o = make_float2(v.x + bv.x, v.y + bv.y);
                        atomicAdd((float2*)&g_sums[batch_s[ra] * 128 + c0], o);
                    }
                    if (nbn < N_NODES) {
                        float2 o = make_float2(v.z + bv.x, v.w + bv.y);
                        atomicAdd((float2*)&g_sums[batch_s[rb] * 128 + c0], o);
                    }
                }
            }
        }
        __syncthreads();
    }
}

__global__ void finalize_kernel(float* __restrict__ out) {
    int i = blockIdx.x * blockDim.x + threadIdx.x;
    if (i >= NGRAPH * HDIM) return;
    out[i] = g_sums[i] / fmaxf(g_cnt[i >> 7], 1.0f);
}

// ---------------- launcher ----------------
extern "C" void kernel_launch(void* const* d_in, const int* in_sizes, int n_in,
                              void* d_out, int out_size) {
    const int*   z       = (const int*)d_in[0];
    const float* pos     = (const float*)d_in[1];
    const int*   ei      = (const int*)d_in[2];
    const int*   batch   = (const int*)d_in[3];
    const float* emb     = (const float*)d_in[4];
    const float* mlp_w1  = (const float*)d_in[5];
    const float* mlp_b1  = (const float*)d_in[6];
    const float* mlp_w2  = (const float*)d_in[7];
    const float* mlp_b2  = (const float*)d_in[8];
    const float* conv_w1 = (const float*)d_in[9];
    const float* conv_w2 = (const float*)d_in[10];
    const float* conv_b2 = (const float*)d_in[11];
    const float* lin_w   = (const float*)d_in[12];
    const float* lin_b   = (const float*)d_in[13];
    const float* out1_w  = (const float*)d_in[14];
    const float* out1_b  = (const float*)d_in[15];
    const float* out2_w  = (const float*)d_in[16];
    const float* out2_b  = (const float*)d_in[17];
    float* out = (float*)d_out;

    const int* src = ei;
    const int* dst = ei + N_EDGES;

    const int EDGE_SMEM = 104960;
    const int NODE_SMEM = 203264;
    const int XF0_SMEM  = 67584;

    cudaFuncSetAttribute(edge_mma_kernel, cudaFuncAttributeMaxDynamicSharedMemorySize, EDGE_SMEM);
    cudaFuncSetAttribute(node_fused_kernel, cudaFuncAttributeMaxDynamicSharedMemorySize, NODE_SMEM);
    cudaFuncSetAttribute(xf0_kernel, cudaFuncAttributeMaxDynamicSharedMemorySize, XF0_SMEM);

    misc_init_kernel<<<(N_NODES + 255) / 256, 256>>>();
    init_h_kernel<<<(N_NODES * HDIM + 255) / 256, 256>>>(z, emb);
    dist_hist_kernel<<<(N_EDGES + 255) / 256, 256>>>(src, dst, pos);
    scan_kernel<<<1, 1024>>>();
    scatter_kernel<<<(N_EDGES + 255) / 256, 256>>>(src, dst);
    build_frags_kernel<<<(NLAYERS * 4096 + 255) / 256, 256>>>(
        mlp_w1, mlp_w2, conv_w2, lin_w, conv_w1, out1_w, out2_w);
    zero_agg_kernel<<<(N_NODES * HDIM + 255) / 256, 256>>>();
    cnt_kernel<<<(N_NODES + 255) / 256, 256>>>(batch);

    xf0_kernel<<<NODE_TILES, 256, XF0_SMEM>>>();   // xf for layer 0

    for (int l = 0; l < NLAYERS; l++) {
        edge_mma_kernel<<<296, 256, EDGE_SMEM>>>(
            l, mlp_b1 + (size_t)l * 128, mlp_b2 + (size_t)l * 128);
        int do_c = (l < NLAYERS - 1) ? 1 : 0;
        node_fused_kernel<<<148, 256, NODE_SMEM>>>(
            l, conv_b2 + (size_t)l * 128, lin_b + (size_t)l * 128,
            out1_b, out2_b, batch, do_c);
    }

    finalize_kernel<<<(NGRAPH * HDIM + 255) / 256, 256>>>(out);
}

// round 14
// speedup vs baseline: 1.7103x; 1.0067x over previous
#include <cuda_runtime.h>
#include <cuda_fp16.h>
#include <math.h>
#include <stdint.h>

#define N_NODES 20000
#define N_EDGES 640000
#define HDIM    128
#define GDIM    50
#define NLAYERS 6
#define NGRAPH  64
#define CUTOFF  10.0f
#define LOG2F_  0.69314718055994531f
#define PI_     3.14159265358979323846f

#define EPT     128
#define NTILES  (N_EDGES / EPT)
#define EA_STR  72
#define HID_STR 136
#define NODE_TILES ((N_NODES + 127) / 128)
#define SCAN_BLOCKS ((N_NODES + 1023) / 1024)   // 20

// ---------------- device scratch ----------------
static __device__ __align__(16) float  g_h[N_NODES * HDIM];
static __device__ __align__(16) float  g_xf[N_NODES * HDIM];
static __device__ __align__(16) float  g_agg[N_NODES * HDIM];
static __device__ __align__(16) float  g_d[N_EDGES];
static __device__ __align__(16) float  g_C[N_EDGES];
static __device__ __align__(16) float  g_sums[NGRAPH * HDIM];
static __device__ float g_cnt[NGRAPH];
static __device__ int   g_hist[N_NODES];
static __device__ int   g_bsum[SCAN_BLOCKS];
static __device__ int   g_srcp[N_EDGES];
static __device__ int   g_dstp[N_EDGES];
static __device__ float g_Cp[N_EDGES];
static __device__ float g_dp[N_EDGES];
// prebuilt fp16 B-fragments (m16n8k16 layout)
static __device__ __align__(16) uint2 g_w1f[NLAYERS][2048];
static __device__ __align__(16) uint2 g_w2f[NLAYERS][4096];
static __device__ __align__(16) uint2 g_wAf[NLAYERS][4096];
static __device__ __align__(16) uint2 g_wBf[NLAYERS][4096];
static __device__ __align__(16) uint2 g_wCf[NLAYERS][4096];
static __device__ __align__(16) uint2 g_wO1f[4096];
static __device__ __align__(16) uint2 g_wO2f[4096];

// ---------------- helpers ----------------
__device__ __forceinline__ float sspf_fast(float x) {
    return fmaxf(x, 0.f) + __logf(1.f + __expf(-fabsf(x))) - LOG2F_;
}
__device__ __forceinline__ uint32_t smem_u32(const void* p) {
    uint32_t a;
    asm("{ .reg .u64 t; cvta.to.shared.u64 t, %1; cvt.u32.u64 %0, t; }" : "=r"(a) : "l"(p));
    return a;
}
__device__ __forceinline__ uint32_t f2h2(float lo, float hi) {
    __half2 h = __floats2half2_rn(lo, hi);
    return *reinterpret_cast<uint32_t*>(&h);
}
__device__ __forceinline__ void mma16816(float4& d, const uint32_t a[4], uint2 b) {
    asm volatile(
        "mma.sync.aligned.m16n8k16.row.col.f32.f16.f16.f32 "
        "{%0,%1,%2,%3}, {%4,%5,%6,%7}, {%8,%9}, {%0,%1,%2,%3};\n"
        : "+f"(d.x), "+f"(d.y), "+f"(d.z), "+f"(d.w)
        : "r"(a[0]), "r"(a[1]), "r"(a[2]), "r"(a[3]), "r"(b.x), "r"(b.y));
}
__device__ __forceinline__ void ldsm4(uint32_t r[4], const void* p) {
    uint32_t a = smem_u32(p);
    asm volatile("ldmatrix.sync.aligned.m8n8.x4.shared.b16 {%0,%1,%2,%3}, [%4];"
        : "=r"(r[0]), "=r"(r[1]), "=r"(r[2]), "=r"(r[3]) : "r"(a));
}
#define PAIR_BAR(id) asm volatile("bar.sync %0, 64;" :: "r"(id) : "memory")

// ---------------- precompute ----------------
// zero agg + hist + sums + cnt in one kernel
__global__ void zero_all_kernel() {
    int i = blockIdx.x * blockDim.x + threadIdx.x;
    if (i < N_NODES * HDIM) g_agg[i] = 0.f;
    if (i < N_NODES) g_hist[i] = 0;
    if (i < NGRAPH * HDIM) g_sums[i] = 0.f;
    if (i < NGRAPH) g_cnt[i] = 0.f;
}

// h = emb[z]; also per-graph node count
__global__ void init_h_kernel(const int* __restrict__ z, const float* __restrict__ emb,
                              const int* __restrict__ batch) {
    int i = blockIdx.x * blockDim.x + threadIdx.x;
    if (i >= N_NODES * HDIM) return;
    int n = i >> 7, j = i & 127;
    g_h[i] = emb[z[n] * HDIM + j];
    if (j == 0) atomicAdd(&g_cnt[batch[n]], 1.0f);
}

// distance + cutoff + dst histogram in one pass
__global__ void dist_hist_kernel(const int* __restrict__ src, const int* __restrict__ dst,
                                 const float* __restrict__ pos) {
    int e = blockIdx.x * blockDim.x + threadIdx.x;
    if (e >= N_EDGES) return;
    int s = src[e], t = dst[e];
    float dx = pos[s * 3 + 0] - pos[t * 3 + 0];
    float dy = pos[s * 3 + 1] - pos[t * 3 + 1];
    float dz = pos[s * 3 + 2] - pos[t * 3 + 2];
    float d = sqrtf(dx * dx + dy * dy + dz * dz);
    g_d[e] = d;
    g_C[e] = 0.5f * (cosf(d * (PI_ / CUTOFF)) + 1.0f);
    atomicAdd(&g_hist[t], 1);
}

// parallel exclusive scan of g_hist (3 phases)
__global__ void scan1_kernel() {
    __shared__ int s[1024];
    int t = threadIdx.x;
    int idx = blockIdx.x * 1024 + t;
    int v = (idx < N_NODES) ? g_hist[idx] : 0;
    s[t] = v;
    __syncthreads();
    for (int off = 512; off > 0; off >>= 1) {
        if (t < off) s[t] += s[t + off];
        __syncthreads();
    }
    if (t == 0) g_bsum[blockIdx.x] = s[0];
}
__global__ void scan2_kernel() {   // 1 block, serial spine (20 elems)
    if (threadIdx.x == 0) {
        int run = 0;
        for (int b = 0; b < SCAN_BLOCKS; b++) {
            int c = g_bsum[b];
            g_bsum[b] = run;
            run += c;
        }
    }
}
__global__ void scan3_kernel() {
    __shared__ int s[1024];
    int t = threadIdx.x;
    int idx = blockIdx.x * 1024 + t;
    int v = (idx < N_NODES) ? g_hist[idx] : 0;
    s[t] = v;
    __syncthreads();
    // Hillis-Steele inclusive scan
    for (int off = 1; off < 1024; off <<= 1) {
        int u = (t >= off) ? s[t - off] : 0;
        __syncthreads();
        s[t] += u;
        __syncthreads();
    }
    if (idx < N_NODES) g_hist[idx] = s[t] - v + g_bsum[blockIdx.x];
}

__global__ void scatter_kernel(const int* __restrict__ src, const int* __restrict__ dst) {
    int e = blockIdx.x * blockDim.x + threadIdx.x;
    if (e >= N_EDGES) return;
    int d = dst[e];
    int p = atomicAdd(&g_hist[d], 1);
    g_srcp[p] = src[e];
    g_dstp[p] = d;
    g_Cp[p]   = g_C[e];
    g_dp[p]   = g_d[e];
}

// build all fp16 B-fragments once (m16n8k16 layout)
__device__ __forceinline__ uint2 frag_of(const float* w, int k0, int n) {
    return make_uint2(f2h2(w[k0 * 128 + n], w[(k0 + 1) * 128 + n]),
                      f2h2(w[(k0 + 8) * 128 + n], w[(k0 + 9) * 128 + n]));
}
__global__ void build_frags_kernel(const float* __restrict__ mlp_w1,
                                   const float* __restrict__ mlp_w2,
                                   const float* __restrict__ conv_w2,
                                   const float* __restrict__ lin_w,
                                   const float* __restrict__ conv_w1,
                                   const float* __restrict__ out1_w,
                                   const float* __restrict__ out2_w) {
    int i = blockIdx.x * blockDim.x + threadIdx.x;
    if (i >= NLAYERS * 4096) return;
    int l = i / 4096, j = i % 4096;
    int lane = j & 31;
    int g_ = lane >> 2, t_ = lane & 3;
    {
        int kt = (j >> 5) & 7, nt = j >> 8;
        int k0 = kt * 16 + 2 * t_, n = nt * 8 + g_;
        g_w2f[l][j] = frag_of(mlp_w2 + (size_t)l * 16384, k0, n);
        g_wAf[l][j] = frag_of(conv_w2 + (size_t)l * 16384, k0, n);
        g_wBf[l][j] = frag_of(lin_w + (size_t)l * 16384, k0, n);
        g_wCf[l][j] = frag_of(conv_w1 + (size_t)l * 16384, k0, n);
        if (l == 0) {
            g_wO1f[j] = frag_of(out1_w, k0, n);
            g_wO2f[j] = frag_of(out2_w, k0, n);
        }
    }
    if (j < 2048) {
        int kt = (j >> 5) & 3, nt = j >> 7;
        int k0 = kt * 16 + 2 * t_, n = nt * 8 + g_;
        const float* w1 = mlp_w1 + (size_t)l * GDIM * 128;
        float v0 = (k0     < GDIM) ? w1[k0 * 128 + n]       : 0.f;
        float v1 = (k0 + 1 < GDIM) ? w1[(k0 + 1) * 128 + n] : 0.f;
        float v2 = (k0 + 8 < GDIM) ? w1[(k0 + 8) * 128 + n] : 0.f;
        float v3 = (k0 + 9 < GDIM) ? w1[(k0 + 9) * 128 + n] : 0.f;
        g_w1f[l][j] = make_uint2(f2h2(v0, v1), f2h2(v2, v3));
    }
}

// ---------------- initial xf = h @ conv_w1[0]  (fp16 MMA) -------------------
__global__ __launch_bounds__(256, 2) void xf0_kernel() {
    extern __shared__ char smraw[];
    __half* in_s = (__half*)smraw;             // 34816
    uint2*  wf   = (uint2*)(smraw + 34816);    // 32768
    int tid = threadIdx.x;
    int wid = tid >> 5;
    int lid = tid & 31;
    int gid = lid >> 2;
    int tg  = lid & 3;
    int lrow = lid & 15;
    int lcol = (lid >> 4) << 3;

    for (int i = tid; i < 2048; i += 256)
        ((uint4*)wf)[i] = ((const uint4*)g_wCf[0])[i];

    int n0 = blockIdx.x * 128;
    for (int i = tid; i < 128 * 32; i += 256) {
        int r = i >> 5, c4 = i & 31;
        float4 v = make_float4(0.f, 0.f, 0.f, 0.f);
        if (n0 + r < N_NODES)
            v = ((const float4*)&g_h[(size_t)(n0 + r) * 128])[c4];
        *(uint2*)&in_s[r * HID_STR + c4 * 4] = make_uint2(f2h2(v.x, v.y), f2h2(v.z, v.w));
    }
    __syncthreads();

    int mbase = (wid & 3) * 32;
    int nb    = (wid >> 2) * 8;
    float4 acc[2][8];
    #pragma unroll
    for (int mi = 0; mi < 2; mi++)
        #pragma unroll
        for (int ni = 0; ni < 8; ni++)
            acc[mi][ni] = make_float4(0.f, 0.f, 0.f, 0.f);
    #pragma unroll
    for (int kt = 0; kt < 8; kt++) {
        uint32_t a0[4], a1[4];
        ldsm4(a0, &in_s[(mbase + lrow) * HID_STR + kt * 16 + lcol]);
        ldsm4(a1, &in_s[(mbase + 16 + lrow) * HID_STR + kt * 16 + lcol]);
        #pragma unroll
        for (int ni = 0; ni < 8; ni++) {
            uint2 b = wf[((nb + ni) * 8 + kt) * 32 + lid];
            mma16816(acc[0][ni], a0, b);
            mma16816(acc[1][ni], a1, b);
        }
    }
    #pragma unroll
    for (int mi = 0; mi < 2; mi++) {
        int ra = mbase + mi * 16 + gid;
        int rb = ra + 8;
        int na = n0 + ra, nbn = n0 + rb;
        #pragma unroll
        for (int ni = 0; ni < 8; ni++) {
            int c0 = (nb + ni) * 8 + 2 * tg;
            float4 v = acc[mi][ni];
            if (na < N_NODES)
                *(float2*)&g_xf[(size_t)na * 128 + c0] = make_float2(v.x, v.y);
            if (nbn < N_NODES)
                *(float2*)&g_xf[(size_t)nbn * 128 + c0] = make_float2(v.z, v.w);
        }
    }
}

// ---------------- fp16 MMA edge kernel (pair-barrier pipeline) -------------
__global__ __launch_bounds__(256, 2) void edge_mma_kernel(
        int layer, const float* __restrict__ b1, const float* __restrict__ b2) {
    extern __shared__ char smraw[];
    __half* ea_s  = (__half*)smraw;                   // 18432
    __half* hid_s = (__half*)(smraw + 18432);         // 34816
    __half* msg_h = hid_s;                            // aliases hid (post-GEMM2)
    uint2*  w1f   = (uint2*)(smraw + 53248);          // 16384
    uint2*  w2f   = (uint2*)(smraw + 69632);          // 32768
    float*  b1_s  = (float*)(smraw + 102400);
    float*  b2_s  = b1_s + 128;
    float*  C_s   = b2_s + 128;
    int*    src_s = (int*)(C_s + 128);
    int*    dst_s = src_s + 128;

    int tid = threadIdx.x;
    int wid = tid >> 5;
    int lid = tid & 31;
    int gid = lid >> 2;
    int tg  = lid & 3;
    int lrow = lid & 15;
    int lcol = (lid >> 4) << 3;
    int strip = wid & 3;
    int half  = wid >> 2;
    int bar_id = 1 + strip;

    const float step  = CUTOFF / (GDIM - 1);
    const float inv_step = (GDIM - 1) / CUTOFF;
    const float coeff = -0.5f / (step * step);

    if (tid < 128) { b1_s[tid] = b1[tid]; b2_s[tid] = b2[tid]; }
    for (int i = tid; i < 1024; i += 256)
        ((uint4*)w1f)[i] = ((const uint4*)g_w1f[layer])[i];
    for (int i = tid; i < 2048; i += 256)
        ((uint4*)w2f)[i] = ((const uint4*)g_w2f[layer])[i];
    __syncthreads();

    int mbase = strip * 32;
    int nb    = half * 8;
    // reducer chunk aligned to own strip: pair {w, w+4} covers strip's 2 chunks
    int rchunk = 2 * strip + half;
    int rr0 = rchunk * 16;

    // prefetch first tile scalars
    int psrc = 0, pdst = 0;
    float pC = 0.f, pd = 0.f;
    int t = blockIdx.x;
    if (t < NTILES && tid < 128) {
        int e0 = t * EPT;
        psrc = g_srcp[e0 + tid];
        pdst = g_dstp[e0 + tid];
        pC   = g_Cp[e0 + tid];
        pd   = g_dp[e0 + tid];
    }

    for (; t < NTILES; t += gridDim.x) {
        // commit scalars + compute gaussian rows in-kernel (±6 window,
        // bit-identical to full 50-center evaluation in fp16)
        if (tid < 128) {
            src_s[tid] = psrc; dst_s[tid] = pdst; C_s[tid] = pC;
            uint4 z4 = make_uint4(0, 0, 0, 0);
            #pragma unroll
            for (int j = 0; j < 8; j++)
                *(uint4*)&ea_s[tid * EA_STR + j * 8] = z4;
            int c0 = (int)rintf(pd * inv_step);
            #pragma unroll
            for (int k = -6; k <= 6; k++) {
                int c = c0 + k;
                if (c >= 0 && c < GDIM) {
                    float diff = pd - c * step;
                    ea_s[tid * EA_STR + c] = __float2half_rn(__expf(coeff * diff * diff));
                }
            }
        }
        __syncthreads();   // S1: ea + scalars visible to all warps

        float4 acc[2][8];
        #pragma unroll
        for (int mi = 0; mi < 2; mi++)
            #pragma unroll
            for (int ni = 0; ni < 8; ni++)
                acc[mi][ni] = make_float4(0.f, 0.f, 0.f, 0.f);

        // GEMM1: K=64 (each warp reads only its own 32-row strip of ea)
        #pragma unroll
        for (int kt = 0; kt < 4; kt++) {
            uint32_t a0[4], a1[4];
            ldsm4(a0, &ea_s[(mbase + lrow) * EA_STR + kt * 16 + lcol]);
            ldsm4(a1, &ea_s[(mbase + 16 + lrow) * EA_STR + kt * 16 + lcol]);
            #pragma unroll
            for (int ni = 0; ni < 8; ni++) {
                uint2 b = w1f[((nb + ni) * 4 + kt) * 32 + lid];
                mma16816(acc[0][ni], a0, b);
                mma16816(acc[1][ni], a1, b);
            }
        }

        // ssp -> fp16 HID (own strip, own column half)
        #pragma unroll
        for (int mi = 0; mi < 2; mi++) {
            int ra = mbase + mi * 16 + gid;
            int rb = ra + 8;
            #pragma unroll
            for (int ni = 0; ni < 8; ni++) {
                int c0 = (nb + ni) * 8 + 2 * tg;
                float4 v = acc[mi][ni];
                float ba = b1_s[c0], bb = b1_s[c0 + 1];
                *(uint32_t*)&hid_s[ra * HID_STR + c0] =
                    f2h2(sspf_fast(v.x + ba), sspf_fast(v.y + bb));
                *(uint32_t*)&hid_s[rb * HID_STR + c0] =
                    f2h2(sspf_fast(v.z + ba), sspf_fast(v.w + bb));
            }
        }
        PAIR_BAR(bar_id);   // P1: pair's hid strip complete

        // prefetch next tile scalars (overlaps GEMM2 + epilogue)
        int tn = t + gridDim.x;
        if (tn < NTILES && tid < 128) {
            int e0n = tn * EPT;
            psrc = g_srcp[e0n + tid];
            pdst = g_dstp[e0n + tid];
            pC   = g_Cp[e0n + tid];
            pd   = g_dp[e0n + tid];
        }

        #pragma unroll
        for (int mi = 0; mi < 2; mi++)
            #pragma unroll
            for (int ni = 0; ni < 8; ni++)
                acc[mi][ni] = make_float4(0.f, 0.f, 0.f, 0.f);

        // GEMM2: K=128 (reads only own strip of hid)
        #pragma unroll
        for (int kt = 0; kt < 8; kt++) {
            uint32_t a0[4], a1[4];
            ldsm4(a0, &hid_s[(mbase + lrow) * HID_STR + kt * 16 + lcol]);
            ldsm4(a1, &hid_s[(mbase + 16 + lrow) * HID_STR + kt * 16 + lcol]);
            #pragma unroll
            for (int ni = 0; ni < 8; ni++) {
                uint2 b = w2f[((nb + ni) * 8 + kt) * 32 + lid];
                mma16816(acc[0][ni], a0, b);
                mma16816(acc[1][ni], a1, b);
            }
        }
        PAIR_BAR(bar_id);   // P2: pair done reading hid strip; safe to overwrite

        // stage fp16 msg = (C2+b2)*C into own strip / own column half
        #pragma unroll
        for (int mi = 0; mi < 2; mi++) {
            int ra = mbase + mi * 16 + gid;
            int rb = ra + 8;
            float Ca = C_s[ra], Cb = C_s[rb];
            #pragma unroll
            for (int ni = 0; ni < 8; ni++) {
                int c0 = (nb + ni) * 8 + 2 * tg;
                float4 v = acc[mi][ni];
                float2 bv = *(const float2*)&b2_s[c0];
                *(uint32_t*)&msg_h[ra * HID_STR + c0] =
                    f2h2((v.x + bv.x) * Ca, (v.y + bv.y) * Ca);
                *(uint32_t*)&msg_h[rb * HID_STR + c0] =
                    f2h2((v.z + bv.x) * Cb, (v.w + bv.y) * Cb);
            }
        }
        PAIR_BAR(bar_id);   // P3: pair's msg strip complete

        // segmented reduce over the 16-row chunk inside own strip
        {
            int cg = lid;
            float4 run = make_float4(0.f, 0.f, 0.f, 0.f);
            int cur = dst_s[rr0];
            #pragma unroll
            for (int j = 0; j < 16; j++) {
                int dd = dst_s[rr0 + j];
                uint2 mh = *(uint2*)&msg_h[(rr0 + j) * HID_STR + cg * 4];
                float2 m01 = __half22float2(*(__half2*)&mh.x);
                float2 m23 = __half22float2(*(__half2*)&mh.y);
                float4 xv = *(const float4*)&g_xf[(size_t)src_s[rr0 + j] * 128 + cg * 4];
                if (dd != cur) {
                    atomicAdd((float4*)&g_agg[(size_t)cur * 128 + cg * 4], run);
                    run = make_float4(0.f, 0.f, 0.f, 0.f);
                    cur = dd;
                }
                run.x += m01.x * xv.x; run.y += m01.y * xv.y;
                run.z += m23.x * xv.z; run.w += m23.y * xv.w;
            }
            atomicAdd((float4*)&g_agg[(size_t)cur * 128 + cg * 4], run);
        }
        __syncthreads();   // S2: dst/src/C consumed before next commit
    }
}

// ---------------- fused node kernel (persistent; zeroes g_agg; l=5 also
// computes the output head into g_sums) --------------------------------------
__global__ __launch_bounds__(256, 1) void node_fused_kernel(
        int layer, const float* __restrict__ bA, const float* __restrict__ bB,
        const float* __restrict__ bO1, const float* __restrict__ bO2,
        const int* __restrict__ batch, int do_c) {
    extern __shared__ char smraw[];
    __half* in_s = (__half*)smraw;                     // 34816
    __half* x_s  = (__half*)(smraw + 34816);           // 34816
    uint2*  wAf  = (uint2*)(smraw + 69632);            // 32768
    uint2*  wBf  = (uint2*)(smraw + 102400);           // 32768
    uint2*  wCf  = (uint2*)(smraw + 135168);           // 32768
    uint2*  wDf  = (uint2*)(smraw + 167936);           // 32768
    float*  bA_s = (float*)(smraw + 200704);
    float*  bB_s = bA_s + 128;
    float*  bO1_s = bB_s + 128;
    float*  bO2_s = bO1_s + 128;
    int*    batch_s = (int*)(bO2_s + 128);

    int tid = threadIdx.x;
    int wid = tid >> 5;
    int lid = tid & 31;
    int gid = lid >> 2;
    int tg  = lid & 3;
    int lrow = lid & 15;
    int lcol = (lid >> 4) << 3;
    int do_out = !do_c;

    if (tid < 128) {
        bA_s[tid] = bA[tid]; bB_s[tid] = bB[tid];
        if (do_out) { bO1_s[tid] = bO1[tid]; bO2_s[tid] = bO2[tid]; }
    }
    for (int i = tid; i < 2048; i += 256) {
        ((uint4*)wAf)[i] = ((const uint4*)g_wAf[layer])[i];
        ((uint4*)wBf)[i] = ((const uint4*)g_wBf[layer])[i];
        if (do_c) {
            ((uint4*)wCf)[i] = ((const uint4*)g_wCf[layer + 1])[i];
        } else {
            ((uint4*)wCf)[i] = ((const uint4*)g_wO1f)[i];
            ((uint4*)wDf)[i] = ((const uint4*)g_wO2f)[i];
        }
    }
    __syncthreads();

    int mbase = (wid & 3) * 32;
    int nb    = (wid >> 2) * 8;

    for (int tile = blockIdx.x; tile < NODE_TILES; tile += gridDim.x) {
        int n0 = tile * 128;
        for (int i = tid; i < 128 * 32; i += 256) {
            int r = i >> 5, c4 = i & 31;
            float4 v = make_float4(0.f, 0.f, 0.f, 0.f);
            if (n0 + r < N_NODES) {
                v = ((const float4*)&g_agg[(size_t)(n0 + r) * 128])[c4];
                ((float4*)&g_agg[(size_t)(n0 + r) * 128])[c4] =
                    make_float4(0.f, 0.f, 0.f, 0.f);
            }
            *(uint2*)&in_s[r * HID_STR + c4 * 4] = make_uint2(f2h2(v.x, v.y), f2h2(v.z, v.w));
        }
        if (do_out && tid < 128)
            batch_s[tid] = (n0 + tid < N_NODES) ? batch[n0 + tid] : 0;
        __syncthreads();

        float4 acc[2][8];
        // ---- GEMM A: x = ssp(agg @ wA + bA) ----
        #pragma unroll
        for (int mi = 0; mi < 2; mi++)
            #pragma unroll
            for (int ni = 0; ni < 8; ni++)
                acc[mi][ni] = make_float4(0.f, 0.f, 0.f, 0.f);
        #pragma unroll
        for (int kt = 0; kt < 8; kt++) {
            uint32_t a0[4], a1[4];
            ldsm4(a0, &in_s[(mbase + lrow) * HID_STR + kt * 16 + lcol]);
            ldsm4(a1, &in_s[(mbase + 16 + lrow) * HID_STR + kt * 16 + lcol]);
            #pragma unroll
            for (int ni = 0; ni < 8; ni++) {
                uint2 b = wAf[((nb + ni) * 8 + kt) * 32 + lid];
                mma16816(acc[0][ni], a0, b);
                mma16816(acc[1][ni], a1, b);
            }
        }
        #pragma unroll
        for (int mi = 0; mi < 2; mi++) {
            int ra = mbase + mi * 16 + gid;
            int rb = ra + 8;
            #pragma unroll
            for (int ni = 0; ni < 8; ni++) {
                int c0 = (nb + ni) * 8 + 2 * tg;
                float4 v = acc[mi][ni];
                float ba = bA_s[c0], bb = bA_s[c0 + 1];
                *(uint32_t*)&x_s[ra * HID_STR + c0] =
                    f2h2(sspf_fast(v.x + ba), sspf_fast(v.y + bb));
                *(uint32_t*)&x_s[rb * HID_STR + c0] =
                    f2h2(sspf_fast(v.z + ba), sspf_fast(v.w + bb));
            }
        }
        __syncthreads();

        // ---- GEMM B: h += x @ wB + bB ----
        #pragma unroll
        for (int mi = 0; mi < 2; mi++)
            #pragma unroll
            for (int ni = 0; ni < 8; ni++)
                acc[mi][ni] = make_float4(0.f, 0.f, 0.f, 0.f);
        #pragma unroll
        for (int kt = 0; kt < 8; kt++) {
            uint32_t a0[4], a1[4];
            ldsm4(a0, &x_s[(mbase + lrow) * HID_STR + kt * 16 + lcol]);
            ldsm4(a1, &x_s[(mbase + 16 + lrow) * HID_STR + kt * 16 + lcol]);
            #pragma unroll
            for (int ni = 0; ni < 8; ni++) {
                uint2 b = wBf[((nb + ni) * 8 + kt) * 32 + lid];
                mma16816(acc[0][ni], a0, b);
                mma16816(acc[1][ni], a1, b);
            }
        }
        #pragma unroll
        for (int mi = 0; mi < 2; mi++) {
            int ra = mbase + mi * 16 + gid;
            int rb = ra + 8;
            int na = n0 + ra, nbn = n0 + rb;
            #pragma unroll
            for (int ni = 0; ni < 8; ni++) {
                int c0 = (nb + ni) * 8 + 2 * tg;
                float4 v = acc[mi][ni];
                float ba = bB_s[c0], bb = bB_s[c0 + 1];
                float hx = 0.f, hy = 0.f, hz = 0.f, hw = 0.f;
                if (na < N_NODES) {
                    float2 hv = *(float2*)&g_h[(size_t)na * 128 + c0];
                    hx = hv.x + v.x + ba;
                    hy = hv.y + v.y + bb;
                    *(float2*)&g_h[(size_t)na * 128 + c0] = make_float2(hx, hy);
                }
                if (nbn < N_NODES) {
                    float2 hv = *(float2*)&g_h[(size_t)nbn * 128 + c0];
                    hz = hv.x + v.z + ba;
                    hw = hv.y + v.w + bb;
                    *(float2*)&g_h[(size_t)nbn * 128 + c0] = make_float2(hz, hw);
                }
                *(uint32_t*)&in_s[ra * HID_STR + c0] = f2h2(hx, hy);
                *(uint32_t*)&in_s[rb * HID_STR + c0] = f2h2(hz, hw);
            }
        }
        __syncthreads();

        if (do_c) {
            // ---- GEMM C: xf = h @ wC ----
            #pragma unroll
            for (int mi = 0; mi < 2; mi++)
                #pragma unroll
                for (int ni = 0; ni < 8; ni++)
                    acc[mi][ni] = make_float4(0.f, 0.f, 0.f, 0.f);
            #pragma unroll
            for (int kt = 0; kt < 8; kt++) {
                uint32_t a0[4], a1[4];
                ldsm4(a0, &in_s[(mbase + lrow) * HID_STR + kt * 16 + lcol]);
                ldsm4(a1, &in_s[(mbase + 16 + lrow) * HID_STR + kt * 16 + lcol]);
                #pragma unroll
                for (int ni = 0; ni < 8; ni++) {
                    uint2 b = wCf[((nb + ni) * 8 + kt) * 32 + lid];
                    mma16816(acc[0][ni], a0, b);
                    mma16816(acc[1][ni], a1, b);
                }
            }
            #pragma unroll
            for (int mi = 0; mi < 2; mi++) {
                int ra = mbase + mi * 16 + gid;
                int rb = ra + 8;
                int na = n0 + ra, nbn = n0 + rb;
                #pragma unroll
                for (int ni = 0; ni < 8; ni++) {
                    int c0 = (nb + ni) * 8 + 2 * tg;
                    float4 v = acc[mi][ni];
                    if (na < N_NODES)
                        *(float2*)&g_xf[(size_t)na * 128 + c0] = make_float2(v.x, v.y);
                    if (nbn < N_NODES)
                        *(float2*)&g_xf[(size_t)nbn * 128 + c0] = make_float2(v.z, v.w);
                }
            }
        } else {
            // ---- output head: x = ssp(h @ out1 + bO1) ----
            #pragma unroll
            for (int mi = 0; mi < 2; mi++)
                #pragma unroll
                for (int ni = 0; ni < 8; ni++)
                    acc[mi][ni] = make_float4(0.f, 0.f, 0.f, 0.f);
            #pragma unroll
            for (int kt = 0; kt < 8; kt++) {
                uint32_t a0[4], a1[4];
                ldsm4(a0, &in_s[(mbase + lrow) * HID_STR + kt * 16 + lcol]);
                ldsm4(a1, &in_s[(mbase + 16 + lrow) * HID_STR + kt * 16 + lcol]);
                #pragma unroll
                for (int ni = 0; ni < 8; ni++) {
                    uint2 b = wCf[((nb + ni) * 8 + kt) * 32 + lid];
                    mma16816(acc[0][ni], a0, b);
                    mma16816(acc[1][ni], a1, b);
                }
            }
            #pragma unroll
            for (int mi = 0; mi < 2; mi++) {
                int ra = mbase + mi * 16 + gid;
                int rb = ra + 8;
                #pragma unroll
                for (int ni = 0; ni < 8; ni++) {
                    int c0 = (nb + ni) * 8 + 2 * tg;
                    float4 v = acc[mi][ni];
                    float ba = bO1_s[c0], bb = bO1_s[c0 + 1];
                    *(uint32_t*)&x_s[ra * HID_STR + c0] =
                        f2h2(sspf_fast(v.x + ba), sspf_fast(v.y + bb));
                    *(uint32_t*)&x_s[rb * HID_STR + c0] =
                        f2h2(sspf_fast(v.z + ba), sspf_fast(v.w + bb));
                }
            }
            __syncthreads();

            // ---- output head: out = x @ out2 + bO2 -> g_sums[batch] ----
            #pragma unroll
            for (int mi = 0; mi < 2; mi++)
                #pragma unroll
                for (int ni = 0; ni < 8; ni++)
                    acc[mi][ni] = make_float4(0.f, 0.f, 0.f, 0.f);
            #pragma unroll
            for (int kt = 0; kt < 8; kt++) {
                uint32_t a0[4], a1[4];
                ldsm4(a0, &x_s[(mbase + lrow) * HID_STR + kt * 16 + lcol]);
                ldsm4(a1, &x_s[(mbase + 16 + lrow) * HID_STR + kt * 16 + lcol]);
                #pragma unroll
                for (int ni = 0; ni < 8; ni++) {
                    uint2 b = wDf[((nb + ni) * 8 + kt) * 32 + lid];
                    mma16816(acc[0][ni], a0, b);
                    mma16816(acc[1][ni], a1, b);
                }
            }
            #pragma unroll
            for (int mi = 0; mi < 2; mi++) {
                int ra = mbase + mi * 16 + gid;
                int rb = ra + 8;
                int na = n0 + ra, nbn = n0 + rb;
                #pragma unroll
                for (int ni = 0; ni < 8; ni++) {
                    int c0 = (nb + ni) * 8 + 2 * tg;
                    float4 v = acc[mi][ni];
                    float2 bv = *(const float2*)&bO2_s[c0];
                    if (na < N_NODES) {
                        float2 o = make_float2(v.x + bv.x, v.y + bv.y);
                        atomicAdd((float2*)&g_sums[batch_s[ra] * 128 + c0], o);
                    }
                    if (nbn < N_NODES) {
                        float2 o = make_float2(v.z + bv.x, v.w + bv.y);
                        atomicAdd((float2*)&g_sums[batch_s[rb] * 128 + c0], o);
                    }
                }
            }
        }
        __syncthreads();
    }
}

__global__ void finalize_kernel(float* __restrict__ out) {
    int i = blockIdx.x * blockDim.x + threadIdx.x;
    if (i >= NGRAPH * HDIM) return;
    out[i] = g_sums[i] / fmaxf(g_cnt[i >> 7], 1.0f);
}

// ---------------- launcher ----------------
extern "C" void kernel_launch(void* const* d_in, const int* in_sizes, int n_in,
                              void* d_out, int out_size) {
    const int*   z       = (const int*)d_in[0];
    const float* pos     = (const float*)d_in[1];
    const int*   ei      = (const int*)d_in[2];
    const int*   batch   = (const int*)d_in[3];
    const float* emb     = (const float*)d_in[4];
    const float* mlp_w1  = (const float*)d_in[5];
    const float* mlp_b1  = (const float*)d_in[6];
    const float* mlp_w2  = (const float*)d_in[7];
    const float* mlp_b2  = (const float*)d_in[8];
    const float* conv_w1 = (const float*)d_in[9];
    const float* conv_w2 = (const float*)d_in[10];
    const float* conv_b2 = (const float*)d_in[11];
    const float* lin_w   = (const float*)d_in[12];
    const float* lin_b   = (const float*)d_in[13];
    const float* out1_w  = (const float*)d_in[14];
    const float* out1_b  = (const float*)d_in[15];
    const float* out2_w  = (const float*)d_in[16];
    const float* out2_b  = (const float*)d_in[17];
    float* out = (float*)d_out;

    const int* src = ei;
    const int* dst = ei + N_EDGES;

    const int EDGE_SMEM = 104960;
    const int NODE_SMEM = 203264;
    const int XF0_SMEM  = 67584;

    cudaFuncSetAttribute(edge_mma_kernel, cudaFuncAttributeMaxDynamicSharedMemorySize, EDGE_SMEM);
    cudaFuncSetAttribute(node_fused_kernel, cudaFuncAttributeMaxDynamicSharedMemorySize, NODE_SMEM);
    cudaFuncSetAttribute(xf0_kernel, cudaFuncAttributeMaxDynamicSharedMemorySize, XF0_SMEM);

    zero_all_kernel<<<(N_NODES * HDIM + 255) / 256, 256>>>();
    init_h_kernel<<<(N_NODES * HDIM + 255) / 256, 256>>>(z, emb, batch);
    dist_hist_kernel<<<(N_EDGES + 255) / 256, 256>>>(src, dst, pos);
    scan1_kernel<<<SCAN_BLOCKS, 1024>>>();
    scan2_kernel<<<1, 32>>>();
    scan3_kernel<<<SCAN_BLOCKS, 1024>>>();
    scatter_kernel<<<(N_EDGES + 255) / 256, 256>>>(src, dst);
    build_frags_kernel<<<(NLAYERS * 4096 + 255) / 256, 256>>>(
        mlp_w1, mlp_w2, conv_w2, lin_w, conv_w1, out1_w, out2_w);

    xf0_kernel<<<NODE_TILES, 256, XF0_SMEM>>>();   // xf for layer 0

    for (int l = 0; l < NLAYERS; l++) {
        edge_mma_kernel<<<296, 256, EDGE_SMEM>>>(
            l, mlp_b1 + (size_t)l * 128, mlp_b2 + (size_t)l * 128);
        int do_c = (l < NLAYERS - 1) ? 1 : 0;
        node_fused_kernel<<<148, 256, NODE_SMEM>>>(
            l, conv_b2 + (size_t)l * 128, lin_b + (size_t)l * 128,
            out1_b, out2_b, batch, do_c);
    }

    finalize_kernel<<<(NGRAPH * HDIM + 255) / 256, 256>>>(out);
}